// round 1
// baseline (speedup 1.0000x reference)
#include <cuda_runtime.h>
#include <math.h>

#define BS   16
#define NSEQ 2048
#define DIM  256
#define NROWS (BS*NSEQ)   // 32768

// ---------------- scratch (device globals: allocation-free rule) ------------
__device__ float g_h1[NROWS*DIM];        // conv1+bn1+relu output   [bt][i]
__device__ float g_xconv[NROWS*DIM];     // conv branch output      [bt][o]
__device__ float g_msg[NROWS*DIM];       // relu(x@w_msg.T+b)       [bt][d]
__device__ float g_xnmp[NROWS*DIM];      // A @ msg                 [bt][d]
__device__ float g_s[NROWS*4];           // s0,s1,s2,sq per row
__device__ float g_wA[DIM*512];          // [k][512]  = [conv1_w^T | w_msg^T]
__device__ float g_w2t[17*DIM*DIM];      // [tap][i][o], prescaled by bn2 scale
__device__ float g_wih_t[512*768];       // [k][768]
__device__ float g_whh_t[DIM*768];       // [k][768]

// ---------------- weight repack ------------------------------------------
__global__ void repack_kernel(const float* __restrict__ conv1_w,
                              const float* __restrict__ w_msg,
                              const float* __restrict__ conv2_w,
                              const float* __restrict__ bn2_g,
                              const float* __restrict__ bn2_v,
                              const float* __restrict__ w_ih,
                              const float* __restrict__ w_hh) {
    int stride = gridDim.x * blockDim.x;
    int idx = blockIdx.x * blockDim.x + threadIdx.x;
    // g_wA[k][c]
    for (int i = idx; i < DIM*512; i += stride) {
        int k = i >> 9, c = i & 511;
        g_wA[i] = (c < DIM) ? conv1_w[c*DIM + k] : w_msg[(c-DIM)*DIM + k];
    }
    // g_w2t[tap][i][o] = conv2_w[o][i][tap] * scale2[o]
    for (int i = idx; i < 17*DIM*DIM; i += stride) {
        int o = i & 255;
        int rest = i >> 8;
        int ic = rest & 255;
        int tap = rest >> 8;
        float sc = bn2_g[o] * rsqrtf(bn2_v[o] + 1e-5f);
        g_w2t[i] = conv2_w[(o*DIM + ic)*17 + tap] * sc;
    }
    // g_wih_t[k][c] = w_ih[c][k]   (w_ih: 768x512)
    for (int i = idx; i < 512*768; i += stride) {
        int k = i / 768, c = i - k*768;
        g_wih_t[i] = w_ih[c*512 + k];
    }
    // g_whh_t[k][c] = w_hh[c][k]   (w_hh: 768x256)
    for (int i = idx; i < DIM*768; i += stride) {
        int k = i / 768, c = i - k*768;
        g_whh_t[i] = w_hh[c*DIM + k];
    }
}

// ---------------- front GEMM: h1 (conv1+bn1+relu) and msg -----------------
// C[32768 x 512] = x[32768 x 256] @ g_wA[256 x 512], split epilogues.
__global__ void __launch_bounds__(256) gemm_front(
        const float* __restrict__ x,
        const float* __restrict__ bn1_g, const float* __restrict__ bn1_b,
        const float* __restrict__ bn1_m, const float* __restrict__ bn1_v,
        const float* __restrict__ b_msg) {
    __shared__ float As[16][64];
    __shared__ float Bs[16][64];
    const int row0 = blockIdx.y * 64;
    const int col0 = blockIdx.x * 64;
    const int tid = threadIdx.x;
    const int tx = tid & 15, ty = tid >> 4;
    const int lm = tid >> 2;          // 0..63
    const int lk = (tid & 3) * 4;     // 0,4,8,12
    const int kb = tid >> 4;          // 0..15
    const int nb = (tid & 15) * 4;    // 0..60

    float acc[4][4] = {};
    for (int k0 = 0; k0 < DIM; k0 += 16) {
        float4 a = *(const float4*)&x[(size_t)(row0+lm)*DIM + k0 + lk];
        As[lk+0][lm]=a.x; As[lk+1][lm]=a.y; As[lk+2][lm]=a.z; As[lk+3][lm]=a.w;
        *(float4*)&Bs[kb][nb] = *(const float4*)&g_wA[(k0+kb)*512 + col0 + nb];
        __syncthreads();
        #pragma unroll
        for (int kk = 0; kk < 16; kk++) {
            float4 av = *(float4*)&As[kk][ty*4];
            float4 bv = *(float4*)&Bs[kk][tx*4];
            float a_[4] = {av.x,av.y,av.z,av.w};
            float b_[4] = {bv.x,bv.y,bv.z,bv.w};
            #pragma unroll
            for (int i = 0; i < 4; i++)
                #pragma unroll
                for (int j = 0; j < 4; j++)
                    acc[i][j] += a_[i]*b_[j];
        }
        __syncthreads();
    }
    #pragma unroll
    for (int j = 0; j < 4; j++) {
        int c = col0 + tx*4 + j;
        float sc, sh;
        if (c < DIM) {
            sc = bn1_g[c] * rsqrtf(bn1_v[c] + 1e-5f);
            sh = bn1_b[c] - bn1_m[c]*sc;
        } else {
            sc = 1.0f; sh = b_msg[c-DIM];
        }
        #pragma unroll
        for (int i = 0; i < 4; i++) {
            int r = row0 + ty*4 + i;
            float v = fmaxf(acc[i][j]*sc + sh, 0.0f);
            if (c < DIM) g_h1[(size_t)r*DIM + c] = v;
            else         g_msg[(size_t)r*DIM + (c-DIM)] = v;
        }
    }
}

// ---------------- s / sq (tiny: 256 -> 3 projection) ----------------------
__global__ void skernel(const float* __restrict__ x,
                        const float* __restrict__ w_se,
                        const float* __restrict__ b_se) {
    int row = blockIdx.x * 8 + (threadIdx.x >> 5);
    int lane = threadIdx.x & 31;
    float p0=0.f, p1=0.f, p2=0.f;
    for (int k = lane; k < DIM; k += 32) {
        float xv = x[(size_t)row*DIM + k];
        p0 += xv * w_se[k];
        p1 += xv * w_se[DIM + k];
        p2 += xv * w_se[2*DIM + k];
    }
    #pragma unroll
    for (int off = 16; off > 0; off >>= 1) {
        p0 += __shfl_down_sync(0xffffffffu, p0, off);
        p1 += __shfl_down_sync(0xffffffffu, p1, off);
        p2 += __shfl_down_sync(0xffffffffu, p2, off);
    }
    if (lane == 0) {
        p0 += b_se[0]; p1 += b_se[1]; p2 += b_se[2];
        g_s[row*4+0] = p0;
        g_s[row*4+1] = p1;
        g_s[row*4+2] = p2;
        g_s[row*4+3] = p0*p0 + p1*p1 + p2*p2;
    }
}

// ---------------- conv2 (17-tap) + bn2 + residual + relu ------------------
__global__ void __launch_bounds__(256) conv2_kernel(
        const float* __restrict__ x,
        const float* __restrict__ bn2_g, const float* __restrict__ bn2_b,
        const float* __restrict__ bn2_m, const float* __restrict__ bn2_v) {
    __shared__ float As[16][64];
    __shared__ float Bs[16][64];
    const int b    = blockIdx.z;
    const int t0   = blockIdx.y * 64;
    const int col0 = blockIdx.x * 64;
    const int tid = threadIdx.x;
    const int tx = tid & 15, ty = tid >> 4;
    const int lm = tid >> 2;
    const int lk = (tid & 3) * 4;
    const int kb = tid >> 4;
    const int nb = (tid & 15) * 4;

    float acc[4][4] = {};
    for (int tap = 0; tap < 17; tap++) {
        const int tbase = t0 + tap - 8;
        for (int k0 = 0; k0 < DIM; k0 += 16) {
            int t = tbase + lm;
            float4 a;
            if (t >= 0 && t < NSEQ)
                a = *(const float4*)&g_h1[((size_t)(b*NSEQ + t))*DIM + k0 + lk];
            else
                a = make_float4(0.f,0.f,0.f,0.f);
            As[lk+0][lm]=a.x; As[lk+1][lm]=a.y; As[lk+2][lm]=a.z; As[lk+3][lm]=a.w;
            *(float4*)&Bs[kb][nb] =
                *(const float4*)&g_w2t[((size_t)(tap*DIM + k0 + kb))*DIM + col0 + nb];
            __syncthreads();
            #pragma unroll
            for (int kk = 0; kk < 16; kk++) {
                float4 av = *(float4*)&As[kk][ty*4];
                float4 bv = *(float4*)&Bs[kk][tx*4];
                float a_[4] = {av.x,av.y,av.z,av.w};
                float b_[4] = {bv.x,bv.y,bv.z,bv.w};
                #pragma unroll
                for (int i = 0; i < 4; i++)
                    #pragma unroll
                    for (int j = 0; j < 4; j++)
                        acc[i][j] += a_[i]*b_[j];
            }
            __syncthreads();
        }
    }
    #pragma unroll
    for (int j = 0; j < 4; j++) {
        int o = col0 + tx*4 + j;
        float sc = bn2_g[o] * rsqrtf(bn2_v[o] + 1e-5f);
        float sh = bn2_b[o] - bn2_m[o]*sc;
        #pragma unroll
        for (int i = 0; i < 4; i++) {
            int r = b*NSEQ + t0 + ty*4 + i;
            float v = acc[i][j] + sh + x[(size_t)r*DIM + o];
            g_xconv[(size_t)r*DIM + o] = fmaxf(v, 0.0f);
        }
    }
}

// ---------------- fused NMP: x_nmp = (exp(-dist)*mask) @ msg --------------
// block: 64 n-rows x 256 d-cols. 256 threads = 8 warps(row groups) x 32 col
// groups; each thread does 8 rows x 8 cols. msg tile (32 m) in smem.
__global__ void __launch_bounds__(256) nmp_kernel(const float* __restrict__ mask) {
    __shared__ float sMsg[32*DIM];   // 32KB
    __shared__ float sW[64*32];      // 8KB
    __shared__ float sSn[64*4];
    __shared__ float sSm[32*4];
    const int b  = blockIdx.y;
    const int n0 = blockIdx.x * 64;
    const int tid = threadIdx.x;
    const int rg = tid >> 5;     // warp id: rows rg, rg+8, ..., rg+56
    const int cg = tid & 31;     // cols cg*8 .. cg*8+7

    sSn[tid] = g_s[(size_t)(b*NSEQ + n0)*4 + tid];   // 256 floats, contiguous
    float acc[8][8] = {};
    const float* msrc = &g_msg[(size_t)b*NSEQ*DIM];
    const size_t mbase = ((size_t)b*NSEQ + n0) * NSEQ;

    for (int m0 = 0; m0 < NSEQ; m0 += 32) {
        __syncthreads();   // previous tile fully consumed
        {   // copy msg tile: 32 rows x 256 = 8192 floats, contiguous
            const float4* src4 = (const float4*)&msrc[(size_t)m0*DIM];
            float4* dst4 = (float4*)sMsg;
            #pragma unroll
            for (int q = 0; q < 8; q++) dst4[tid + 256*q] = src4[tid + 256*q];
        }
        if (tid < 128) sSm[tid] = g_s[(size_t)(b*NSEQ + m0)*4 + tid];
        __syncthreads();
        // weights: 64x32 entries, 8 per thread
        #pragma unroll
        for (int q = 0; q < 8; q++) {
            int lin = tid + 256*q;
            int rr = lin >> 5, mm = lin & 31;
            float d = sSn[rr*4+3] + sSm[mm*4+3]
                    - 2.0f*(sSn[rr*4+0]*sSm[mm*4+0]
                          + sSn[rr*4+1]*sSm[mm*4+1]
                          + sSn[rr*4+2]*sSm[mm*4+2]);
            float mk = mask[mbase + (size_t)rr*NSEQ + m0 + mm];
            sW[rr*32 + mm] = __expf(-d) * mk;
        }
        __syncthreads();
        #pragma unroll
        for (int mm = 0; mm < 32; mm++) {
            float w[8];
            #pragma unroll
            for (int p = 0; p < 8; p++) w[p] = sW[(rg + 8*p)*32 + mm];
            float4 v0 = *(float4*)&sMsg[mm*DIM + cg*8];
            float4 v1 = *(float4*)&sMsg[mm*DIM + cg*8 + 4];
            float mv[8] = {v0.x,v0.y,v0.z,v0.w, v1.x,v1.y,v1.z,v1.w};
            #pragma unroll
            for (int p = 0; p < 8; p++)
                #pragma unroll
                for (int q = 0; q < 8; q++)
                    acc[p][q] += w[p]*mv[q];
        }
    }
    #pragma unroll
    for (int p = 0; p < 8; p++) {
        size_t row = (size_t)b*NSEQ + n0 + rg + 8*p;
        *(float4*)&g_xnmp[row*DIM + cg*8]     = make_float4(acc[p][0],acc[p][1],acc[p][2],acc[p][3]);
        *(float4*)&g_xnmp[row*DIM + cg*8 + 4] = make_float4(acc[p][4],acc[p][5],acc[p][6],acc[p][7]);
    }
}

// ---------------- fused GRU: gi + gh GEMMs + gates ------------------------
__global__ void __launch_bounds__(256) gru_kernel(
        const float* __restrict__ x,
        const float* __restrict__ b_ih, const float* __restrict__ b_hh,
        float* __restrict__ out) {
    __shared__ float As[16][64];
    __shared__ float Br[16][64];
    __shared__ float Bz[16][64];
    __shared__ float Bn[16][64];
    const int row0 = blockIdx.y * 64;
    const int j0   = blockIdx.x * 64;
    const int tid = threadIdx.x;
    const int tx = tid & 15, ty = tid >> 4;
    const int lm = tid >> 2;
    const int lk = (tid & 3) * 4;
    const int kb = tid >> 4;
    const int nb = (tid & 15) * 4;

    float ar[4][4] = {}, az[4][4] = {}, ain[4][4] = {}, ahn[4][4] = {};

    // phase 1: gi over K=512 of x_in = [x_conv | x_nmp]
    for (int k0 = 0; k0 < 512; k0 += 16) {
        const float* Asrc = (k0 < 256) ? g_xconv : g_xnmp;
        int kloc = k0 & 255;
        float4 a = *(const float4*)&Asrc[(size_t)(row0+lm)*DIM + kloc + lk];
        As[lk+0][lm]=a.x; As[lk+1][lm]=a.y; As[lk+2][lm]=a.z; As[lk+3][lm]=a.w;
        const float* wrow = &g_wih_t[(size_t)(k0+kb)*768];
        *(float4*)&Br[kb][nb] = *(const float4*)&wrow[      j0 + nb];
        *(float4*)&Bz[kb][nb] = *(const float4*)&wrow[256 + j0 + nb];
        *(float4*)&Bn[kb][nb] = *(const float4*)&wrow[512 + j0 + nb];
        __syncthreads();
        #pragma unroll
        for (int kk = 0; kk < 16; kk++) {
            float4 av  = *(float4*)&As[kk][ty*4];
            float4 brv = *(float4*)&Br[kk][tx*4];
            float4 bzv = *(float4*)&Bz[kk][tx*4];
            float4 bnv = *(float4*)&Bn[kk][tx*4];
            float a_[4]  = {av.x,av.y,av.z,av.w};
            float br_[4] = {brv.x,brv.y,brv.z,brv.w};
            float bz_[4] = {bzv.x,bzv.y,bzv.z,bzv.w};
            float bn_[4] = {bnv.x,bnv.y,bnv.z,bnv.w};
            #pragma unroll
            for (int i = 0; i < 4; i++)
                #pragma unroll
                for (int j = 0; j < 4; j++) {
                    ar[i][j]  += a_[i]*br_[j];
                    az[i][j]  += a_[i]*bz_[j];
                    ain[i][j] += a_[i]*bn_[j];
                }
        }
        __syncthreads();
    }
    // phase 2: gh over K=256 of x (r,z fold in; n stays separate)
    for (int k0 = 0; k0 < 256; k0 += 16) {
        float4 a = *(const float4*)&x[(size_t)(row0+lm)*DIM + k0 + lk];
        As[lk+0][lm]=a.x; As[lk+1][lm]=a.y; As[lk+2][lm]=a.z; As[lk+3][lm]=a.w;
        const float* wrow = &g_whh_t[(size_t)(k0+kb)*768];
        *(float4*)&Br[kb][nb] = *(const float4*)&wrow[      j0 + nb];
        *(float4*)&Bz[kb][nb] = *(const float4*)&wrow[256 + j0 + nb];
        *(float4*)&Bn[kb][nb] = *(const float4*)&wrow[512 + j0 + nb];
        __syncthreads();
        #pragma unroll
        for (int kk = 0; kk < 16; kk++) {
            float4 av  = *(float4*)&As[kk][ty*4];
            float4 brv = *(float4*)&Br[kk][tx*4];
            float4 bzv = *(float4*)&Bz[kk][tx*4];
            float4 bnv = *(float4*)&Bn[kk][tx*4];
            float a_[4]  = {av.x,av.y,av.z,av.w};
            float br_[4] = {brv.x,brv.y,brv.z,brv.w};
            float bz_[4] = {bzv.x,bzv.y,bzv.z,bzv.w};
            float bn_[4] = {bnv.x,bnv.y,bnv.z,bnv.w};
            #pragma unroll
            for (int i = 0; i < 4; i++)
                #pragma unroll
                for (int j = 0; j < 4; j++) {
                    ar[i][j]  += a_[i]*br_[j];
                    az[i][j]  += a_[i]*bz_[j];
                    ahn[i][j] += a_[i]*bn_[j];
                }
        }
        __syncthreads();
    }
    // gate epilogue
    #pragma unroll
    for (int j = 0; j < 4; j++) {
        int c = j0 + tx*4 + j;
        float bir = b_ih[c],       bhr = b_hh[c];
        float biz = b_ih[256 + c], bhz = b_hh[256 + c];
        float bin = b_ih[512 + c], bhn = b_hh[512 + c];
        #pragma unroll
        for (int i = 0; i < 4; i++) {
            size_t r = (size_t)row0 + ty*4 + i;
            float rv = 1.0f/(1.0f + __expf(-(ar[i][j] + bir + bhr)));
            float zv = 1.0f/(1.0f + __expf(-(az[i][j] + biz + bhz)));
            float nv = tanhf(ain[i][j] + bin + rv*(ahn[i][j] + bhn));
            float xv = x[r*DIM + c];
            out[r*DIM + c] = (1.0f - zv)*nv + zv*xv;
        }
    }
}

// ---------------- launch --------------------------------------------------
extern "C" void kernel_launch(void* const* d_in, const int* in_sizes, int n_in,
                              void* d_out, int out_size) {
    const float* x       = (const float*)d_in[0];
    const float* mask    = (const float*)d_in[1];
    const float* w_se    = (const float*)d_in[2];
    const float* b_se    = (const float*)d_in[3];
    const float* conv1_w = (const float*)d_in[4];
    const float* bn1_g   = (const float*)d_in[5];
    const float* bn1_b   = (const float*)d_in[6];
    const float* bn1_m   = (const float*)d_in[7];
    const float* bn1_v   = (const float*)d_in[8];
    const float* conv2_w = (const float*)d_in[9];
    const float* bn2_g   = (const float*)d_in[10];
    const float* bn2_b   = (const float*)d_in[11];
    const float* bn2_m   = (const float*)d_in[12];
    const float* bn2_v   = (const float*)d_in[13];
    const float* w_msg   = (const float*)d_in[14];
    const float* b_msg   = (const float*)d_in[15];
    const float* w_ih    = (const float*)d_in[16];
    const float* b_ih    = (const float*)d_in[17];
    const float* w_hh    = (const float*)d_in[18];
    const float* b_hh    = (const float*)d_in[19];
    float* out = (float*)d_out;

    repack_kernel<<<512, 256>>>(conv1_w, w_msg, conv2_w, bn2_g, bn2_v, w_ih, w_hh);

    gemm_front<<<dim3(8, NROWS/64), 256>>>(x, bn1_g, bn1_b, bn1_m, bn1_v, b_msg);

    skernel<<<NROWS/8, 256>>>(x, w_se, b_se);

    conv2_kernel<<<dim3(4, NSEQ/64, BS), 256>>>(x, bn2_g, bn2_b, bn2_m, bn2_v);

    nmp_kernel<<<dim3(NSEQ/64, BS), 256>>>(mask);

    gru_kernel<<<dim3(4, NROWS/64), 256>>>(x, b_ih, b_hh, out);
}

// round 2
// speedup vs baseline: 1.0403x; 1.0403x over previous
#include <cuda_runtime.h>
#include <math.h>

#define BS   16
#define NSEQ 2048
#define DIM  256
#define NROWS (BS*NSEQ)   // 32768

// ---------------- scratch (device globals: allocation-free rule) ------------
__device__ float g_h1[NROWS*DIM];        // conv1+bn1+relu output
__device__ float g_xconv[NROWS*DIM];     // conv branch output
__device__ float g_msg[NROWS*DIM];       // relu(x@w_msg.T+b)
__device__ float g_xnmp[NROWS*DIM];      // A @ msg
__device__ float g_s[NROWS*4];           // s0,s1,s2,sq per row
__device__ float g_gi[NROWS*768];        // x_in @ w_ih^T (no bias)
__device__ float g_gh[NROWS*768];        // x @ w_hh^T (no bias)
__device__ float g_wA[DIM*512];          // [k][512]  = [conv1_w^T | w_msg^T]
__device__ float g_w2t[17*DIM*DIM];      // [tap*256+k][o], prescaled by bn2 scale
__device__ float g_wih_t[512*768];       // [k][768]
__device__ float g_whh_t[DIM*768];       // [k][768]

// ---------------- weight repack ------------------------------------------
__global__ void repack_kernel(const float* __restrict__ conv1_w,
                              const float* __restrict__ w_msg,
                              const float* __restrict__ conv2_w,
                              const float* __restrict__ bn2_g,
                              const float* __restrict__ bn2_v,
                              const float* __restrict__ w_ih,
                              const float* __restrict__ w_hh) {
    int stride = gridDim.x * blockDim.x;
    int idx = blockIdx.x * blockDim.x + threadIdx.x;
    for (int i = idx; i < DIM*512; i += stride) {
        int k = i >> 9, c = i & 511;
        g_wA[i] = (c < DIM) ? conv1_w[c*DIM + k] : w_msg[(c-DIM)*DIM + k];
    }
    for (int i = idx; i < 17*DIM*DIM; i += stride) {
        int o = i & 255;
        int rest = i >> 8;
        int ic = rest & 255;
        int tap = rest >> 8;
        float sc = bn2_g[o] * rsqrtf(bn2_v[o] + 1e-5f);
        g_w2t[i] = conv2_w[(o*DIM + ic)*17 + tap] * sc;
    }
    for (int i = idx; i < 512*768; i += stride) {
        int k = i / 768, c = i - k*768;
        g_wih_t[i] = w_ih[c*512 + k];
    }
    for (int i = idx; i < DIM*768; i += stride) {
        int k = i / 768, c = i - k*768;
        g_whh_t[i] = w_hh[c*DIM + k];
    }
}

// ================= shared GEMM machinery (128x128x16, 8x8/thread) ========
#define SA_STRIDE 132   // 128 + 4 pad (float4-aligned, 2-way STS conflict max)

#define GEMM_DECLS \
    __shared__ float As[2][16*SA_STRIDE]; \
    __shared__ float Bs[2][16*128]; \
    const int tid = threadIdx.x; \
    const int tx = tid & 15, ty = tid >> 4; \
    const int ty8 = ty*8, tx8 = tx*8; \
    const int ar_ = tid >> 2;            /* A row 0..63 (+64 second) */ \
    const int ac_ = (tid & 3) * 4;       /* A k-offset 0,4,8,12 */ \
    const int br_ = tid >> 4;            /* B k-row 0..15 */ \
    const int bc_ = (tid & 15) * 8;      /* B col offset */ \
    float4 pa0, pa1, pb0, pb1; \
    float acc[8][8] = {};

#define STORE_AB(buf) { \
    float* ap = &As[buf][0]; \
    ap[(ac_+0)*SA_STRIDE + ar_] = pa0.x; \
    ap[(ac_+1)*SA_STRIDE + ar_] = pa0.y; \
    ap[(ac_+2)*SA_STRIDE + ar_] = pa0.z; \
    ap[(ac_+3)*SA_STRIDE + ar_] = pa0.w; \
    ap[(ac_+0)*SA_STRIDE + ar_ + 64] = pa1.x; \
    ap[(ac_+1)*SA_STRIDE + ar_ + 64] = pa1.y; \
    ap[(ac_+2)*SA_STRIDE + ar_ + 64] = pa1.z; \
    ap[(ac_+3)*SA_STRIDE + ar_ + 64] = pa1.w; \
    float* bq = &Bs[buf][br_*128 + bc_]; \
    *(float4*)bq = pb0; *(float4*)(bq+4) = pb1; }

#define GEMM_COMPUTE(buf) { \
    const float* ab = &As[buf][0]; \
    const float* bb = &Bs[buf][0]; \
    _Pragma("unroll") \
    for (int kk = 0; kk < 16; kk++) { \
        float4 a0 = *(const float4*)&ab[kk*SA_STRIDE + ty8]; \
        float4 a1 = *(const float4*)&ab[kk*SA_STRIDE + ty8 + 4]; \
        float4 b0 = *(const float4*)&bb[kk*128 + tx8]; \
        float4 b1 = *(const float4*)&bb[kk*128 + tx8 + 4]; \
        float av[8] = {a0.x,a0.y,a0.z,a0.w,a1.x,a1.y,a1.z,a1.w}; \
        float bv[8] = {b0.x,b0.y,b0.z,b0.w,b1.x,b1.y,b1.z,b1.w}; \
        _Pragma("unroll") \
        for (int i = 0; i < 8; i++) \
            _Pragma("unroll") \
            for (int j = 0; j < 8; j++) \
                acc[i][j] += av[i]*bv[j]; \
    } }

// ---------------- front GEMM: h1 (conv1+bn1+relu) and msg -----------------
// C[32768 x 512] = x[32768 x 256] @ g_wA[256 x 512]
__global__ void __launch_bounds__(256) gemm_front(
        const float* __restrict__ x,
        const float* __restrict__ bn1_g, const float* __restrict__ bn1_b,
        const float* __restrict__ bn1_m, const float* __restrict__ bn1_v,
        const float* __restrict__ b_msg) {
    GEMM_DECLS
    const int row0 = blockIdx.y * 128;
    const int col0 = blockIdx.x * 128;

#define LOAD_FRONT(kt) { int k0 = (kt)*16; \
    pa0 = *(const float4*)&x[(size_t)(row0 + ar_)*DIM + k0 + ac_]; \
    pa1 = *(const float4*)&x[(size_t)(row0 + ar_ + 64)*DIM + k0 + ac_]; \
    const float* bp = &g_wA[(size_t)(k0 + br_)*512 + col0 + bc_]; \
    pb0 = *(const float4*)bp; pb1 = *(const float4*)(bp+4); }

    LOAD_FRONT(0); STORE_AB(0); __syncthreads();
    const int nt = DIM/16;
    for (int kt = 0; kt < nt; kt++) {
        int buf = kt & 1;
        if (kt+1 < nt) LOAD_FRONT(kt+1);
        GEMM_COMPUTE(buf);
        if (kt+1 < nt) STORE_AB(1-buf);
        __syncthreads();
    }
#undef LOAD_FRONT
    #pragma unroll
    for (int j = 0; j < 8; j++) {
        int c = col0 + tx8 + j;
        float sc, sh;
        if (c < DIM) {
            sc = bn1_g[c] * rsqrtf(bn1_v[c] + 1e-5f);
            sh = bn1_b[c] - bn1_m[c]*sc;
        } else { sc = 1.0f; sh = b_msg[c-DIM]; }
        #pragma unroll
        for (int i = 0; i < 8; i++) {
            size_t r = (size_t)row0 + ty8 + i;
            float v = fmaxf(acc[i][j]*sc + sh, 0.0f);
            if (c < DIM) g_h1[r*DIM + c] = v;
            else         g_msg[r*DIM + (c-DIM)] = v;
        }
    }
}

// ---------------- conv2 (17-tap) as K=4352 GEMM + bn2 + residual + relu ---
__global__ void __launch_bounds__(256) conv2_kernel(
        const float* __restrict__ x,
        const float* __restrict__ bn2_g, const float* __restrict__ bn2_b,
        const float* __restrict__ bn2_m, const float* __restrict__ bn2_v) {
    GEMM_DECLS
    const int b    = blockIdx.z;
    const int t0   = blockIdx.y * 128;
    const int col0 = blockIdx.x * 128;
    const float* h1b = &g_h1[(size_t)b*NSEQ*DIM];

#define LOAD_C2(kt) { int k0 = (kt)*16; \
    int tap = k0 >> 8; int kloc = k0 & 255; \
    int t1 = t0 + ar_ + tap - 8; \
    int t2 = t1 + 64; \
    pa0 = make_float4(0.f,0.f,0.f,0.f); \
    pa1 = make_float4(0.f,0.f,0.f,0.f); \
    if ((unsigned)t1 < (unsigned)NSEQ) \
        pa0 = *(const float4*)&h1b[(size_t)t1*DIM + kloc + ac_]; \
    if ((unsigned)t2 < (unsigned)NSEQ) \
        pa1 = *(const float4*)&h1b[(size_t)t2*DIM + kloc + ac_]; \
    const float* bp = &g_w2t[(size_t)(k0 + br_)*DIM + col0 + bc_]; \
    pb0 = *(const float4*)bp; pb1 = *(const float4*)(bp+4); }

    LOAD_C2(0); STORE_AB(0); __syncthreads();
    const int nt = 17*DIM/16;  // 272
    for (int kt = 0; kt < nt; kt++) {
        int buf = kt & 1;
        if (kt+1 < nt) LOAD_C2(kt+1);
        GEMM_COMPUTE(buf);
        if (kt+1 < nt) STORE_AB(1-buf);
        __syncthreads();
    }
#undef LOAD_C2
    #pragma unroll
    for (int j = 0; j < 8; j++) {
        int o = col0 + tx8 + j;
        float sc = bn2_g[o] * rsqrtf(bn2_v[o] + 1e-5f);
        float sh = bn2_b[o] - bn2_m[o]*sc;
        #pragma unroll
        for (int i = 0; i < 8; i++) {
            size_t r = (size_t)b*NSEQ + t0 + ty8 + i;
            float v = acc[i][j] + sh + x[r*DIM + o];
            g_xconv[r*DIM + o] = fmaxf(v, 0.0f);
        }
    }
}

// ---------------- gi GEMM: [xconv|xnmp] @ w_ih^T  (K=512, N=768) ----------
__global__ void __launch_bounds__(256) gemm_gi() {
    GEMM_DECLS
    const int row0 = blockIdx.y * 128;
    const int col0 = blockIdx.x * 128;

#define LOAD_GI(kt) { int k0 = (kt)*16; \
    const float* Asrc = (k0 < 256) ? g_xconv : g_xnmp; \
    int kloc = k0 & 255; \
    pa0 = *(const float4*)&Asrc[(size_t)(row0 + ar_)*DIM + kloc + ac_]; \
    pa1 = *(const float4*)&Asrc[(size_t)(row0 + ar_ + 64)*DIM + kloc + ac_]; \
    const float* bp = &g_wih_t[(size_t)(k0 + br_)*768 + col0 + bc_]; \
    pb0 = *(const float4*)bp; pb1 = *(const float4*)(bp+4); }

    LOAD_GI(0); STORE_AB(0); __syncthreads();
    const int nt = 512/16;
    for (int kt = 0; kt < nt; kt++) {
        int buf = kt & 1;
        if (kt+1 < nt) LOAD_GI(kt+1);
        GEMM_COMPUTE(buf);
        if (kt+1 < nt) STORE_AB(1-buf);
        __syncthreads();
    }
#undef LOAD_GI
    #pragma unroll
    for (int i = 0; i < 8; i++) {
        size_t r = (size_t)row0 + ty8 + i;
        #pragma unroll
        for (int j = 0; j < 8; j += 4)
            *(float4*)&g_gi[r*768 + col0 + tx8 + j] =
                make_float4(acc[i][j],acc[i][j+1],acc[i][j+2],acc[i][j+3]);
    }
}

// ---------------- gh GEMM: x @ w_hh^T  (K=256, N=768) ---------------------
__global__ void __launch_bounds__(256) gemm_gh(const float* __restrict__ x) {
    GEMM_DECLS
    const int row0 = blockIdx.y * 128;
    const int col0 = blockIdx.x * 128;

#define LOAD_GH(kt) { int k0 = (kt)*16; \
    pa0 = *(const float4*)&x[(size_t)(row0 + ar_)*DIM + k0 + ac_]; \
    pa1 = *(const float4*)&x[(size_t)(row0 + ar_ + 64)*DIM + k0 + ac_]; \
    const float* bp = &g_whh_t[(size_t)(k0 + br_)*768 + col0 + bc_]; \
    pb0 = *(const float4*)bp; pb1 = *(const float4*)(bp+4); }

    LOAD_GH(0); STORE_AB(0); __syncthreads();
    const int nt = DIM/16;
    for (int kt = 0; kt < nt; kt++) {
        int buf = kt & 1;
        if (kt+1 < nt) LOAD_GH(kt+1);
        GEMM_COMPUTE(buf);
        if (kt+1 < nt) STORE_AB(1-buf);
        __syncthreads();
    }
#undef LOAD_GH
    #pragma unroll
    for (int i = 0; i < 8; i++) {
        size_t r = (size_t)row0 + ty8 + i;
        #pragma unroll
        for (int j = 0; j < 8; j += 4)
            *(float4*)&g_gh[r*768 + col0 + tx8 + j] =
                make_float4(acc[i][j],acc[i][j+1],acc[i][j+2],acc[i][j+3]);
    }
}

// ---------------- gate epilogue ------------------------------------------
__global__ void gate_kernel(const float* __restrict__ x,
                            const float* __restrict__ b_ih,
                            const float* __restrict__ b_hh,
                            float* __restrict__ out) {
    int idx = blockIdx.x * blockDim.x + threadIdx.x;   // one float4 of cols
    size_t r = idx >> 6;
    int c = (idx & 63) * 4;
    const float* gi = &g_gi[r*768];
    const float* gh = &g_gh[r*768];
    float4 gir = *(const float4*)&gi[c];
    float4 giz = *(const float4*)&gi[256 + c];
    float4 gin = *(const float4*)&gi[512 + c];
    float4 ghr = *(const float4*)&gh[c];
    float4 ghz = *(const float4*)&gh[256 + c];
    float4 ghn = *(const float4*)&gh[512 + c];
    float4 xv  = *(const float4*)&x[r*DIM + c];
    float4 o;
    #pragma unroll
    for (int q = 0; q < 4; q++) {
        float air = (&gir.x)[q] + b_ih[c+q]       + (&ghr.x)[q] + b_hh[c+q];
        float aiz = (&giz.x)[q] + b_ih[256 + c+q] + (&ghz.x)[q] + b_hh[256 + c+q];
        float rv = 1.0f/(1.0f + __expf(-air));
        float zv = 1.0f/(1.0f + __expf(-aiz));
        float nv = tanhf((&gin.x)[q] + b_ih[512 + c+q]
                       + rv*((&ghn.x)[q] + b_hh[512 + c+q]));
        (&o.x)[q] = (1.0f - zv)*nv + zv*(&xv.x)[q];
    }
    *(float4*)&out[r*DIM + c] = o;
}

// ---------------- s / sq (tiny: 256 -> 3 projection) ----------------------
__global__ void skernel(const float* __restrict__ x,
                        const float* __restrict__ w_se,
                        const float* __restrict__ b_se) {
    int row = blockIdx.x * 8 + (threadIdx.x >> 5);
    int lane = threadIdx.x & 31;
    float p0=0.f, p1=0.f, p2=0.f;
    for (int k = lane; k < DIM; k += 32) {
        float xv = x[(size_t)row*DIM + k];
        p0 += xv * w_se[k];
        p1 += xv * w_se[DIM + k];
        p2 += xv * w_se[2*DIM + k];
    }
    #pragma unroll
    for (int off = 16; off > 0; off >>= 1) {
        p0 += __shfl_down_sync(0xffffffffu, p0, off);
        p1 += __shfl_down_sync(0xffffffffu, p1, off);
        p2 += __shfl_down_sync(0xffffffffu, p2, off);
    }
    if (lane == 0) {
        p0 += b_se[0]; p1 += b_se[1]; p2 += b_se[2];
        g_s[row*4+0] = p0;
        g_s[row*4+1] = p1;
        g_s[row*4+2] = p2;
        g_s[row*4+3] = p0*p0 + p1*p1 + p2*p2;
    }
}

// ---------------- fused NMP: x_nmp = (exp(-dist)*mask) @ msg --------------
__global__ void __launch_bounds__(256) nmp_kernel(const float* __restrict__ mask) {
    __shared__ float sMsg[32*DIM];   // 32KB
    __shared__ float sW[64*32];      // 8KB
    __shared__ float sSn[64*4];
    __shared__ float sSm[32*4];
    const int b  = blockIdx.y;
    const int n0 = blockIdx.x * 64;
    const int tid = threadIdx.x;
    const int rg = tid >> 5;
    const int cg = tid & 31;

    sSn[tid] = g_s[(size_t)(b*NSEQ + n0)*4 + tid];
    float acc[8][8] = {};
    const float* msrc = &g_msg[(size_t)b*NSEQ*DIM];
    const size_t mbase = ((size_t)b*NSEQ + n0) * NSEQ;

    for (int m0 = 0; m0 < NSEQ; m0 += 32) {
        __syncthreads();
        {
            const float4* src4 = (const float4*)&msrc[(size_t)m0*DIM];
            float4* dst4 = (float4*)sMsg;
            #pragma unroll
            for (int q = 0; q < 8; q++) dst4[tid + 256*q] = src4[tid + 256*q];
        }
        if (tid < 128) sSm[tid] = g_s[(size_t)(b*NSEQ + m0)*4 + tid];
        __syncthreads();
        #pragma unroll
        for (int q = 0; q < 8; q++) {
            int lin = tid + 256*q;
            int rr = lin >> 5, mm = lin & 31;
            float d = sSn[rr*4+3] + sSm[mm*4+3]
                    - 2.0f*(sSn[rr*4+0]*sSm[mm*4+0]
                          + sSn[rr*4+1]*sSm[mm*4+1]
                          + sSn[rr*4+2]*sSm[mm*4+2]);
            float mk = mask[mbase + (size_t)rr*NSEQ + m0 + mm];
            sW[rr*32 + mm] = __expf(-d) * mk;
        }
        __syncthreads();
        #pragma unroll
        for (int mm = 0; mm < 32; mm++) {
            float w[8];
            #pragma unroll
            for (int p = 0; p < 8; p++) w[p] = sW[(rg + 8*p)*32 + mm];
            float4 v0 = *(float4*)&sMsg[mm*DIM + cg*8];
            float4 v1 = *(float4*)&sMsg[mm*DIM + cg*8 + 4];
            float mv[8] = {v0.x,v0.y,v0.z,v0.w, v1.x,v1.y,v1.z,v1.w};
            #pragma unroll
            for (int p = 0; p < 8; p++)
                #pragma unroll
                for (int q = 0; q < 8; q++)
                    acc[p][q] += w[p]*mv[q];
        }
    }
    #pragma unroll
    for (int p = 0; p < 8; p++) {
        size_t row = (size_t)b*NSEQ + n0 + rg + 8*p;
        *(float4*)&g_xnmp[row*DIM + cg*8]     = make_float4(acc[p][0],acc[p][1],acc[p][2],acc[p][3]);
        *(float4*)&g_xnmp[row*DIM + cg*8 + 4] = make_float4(acc[p][4],acc[p][5],acc[p][6],acc[p][7]);
    }
}

// ---------------- launch --------------------------------------------------
extern "C" void kernel_launch(void* const* d_in, const int* in_sizes, int n_in,
                              void* d_out, int out_size) {
    const float* x       = (const float*)d_in[0];
    const float* mask    = (const float*)d_in[1];
    const float* w_se    = (const float*)d_in[2];
    const float* b_se    = (const float*)d_in[3];
    const float* conv1_w = (const float*)d_in[4];
    const float* bn1_g   = (const float*)d_in[5];
    const float* bn1_b   = (const float*)d_in[6];
    const float* bn1_m   = (const float*)d_in[7];
    const float* bn1_v   = (const float*)d_in[8];
    const float* conv2_w = (const float*)d_in[9];
    const float* bn2_g   = (const float*)d_in[10];
    const float* bn2_b   = (const float*)d_in[11];
    const float* bn2_m   = (const float*)d_in[12];
    const float* bn2_v   = (const float*)d_in[13];
    const float* w_msg   = (const float*)d_in[14];
    const float* b_msg   = (const float*)d_in[15];
    const float* w_ih    = (const float*)d_in[16];
    const float* b_ih    = (const float*)d_in[17];
    const float* w_hh    = (const float*)d_in[18];
    const float* b_hh    = (const float*)d_in[19];
    float* out = (float*)d_out;

    repack_kernel<<<512, 256>>>(conv1_w, w_msg, conv2_w, bn2_g, bn2_v, w_ih, w_hh);

    gemm_front<<<dim3(4, NROWS/128), 256>>>(x, bn1_g, bn1_b, bn1_m, bn1_v, b_msg);

    skernel<<<NROWS/8, 256>>>(x, w_se, b_se);

    conv2_kernel<<<dim3(2, NSEQ/128, BS), 256>>>(x, bn2_g, bn2_b, bn2_m, bn2_v);

    nmp_kernel<<<dim3(NSEQ/64, BS), 256>>>(mask);

    gemm_gi<<<dim3(6, NROWS/128), 256>>>();
    gemm_gh<<<dim3(6, NROWS/128), 256>>>(x);

    gate_kernel<<<NROWS*64/256, 256>>>(x, b_ih, b_hh, out);
}

// round 4
// speedup vs baseline: 1.6993x; 1.6334x over previous
#include <cuda_runtime.h>
#include <cuda_bf16.h>
#include <math.h>
#include <stdint.h>

#define BS   16
#define NSEQ 2048
#define DIM  256
#define NROWS (BS*NSEQ)   // 32768

// ---------------- scratch (device globals) --------------------------------
__device__ float g_msg[NROWS*DIM];
__device__ float g_s[NROWS*4];
__device__ float g_gi[(size_t)NROWS*768];
__device__ float g_gh[(size_t)NROWS*768];

// bf16 hi/lo split activations
__device__ __nv_bfloat16 g_xh[NROWS*DIM],  g_xl[NROWS*DIM];
__device__ __nv_bfloat16 g_h1h[NROWS*DIM], g_h1l[NROWS*DIM];
__device__ __nv_bfloat16 g_xch[NROWS*DIM], g_xcl[NROWS*DIM];
__device__ __nv_bfloat16 g_xnh[NROWS*DIM], g_xnl[NROWS*DIM];

// bf16 hi/lo split weights ([out][in], K-major)
__device__ __nv_bfloat16 g_wfh[512*256],  g_wfl[512*256];     // front: [conv1|w_msg]
__device__ __nv_bfloat16 g_w2h[256*4352], g_w2l[256*4352];    // conv2: [o][tap*256+ic]*bn2sc
__device__ __nv_bfloat16 g_wihh[768*512], g_wihl[768*512];
__device__ __nv_bfloat16 g_whhh[768*256], g_whhl[768*256];

// bn constants
__device__ float g_sc1[DIM], g_sh1[DIM], g_sh2[DIM], g_bmsg[DIM];

// ---------------- helpers --------------------------------------------------
__device__ __forceinline__ uint32_t smem_u32(const void* p) {
    uint32_t a;
    asm("{ .reg .u64 t; cvta.to.shared.u64 t, %1; cvt.u32.u64 %0, t; }"
        : "=r"(a) : "l"(p));
    return a;
}

// hi/lo split pack: returns packed hi pair, writes packed lo pair
__device__ __forceinline__ uint32_t pksplit(float a, float b, uint32_t& lo) {
    __nv_bfloat16 ha = __float2bfloat16(a), hb = __float2bfloat16(b);
    float la = a - __bfloat162float(ha), lb = b - __bfloat162float(hb);
    __nv_bfloat16 hla = __float2bfloat16(la), hlb = __float2bfloat16(lb);
    lo = (uint32_t)__bfloat16_as_ushort(hla) | ((uint32_t)__bfloat16_as_ushort(hlb) << 16);
    return (uint32_t)__bfloat16_as_ushort(ha) | ((uint32_t)__bfloat16_as_ushort(hb) << 16);
}

#define LDMX4(r0,r1,r2,r3,addr) \
    asm volatile("ldmatrix.sync.aligned.m8n8.x4.shared.b16 {%0,%1,%2,%3}, [%4];" \
        : "=r"(r0),"=r"(r1),"=r"(r2),"=r"(r3) : "r"(addr))

#define MMA_BF16(d, a, b0, b1) \
    asm volatile("mma.sync.aligned.m16n8k16.row.col.f32.bf16.bf16.f32 " \
        "{%0,%1,%2,%3}, {%4,%5,%6,%7}, {%8,%9}, {%0,%1,%2,%3};" \
        : "+f"((d)[0]),"+f"((d)[1]),"+f"((d)[2]),"+f"((d)[3]) \
        : "r"((a)[0]),"r"((a)[1]),"r"((a)[2]),"r"((a)[3]), "r"(b0),"r"(b1))

// ---------------- repack: weights -> bf16 split, bn consts, x split -------
__global__ void repack_kernel(const float* __restrict__ x,
                              const float* __restrict__ conv1_w,
                              const float* __restrict__ w_msg,
                              const float* __restrict__ conv2_w,
                              const float* __restrict__ bn1_g, const float* __restrict__ bn1_b,
                              const float* __restrict__ bn1_m, const float* __restrict__ bn1_v,
                              const float* __restrict__ bn2_g, const float* __restrict__ bn2_b,
                              const float* __restrict__ bn2_m, const float* __restrict__ bn2_v,
                              const float* __restrict__ b_msg,
                              const float* __restrict__ w_ih,
                              const float* __restrict__ w_hh) {
    int stride = gridDim.x * blockDim.x;
    int idx = blockIdx.x * blockDim.x + threadIdx.x;
    if (idx < DIM) {
        float sc = bn1_g[idx] * rsqrtf(bn1_v[idx] + 1e-5f);
        g_sc1[idx] = sc;
        g_sh1[idx] = bn1_b[idx] - bn1_m[idx]*sc;
        float sc2 = bn2_g[idx] * rsqrtf(bn2_v[idx] + 1e-5f);
        g_sh2[idx] = bn2_b[idx] - bn2_m[idx]*sc2;
        g_bmsg[idx] = b_msg[idx];
    }
    for (int i = idx; i < 512*256; i += stride) {
        int n = i >> 8, k = i & 255;
        float v = (n < 256) ? conv1_w[n*256 + k] : w_msg[(n-256)*256 + k];
        __nv_bfloat16 h = __float2bfloat16(v);
        g_wfh[i] = h; g_wfl[i] = __float2bfloat16(v - __bfloat162float(h));
    }
    for (int i = idx; i < 256*4352; i += stride) {
        int o = i / 4352, kk = i - o*4352;
        int tap = kk >> 8, ic = kk & 255;
        float sc = bn2_g[o] * rsqrtf(bn2_v[o] + 1e-5f);
        float v = conv2_w[(o*256 + ic)*17 + tap] * sc;
        __nv_bfloat16 h = __float2bfloat16(v);
        g_w2h[i] = h; g_w2l[i] = __float2bfloat16(v - __bfloat162float(h));
    }
    for (int i = idx; i < 768*512; i += stride) {
        float v = w_ih[i];
        __nv_bfloat16 h = __float2bfloat16(v);
        g_wihh[i] = h; g_wihl[i] = __float2bfloat16(v - __bfloat162float(h));
    }
    for (int i = idx; i < 768*256; i += stride) {
        float v = w_hh[i];
        __nv_bfloat16 h = __float2bfloat16(v);
        g_whhh[i] = h; g_whhl[i] = __float2bfloat16(v - __bfloat162float(h));
    }
    for (int i = idx; i < NROWS*DIM; i += stride) {
        float v = x[i];
        __nv_bfloat16 h = __float2bfloat16(v);
        g_xh[i] = h; g_xl[i] = __float2bfloat16(v - __bfloat162float(h));
    }
}

// ================= HMMA GEMM (128x128 tile, bf16 split, mma.sync) =========
// MODE: 0=FRONT (N=512,K=256), 1=CONV2 (K=4352), 2=GI (N=768,K=512), 3=GH (N=768,K=256)
// smem per stage: 4 arrays x 128 rows x 80B pitch = 40960B; double buffered.
#define PITCH 80
#define ARR   10240
#define STAGE 40960
#define SM_AHI(s) ((s)*STAGE + 0)
#define SM_ALO(s) ((s)*STAGE + ARR)
#define SM_BHI(s) ((s)*STAGE + 2*ARR)
#define SM_BLO(s) ((s)*STAGE + 3*ARR)
#define GEMM_SMEM 81920

template<int MODE>
__global__ void __launch_bounds__(256) mma_gemm(const float* __restrict__ x) {
    extern __shared__ char smem[];
    const int tid  = threadIdx.x;
    const int wid  = tid >> 5, lane = tid & 31;
    const int warp_m = wid & 1;        // 2 x 64 rows
    const int warp_n = wid >> 1;       // 4 x 32 cols
    const int gid  = lane >> 2, tid4 = lane & 3;
    const uint32_t sb = smem_u32(smem);

    constexpr int KT = (MODE==0) ? 256 : (MODE==1) ? 4352 : (MODE==2) ? 512 : 256;
    constexpr int NC = KT / 32;
    const int col0 = blockIdx.x * 128;
    const int bz = blockIdx.z;
    const int t0 = blockIdx.y * 128;
    const int row0 = (MODE==1) ? (bz*NSEQ + t0) : t0;

    // ldmatrix lane-address components (byte offsets within an array)
    const uint32_t aOff = (uint32_t)(lane & 15)*PITCH + (uint32_t)(lane >> 4)*16;
    const uint32_t bOff = (uint32_t)(((lane >> 4) << 3) + (lane & 7))*PITCH
                        + (uint32_t)((lane >> 3) & 1)*16;

    float acc[4][4][4] = {};
    uint4 pA0h, pA1h, pA0l, pA1l, pB0h, pB1h, pB0l, pB1l;

#define LOADC(c) { \
    int idx0 = tid, idx1 = tid + 256; \
    int r0_ = idx0 >> 2, u0_ = idx0 & 3; \
    int r1_ = idx1 >> 2, u1_ = idx1 & 3; \
    if (MODE == 0) { \
        size_t a0 = (size_t)(row0+r0_)*256 + (c)*32 + u0_*8; \
        size_t a1 = (size_t)(row0+r1_)*256 + (c)*32 + u1_*8; \
        pA0h = *(const uint4*)&g_xh[a0]; pA0l = *(const uint4*)&g_xl[a0]; \
        pA1h = *(const uint4*)&g_xh[a1]; pA1l = *(const uint4*)&g_xl[a1]; \
        size_t b0 = (size_t)(col0+r0_)*256 + (c)*32 + u0_*8; \
        size_t b1 = (size_t)(col0+r1_)*256 + (c)*32 + u1_*8; \
        pB0h = *(const uint4*)&g_wfh[b0]; pB0l = *(const uint4*)&g_wfl[b0]; \
        pB1h = *(const uint4*)&g_wfh[b1]; pB1l = *(const uint4*)&g_wfl[b1]; \
    } else if (MODE == 1) { \
        int tap = (c) >> 3, kloc = ((c) & 7)*32; \
        int t1_ = t0 + r0_ + tap - 8, t2_ = t0 + r1_ + tap - 8; \
        pA0h = make_uint4(0,0,0,0); pA0l = make_uint4(0,0,0,0); \
        pA1h = make_uint4(0,0,0,0); pA1l = make_uint4(0,0,0,0); \
        if ((unsigned)t1_ < (unsigned)NSEQ) { \
            size_t a0 = ((size_t)bz*NSEQ + t1_)*256 + kloc + u0_*8; \
            pA0h = *(const uint4*)&g_h1h[a0]; pA0l = *(const uint4*)&g_h1l[a0]; } \
        if ((unsigned)t2_ < (unsigned)NSEQ) { \
            size_t a1 = ((size_t)bz*NSEQ + t2_)*256 + kloc + u1_*8; \
            pA1h = *(const uint4*)&g_h1h[a1]; pA1l = *(const uint4*)&g_h1l[a1]; } \
        size_t b0 = (size_t)(col0+r0_)*4352 + (c)*32 + u0_*8; \
        size_t b1 = (size_t)(col0+r1_)*4352 + (c)*32 + u1_*8; \
        pB0h = *(const uint4*)&g_w2h[b0]; pB0l = *(const uint4*)&g_w2l[b0]; \
        pB1h = *(const uint4*)&g_w2h[b1]; pB1l = *(const uint4*)&g_w2l[b1]; \
    } else if (MODE == 2) { \
        const __nv_bfloat16* srch = ((c) < 8) ? g_xch : g_xnh; \
        const __nv_bfloat16* srcl = ((c) < 8) ? g_xcl : g_xnl; \
        int kk_ = ((c) & 7)*32; \
        size_t a0 = (size_t)(row0+r0_)*256 + kk_ + u0_*8; \
        size_t a1 = (size_t)(row0+r1_)*256 + kk_ + u1_*8; \
        pA0h = *(const uint4*)&srch[a0]; pA0l = *(const uint4*)&srcl[a0]; \
        pA1h = *(const uint4*)&srch[a1]; pA1l = *(const uint4*)&srcl[a1]; \
        size_t b0 = (size_t)(col0+r0_)*512 + (c)*32 + u0_*8; \
        size_t b1 = (size_t)(col0+r1_)*512 + (c)*32 + u1_*8; \
        pB0h = *(const uint4*)&g_wihh[b0]; pB0l = *(const uint4*)&g_wihl[b0]; \
        pB1h = *(const uint4*)&g_wihh[b1]; pB1l = *(const uint4*)&g_wihl[b1]; \
    } else { \
        size_t a0 = (size_t)(row0+r0_)*256 + (c)*32 + u0_*8; \
        size_t a1 = (size_t)(row0+r1_)*256 + (c)*32 + u1_*8; \
        pA0h = *(const uint4*)&g_xh[a0]; pA0l = *(const uint4*)&g_xl[a0]; \
        pA1h = *(const uint4*)&g_xh[a1]; pA1l = *(const uint4*)&g_xl[a1]; \
        size_t b0 = (size_t)(col0+r0_)*256 + (c)*32 + u0_*8; \
        size_t b1 = (size_t)(col0+r1_)*256 + (c)*32 + u1_*8; \
        pB0h = *(const uint4*)&g_whhh[b0]; pB0l = *(const uint4*)&g_whhl[b0]; \
        pB1h = *(const uint4*)&g_whhh[b1]; pB1l = *(const uint4*)&g_whhl[b1]; \
    } }

#define STSC(s) { \
    int idx0 = tid, idx1 = tid + 256; \
    int o0 = (idx0 >> 2)*PITCH + (idx0 & 3)*16; \
    int o1 = (idx1 >> 2)*PITCH + (idx1 & 3)*16; \
    *(uint4*)(smem + SM_AHI(s) + o0) = pA0h; *(uint4*)(smem + SM_AHI(s) + o1) = pA1h; \
    *(uint4*)(smem + SM_ALO(s) + o0) = pA0l; *(uint4*)(smem + SM_ALO(s) + o1) = pA1l; \
    *(uint4*)(smem + SM_BHI(s) + o0) = pB0h; *(uint4*)(smem + SM_BHI(s) + o1) = pB1h; \
    *(uint4*)(smem + SM_BLO(s) + o0) = pB0l; *(uint4*)(smem + SM_BLO(s) + o1) = pB1l; }

#define COMPUTE(s) { \
    _Pragma("unroll") \
    for (int ks = 0; ks < 2; ks++) { \
        uint32_t Ah[4][4], Al[4][4], Bh[2][4], Bl[2][4]; \
        _Pragma("unroll") \
        for (int mi = 0; mi < 4; mi++) { \
            uint32_t ad = sb + SM_AHI(s) + (warp_m*64 + mi*16)*PITCH + ks*32 + aOff; \
            LDMX4(Ah[mi][0],Ah[mi][1],Ah[mi][2],Ah[mi][3], ad); \
            ad = sb + SM_ALO(s) + (warp_m*64 + mi*16)*PITCH + ks*32 + aOff; \
            LDMX4(Al[mi][0],Al[mi][1],Al[mi][2],Al[mi][3], ad); \
        } \
        _Pragma("unroll") \
        for (int pj = 0; pj < 2; pj++) { \
            uint32_t bd = sb + SM_BHI(s) + (warp_n*32 + pj*16)*PITCH + ks*32 + bOff; \
            LDMX4(Bh[pj][0],Bh[pj][1],Bh[pj][2],Bh[pj][3], bd); \
            bd = sb + SM_BLO(s) + (warp_n*32 + pj*16)*PITCH + ks*32 + bOff; \
            LDMX4(Bl[pj][0],Bl[pj][1],Bl[pj][2],Bl[pj][3], bd); \
        } \
        _Pragma("unroll") \
        for (int mi = 0; mi < 4; mi++) \
            _Pragma("unroll") \
            for (int pj = 0; pj < 2; pj++) \
                _Pragma("unroll") \
                for (int h = 0; h < 2; h++) { \
                    float* D = acc[mi][pj*2 + h]; \
                    MMA_BF16(D, Ah[mi], Bh[pj][h*2], Bh[pj][h*2+1]); \
                    MMA_BF16(D, Ah[mi], Bl[pj][h*2], Bl[pj][h*2+1]); \
                    MMA_BF16(D, Al[mi], Bh[pj][h*2], Bh[pj][h*2+1]); \
                } \
    } }

    LOADC(0); STSC(0);
    __syncthreads();
    for (int c = 0; c < NC; c++) {
        int buf = c & 1;
        if (c+1 < NC) LOADC(c+1);
        COMPUTE(buf);
        if (c+1 < NC) STSC(1-buf);
        __syncthreads();
    }
#undef LOADC
#undef STSC
#undef COMPUTE

    // ---------------- epilogue ----------------
    #pragma unroll
    for (int mi = 0; mi < 4; mi++) {
        #pragma unroll
        for (int nj = 0; nj < 4; nj++) {
            int c = col0 + warp_n*32 + nj*8 + tid4*2;
            size_t r1 = (size_t)row0 + warp_m*64 + mi*16 + gid;
            size_t r2 = r1 + 8;
            float v00 = acc[mi][nj][0], v01 = acc[mi][nj][1];
            float v10 = acc[mi][nj][2], v11 = acc[mi][nj][3];
            if (MODE == 0) {
                if (c < 256) {
                    float sc0 = g_sc1[c], sc1 = g_sc1[c+1];
                    float sh0 = g_sh1[c], sh1 = g_sh1[c+1];
                    uint32_t lo; uint32_t hi;
                    hi = pksplit(fmaxf(v00*sc0+sh0,0.f), fmaxf(v01*sc1+sh1,0.f), lo);
                    *(uint32_t*)&g_h1h[r1*256 + c] = hi; *(uint32_t*)&g_h1l[r1*256 + c] = lo;
                    hi = pksplit(fmaxf(v10*sc0+sh0,0.f), fmaxf(v11*sc1+sh1,0.f), lo);
                    *(uint32_t*)&g_h1h[r2*256 + c] = hi; *(uint32_t*)&g_h1l[r2*256 + c] = lo;
                } else {
                    int cc = c - 256;
                    float b0 = g_bmsg[cc], b1 = g_bmsg[cc+1];
                    *(float2*)&g_msg[r1*256 + cc] =
                        make_float2(fmaxf(v00+b0,0.f), fmaxf(v01+b1,0.f));
                    *(float2*)&g_msg[r2*256 + cc] =
                        make_float2(fmaxf(v10+b0,0.f), fmaxf(v11+b1,0.f));
                }
            } else if (MODE == 1) {
                float sh0 = g_sh2[c], sh1 = g_sh2[c+1];
                uint32_t lo; uint32_t hi;
                float a0 = fmaxf(v00 + sh0 + x[r1*256+c],   0.f);
                float a1 = fmaxf(v01 + sh1 + x[r1*256+c+1], 0.f);
                hi = pksplit(a0, a1, lo);
                *(uint32_t*)&g_xch[r1*256 + c] = hi; *(uint32_t*)&g_xcl[r1*256 + c] = lo;
                a0 = fmaxf(v10 + sh0 + x[r2*256+c],   0.f);
                a1 = fmaxf(v11 + sh1 + x[r2*256+c+1], 0.f);
                hi = pksplit(a0, a1, lo);
                *(uint32_t*)&g_xch[r2*256 + c] = hi; *(uint32_t*)&g_xcl[r2*256 + c] = lo;
            } else if (MODE == 2) {
                *(float2*)&g_gi[r1*768 + c] = make_float2(v00, v01);
                *(float2*)&g_gi[r2*768 + c] = make_float2(v10, v11);
            } else {
                *(float2*)&g_gh[r1*768 + c] = make_float2(v00, v01);
                *(float2*)&g_gh[r2*768 + c] = make_float2(v10, v11);
            }
        }
    }
}

// ---------------- s / sq ---------------------------------------------------
__global__ void skernel(const float* __restrict__ x,
                        const float* __restrict__ w_se,
                        const float* __restrict__ b_se) {
    int row = blockIdx.x * 8 + (threadIdx.x >> 5);
    int lane = threadIdx.x & 31;
    float p0=0.f, p1=0.f, p2=0.f;
    for (int k = lane; k < DIM; k += 32) {
        float xv = x[(size_t)row*DIM + k];
        p0 += xv * w_se[k];
        p1 += xv * w_se[DIM + k];
        p2 += xv * w_se[2*DIM + k];
    }
    #pragma unroll
    for (int off = 16; off > 0; off >>= 1) {
        p0 += __shfl_down_sync(0xffffffffu, p0, off);
        p1 += __shfl_down_sync(0xffffffffu, p1, off);
        p2 += __shfl_down_sync(0xffffffffu, p2, off);
    }
    if (lane == 0) {
        p0 += b_se[0]; p1 += b_se[1]; p2 += b_se[2];
        g_s[row*4+0] = p0; g_s[row*4+1] = p1; g_s[row*4+2] = p2;
        g_s[row*4+3] = p0*p0 + p1*p1 + p2*p2;
    }
}

// ---------------- fused NMP: x_nmp = (exp(-dist)*mask) @ msg --------------
__global__ void __launch_bounds__(256) nmp_kernel(const float* __restrict__ mask) {
    __shared__ float sMsg[32*DIM];
    __shared__ float sW[64*32];
    __shared__ float sSn[64*4];
    __shared__ float sSm[32*4];
    const int b  = blockIdx.y;
    const int n0 = blockIdx.x * 64;
    const int tid = threadIdx.x;
    const int rg = tid >> 5;
    const int cg = tid & 31;

    sSn[tid] = g_s[(size_t)(b*NSEQ + n0)*4 + tid];
    float acc[8][8] = {};
    const float* msrc = &g_msg[(size_t)b*NSEQ*DIM];
    const size_t mbase = ((size_t)b*NSEQ + n0) * NSEQ;

    for (int m0 = 0; m0 < NSEQ; m0 += 32) {
        __syncthreads();
        {
            const float4* src4 = (const float4*)&msrc[(size_t)m0*DIM];
            float4* dst4 = (float4*)sMsg;
            #pragma unroll
            for (int q = 0; q < 8; q++) dst4[tid + 256*q] = src4[tid + 256*q];
        }
        if (tid < 128) sSm[tid] = g_s[(size_t)(b*NSEQ + m0)*4 + tid];
        __syncthreads();
        #pragma unroll
        for (int q = 0; q < 8; q++) {
            int lin = tid + 256*q;
            int rr = lin >> 5, mm = lin & 31;
            float dd = sSn[rr*4+3] + sSm[mm*4+3]
                    - 2.0f*(sSn[rr*4+0]*sSm[mm*4+0]
                          + sSn[rr*4+1]*sSm[mm*4+1]
                          + sSn[rr*4+2]*sSm[mm*4+2]);
            float mk = mask[mbase + (size_t)rr*NSEQ + m0 + mm];
            sW[rr*32 + mm] = __expf(-dd) * mk;
        }
        __syncthreads();
        #pragma unroll
        for (int mm = 0; mm < 32; mm++) {
            float w[8];
            #pragma unroll
            for (int p = 0; p < 8; p++) w[p] = sW[(rg + 8*p)*32 + mm];
            float4 v0 = *(float4*)&sMsg[mm*DIM + cg*8];
            float4 v1 = *(float4*)&sMsg[mm*DIM + cg*8 + 4];
            float mv[8] = {v0.x,v0.y,v0.z,v0.w, v1.x,v1.y,v1.z,v1.w};
            #pragma unroll
            for (int p = 0; p < 8; p++)
                #pragma unroll
                for (int q = 0; q < 8; q++)
                    acc[p][q] += w[p]*mv[q];
        }
    }
    #pragma unroll
    for (int p = 0; p < 8; p++) {
        size_t row = (size_t)b*NSEQ + n0 + rg + 8*p;
        uint4 vh, vl;
        vh.x = pksplit(acc[p][0], acc[p][1], vl.x);
        vh.y = pksplit(acc[p][2], acc[p][3], vl.y);
        vh.z = pksplit(acc[p][4], acc[p][5], vl.z);
        vh.w = pksplit(acc[p][6], acc[p][7], vl.w);
        *(uint4*)&g_xnh[row*DIM + cg*8] = vh;
        *(uint4*)&g_xnl[row*DIM + cg*8] = vl;
    }
}

// ---------------- gate epilogue ------------------------------------------
__global__ void gate_kernel(const float* __restrict__ x,
                            const float* __restrict__ b_ih,
                            const float* __restrict__ b_hh,
                            float* __restrict__ out) {
    int idx = blockIdx.x * blockDim.x + threadIdx.x;
    size_t r = idx >> 6;
    int c = (idx & 63) * 4;
    const float* gi = &g_gi[r*768];
    const float* gh = &g_gh[r*768];
    float4 gir = *(const float4*)&gi[c];
    float4 giz = *(const float4*)&gi[256 + c];
    float4 gin = *(const float4*)&gi[512 + c];
    float4 ghr = *(const float4*)&gh[c];
    float4 ghz = *(const float4*)&gh[256 + c];
    float4 ghn = *(const float4*)&gh[512 + c];
    float4 xv  = *(const float4*)&x[r*DIM + c];
    float4 o;
    #pragma unroll
    for (int q = 0; q < 4; q++) {
        float air = (&gir.x)[q] + b_ih[c+q]       + (&ghr.x)[q] + b_hh[c+q];
        float aiz = (&giz.x)[q] + b_ih[256 + c+q] + (&ghz.x)[q] + b_hh[256 + c+q];
        float rv = 1.0f/(1.0f + __expf(-air));
        float zv = 1.0f/(1.0f + __expf(-aiz));
        float nv = tanhf((&gin.x)[q] + b_ih[512 + c+q]
                       + rv*((&ghn.x)[q] + b_hh[512 + c+q]));
        (&o.x)[q] = (1.0f - zv)*nv + zv*(&xv.x)[q];
    }
    *(float4*)&out[r*DIM + c] = o;
}

// ---------------- launch --------------------------------------------------
extern "C" void kernel_launch(void* const* d_in, const int* in_sizes, int n_in,
                              void* d_out, int out_size) {
    const float* x       = (const float*)d_in[0];
    const float* mask    = (const float*)d_in[1];
    const float* w_se    = (const float*)d_in[2];
    const float* b_se    = (const float*)d_in[3];
    const float* conv1_w = (const float*)d_in[4];
    const float* bn1_g   = (const float*)d_in[5];
    const float* bn1_b   = (const float*)d_in[6];
    const float* bn1_m   = (const float*)d_in[7];
    const float* bn1_v   = (const float*)d_in[8];
    const float* conv2_w = (const float*)d_in[9];
    const float* bn2_g   = (const float*)d_in[10];
    const float* bn2_b   = (const float*)d_in[11];
    const float* bn2_m   = (const float*)d_in[12];
    const float* bn2_v   = (const float*)d_in[13];
    const float* w_msg   = (const float*)d_in[14];
    const float* b_msg   = (const float*)d_in[15];
    const float* w_ih    = (const float*)d_in[16];
    const float* b_ih    = (const float*)d_in[17];
    const float* w_hh    = (const float*)d_in[18];
    const float* b_hh    = (const float*)d_in[19];
    float* out = (float*)d_out;

    cudaFuncSetAttribute(mma_gemm<0>, cudaFuncAttributeMaxDynamicSharedMemorySize, GEMM_SMEM);
    cudaFuncSetAttribute(mma_gemm<1>, cudaFuncAttributeMaxDynamicSharedMemorySize, GEMM_SMEM);
    cudaFuncSetAttribute(mma_gemm<2>, cudaFuncAttributeMaxDynamicSharedMemorySize, GEMM_SMEM);
    cudaFuncSetAttribute(mma_gemm<3>, cudaFuncAttributeMaxDynamicSharedMemorySize, GEMM_SMEM);

    repack_kernel<<<1024, 256>>>(x, conv1_w, w_msg, conv2_w,
                                 bn1_g, bn1_b, bn1_m, bn1_v,
                                 bn2_g, bn2_b, bn2_m, bn2_v,
                                 b_msg, w_ih, w_hh);

    mma_gemm<0><<<dim3(4, NROWS/128), 256, GEMM_SMEM>>>(x);    // front: h1 + msg

    skernel<<<NROWS/8, 256>>>(x, w_se, b_se);

    mma_gemm<1><<<dim3(2, NSEQ/128, BS), 256, GEMM_SMEM>>>(x); // conv2 -> xconv

    nmp_kernel<<<dim3(NSEQ/64, BS), 256>>>(mask);              // -> xnmp (bf16 split)

    mma_gemm<2><<<dim3(6, NROWS/128), 256, GEMM_SMEM>>>(x);    // gi
    mma_gemm<3><<<dim3(6, NROWS/128), 256, GEMM_SMEM>>>(x);    // gh

    gate_kernel<<<NROWS*64/256, 256>>>(x, b_ih, b_hh, out);
}

// round 5
// speedup vs baseline: 2.2140x; 1.3029x over previous
#include <cuda_runtime.h>
#include <cuda_bf16.h>
#include <math.h>
#include <stdint.h>

#define BS   16
#define NSEQ 2048
#define DIM  256
#define NROWS (BS*NSEQ)   // 32768

// ---------------- scratch (device globals) --------------------------------
__device__ float g_s[NROWS*4];
__device__ float g_gi[(size_t)NROWS*768];
__device__ float g_gh[(size_t)NROWS*768];

// bf16 hi/lo split activations
__device__ __nv_bfloat16 g_xh[NROWS*DIM],  g_xl[NROWS*DIM];
__device__ __nv_bfloat16 g_h1h[NROWS*DIM], g_h1l[NROWS*DIM];
__device__ __nv_bfloat16 g_xch[NROWS*DIM], g_xcl[NROWS*DIM];
__device__ __nv_bfloat16 g_xnh[NROWS*DIM], g_xnl[NROWS*DIM];
__device__ __nv_bfloat16 g_msgh[NROWS*DIM], g_msgl[NROWS*DIM];

// bf16 hi/lo split weights ([out][in], K-major)
__device__ __nv_bfloat16 g_wfh[512*256],  g_wfl[512*256];
__device__ __nv_bfloat16 g_w2h[256*4352], g_w2l[256*4352];
__device__ __nv_bfloat16 g_wihh[768*512], g_wihl[768*512];
__device__ __nv_bfloat16 g_whhh[768*256], g_whhl[768*256];

// bn constants
__device__ float g_sc1[DIM], g_sh1[DIM], g_sh2[DIM], g_bmsg[DIM];

// ---------------- helpers --------------------------------------------------
__device__ __forceinline__ uint32_t smem_u32(const void* p) {
    uint32_t a;
    asm("{ .reg .u64 t; cvta.to.shared.u64 t, %1; cvt.u32.u64 %0, t; }"
        : "=r"(a) : "l"(p));
    return a;
}
__device__ __forceinline__ uint32_t pksplit(float a, float b, uint32_t& lo) {
    __nv_bfloat16 ha = __float2bfloat16(a), hb = __float2bfloat16(b);
    float la = a - __bfloat162float(ha), lb = b - __bfloat162float(hb);
    __nv_bfloat16 hla = __float2bfloat16(la), hlb = __float2bfloat16(lb);
    lo = (uint32_t)__bfloat16_as_ushort(hla) | ((uint32_t)__bfloat16_as_ushort(hlb) << 16);
    return (uint32_t)__bfloat16_as_ushort(ha) | ((uint32_t)__bfloat16_as_ushort(hb) << 16);
}

#define LDMX4(r0,r1,r2,r3,addr) \
    asm volatile("ldmatrix.sync.aligned.m8n8.x4.shared.b16 {%0,%1,%2,%3}, [%4];" \
        : "=r"(r0),"=r"(r1),"=r"(r2),"=r"(r3) : "r"(addr))
#define LDMX4T(r0,r1,r2,r3,addr) \
    asm volatile("ldmatrix.sync.aligned.m8n8.x4.trans.shared.b16 {%0,%1,%2,%3}, [%4];" \
        : "=r"(r0),"=r"(r1),"=r"(r2),"=r"(r3) : "r"(addr))
#define MMA_BF16(d, a, b0, b1) \
    asm volatile("mma.sync.aligned.m16n8k16.row.col.f32.bf16.bf16.f32 " \
        "{%0,%1,%2,%3}, {%4,%5,%6,%7}, {%8,%9}, {%0,%1,%2,%3};" \
        : "+f"((d)[0]),"+f"((d)[1]),"+f"((d)[2]),"+f"((d)[3]) \
        : "r"((a)[0]),"r"((a)[1]),"r"((a)[2]),"r"((a)[3]), "r"(b0),"r"(b1))

#define CPA16(dst, src) \
    asm volatile("cp.async.cg.shared.global [%0], [%1], 16;" :: "r"(dst), "l"(src))
#define CPA16Z(dst, src, sz) \
    asm volatile("cp.async.cg.shared.global [%0], [%1], 16, %2;" :: "r"(dst), "l"(src), "r"(sz))
#define CPCOMMIT() asm volatile("cp.async.commit_group;" ::: "memory")
#define CPWAIT(n)  asm volatile("cp.async.wait_group %0;" :: "n"(n) : "memory")

// ---------------- repack ---------------------------------------------------
__global__ void repack_kernel(const float* __restrict__ x,
                              const float* __restrict__ conv1_w,
                              const float* __restrict__ w_msg,
                              const float* __restrict__ conv2_w,
                              const float* __restrict__ bn1_g, const float* __restrict__ bn1_b,
                              const float* __restrict__ bn1_m, const float* __restrict__ bn1_v,
                              const float* __restrict__ bn2_g, const float* __restrict__ bn2_b,
                              const float* __restrict__ bn2_m, const float* __restrict__ bn2_v,
                              const float* __restrict__ b_msg,
                              const float* __restrict__ w_ih,
                              const float* __restrict__ w_hh) {
    int stride = gridDim.x * blockDim.x;
    int idx = blockIdx.x * blockDim.x + threadIdx.x;
    if (idx < DIM) {
        float sc = bn1_g[idx] * rsqrtf(bn1_v[idx] + 1e-5f);
        g_sc1[idx] = sc;
        g_sh1[idx] = bn1_b[idx] - bn1_m[idx]*sc;
        float sc2 = bn2_g[idx] * rsqrtf(bn2_v[idx] + 1e-5f);
        g_sh2[idx] = bn2_b[idx] - bn2_m[idx]*sc2;
        g_bmsg[idx] = b_msg[idx];
    }
    for (int i = idx; i < 512*256; i += stride) {
        int n = i >> 8, k = i & 255;
        float v = (n < 256) ? conv1_w[n*256 + k] : w_msg[(n-256)*256 + k];
        __nv_bfloat16 h = __float2bfloat16(v);
        g_wfh[i] = h; g_wfl[i] = __float2bfloat16(v - __bfloat162float(h));
    }
    for (int i = idx; i < 256*4352; i += stride) {
        int o = i / 4352, kk = i - o*4352;
        int tap = kk >> 8, ic = kk & 255;
        float sc = bn2_g[o] * rsqrtf(bn2_v[o] + 1e-5f);
        float v = conv2_w[(o*256 + ic)*17 + tap] * sc;
        __nv_bfloat16 h = __float2bfloat16(v);
        g_w2h[i] = h; g_w2l[i] = __float2bfloat16(v - __bfloat162float(h));
    }
    for (int i = idx; i < 768*512; i += stride) {
        float v = w_ih[i];
        __nv_bfloat16 h = __float2bfloat16(v);
        g_wihh[i] = h; g_wihl[i] = __float2bfloat16(v - __bfloat162float(h));
    }
    for (int i = idx; i < 768*256; i += stride) {
        float v = w_hh[i];
        __nv_bfloat16 h = __float2bfloat16(v);
        g_whhh[i] = h; g_whhl[i] = __float2bfloat16(v - __bfloat162float(h));
    }
    for (int i = idx; i < NROWS*DIM; i += stride) {
        float v = x[i];
        __nv_bfloat16 h = __float2bfloat16(v);
        g_xh[i] = h; g_xl[i] = __float2bfloat16(v - __bfloat162float(h));
    }
}

// ================= HMMA GEMM: cp.async 3-stage pipeline ====================
#define PITCH 80
#define ARR   10240
#define STAGE 40960
#define SM_AHI(s) ((s)*STAGE + 0)
#define SM_ALO(s) ((s)*STAGE + ARR)
#define SM_BHI(s) ((s)*STAGE + 2*ARR)
#define SM_BLO(s) ((s)*STAGE + 3*ARR)
#define GEMM_SMEM (3*STAGE)

template<int MODE>
__global__ void __launch_bounds__(256) mma_gemm(const float* __restrict__ x) {
    extern __shared__ char smem[];
    const int tid  = threadIdx.x;
    const int wid  = tid >> 5, lane = tid & 31;
    const int warp_m = wid & 1;
    const int warp_n = wid >> 1;
    const int gid  = lane >> 2, tid4 = lane & 3;
    const uint32_t sb = smem_u32(smem);

    constexpr int KT = (MODE==0) ? 256 : (MODE==1) ? 4352 : (MODE==2) ? 512 : 256;
    constexpr int NC = KT / 32;
    const int col0 = blockIdx.x * 128;
    const int bz = blockIdx.z;
    const int t0 = blockIdx.y * 128;
    const int row0 = (MODE==1) ? (bz*NSEQ + t0) : t0;

    const uint32_t aOff = (uint32_t)(lane & 15)*PITCH + (uint32_t)(lane >> 4)*16;
    const uint32_t bOff = (uint32_t)(((lane >> 4) << 3) + (lane & 7))*PITCH
                        + (uint32_t)((lane >> 3) & 1)*16;

    const int r0_ = tid >> 2, u_ = tid & 3;
    const uint32_t o0 = (uint32_t)(r0_*PITCH + u_*16);
    const uint32_t o1 = o0 + 64*PITCH;

    float acc[4][4][4] = {};

#define CPA_TILE(c, s) { \
    uint32_t dA = sb + SM_AHI(s), dAl = sb + SM_ALO(s); \
    uint32_t dB = sb + SM_BHI(s), dBl = sb + SM_BLO(s); \
    if (MODE == 0) { \
        size_t a0 = (size_t)(row0+r0_)*256 + (c)*32 + u_*8, a1 = a0 + 64*256; \
        CPA16(dA+o0,  g_xh+a0); CPA16(dA+o1,  g_xh+a1); \
        CPA16(dAl+o0, g_xl+a0); CPA16(dAl+o1, g_xl+a1); \
        size_t b0 = (size_t)(col0+r0_)*256 + (c)*32 + u_*8, b1 = b0 + 64*256; \
        CPA16(dB+o0,  g_wfh+b0); CPA16(dB+o1,  g_wfh+b1); \
        CPA16(dBl+o0, g_wfl+b0); CPA16(dBl+o1, g_wfl+b1); \
    } else if (MODE == 1) { \
        int tap = (c) >> 3, kloc = ((c) & 7)*32; \
        int t1 = t0 + r0_ + tap - 8, t2 = t1 + 64; \
        uint32_t z1 = ((unsigned)t1 < (unsigned)NSEQ) ? 16u : 0u; \
        uint32_t z2 = ((unsigned)t2 < (unsigned)NSEQ) ? 16u : 0u; \
        int tc1 = min(max(t1, 0), NSEQ-1), tc2 = min(max(t2, 0), NSEQ-1); \
        size_t a0 = ((size_t)bz*NSEQ + tc1)*256 + kloc + u_*8; \
        size_t a1 = ((size_t)bz*NSEQ + tc2)*256 + kloc + u_*8; \
        CPA16Z(dA+o0,  g_h1h+a0, z1); CPA16Z(dA+o1,  g_h1h+a1, z2); \
        CPA16Z(dAl+o0, g_h1l+a0, z1); CPA16Z(dAl+o1, g_h1l+a1, z2); \
        size_t b0 = (size_t)(col0+r0_)*4352 + (c)*32 + u_*8, b1 = b0 + 64*4352; \
        CPA16(dB+o0,  g_w2h+b0); CPA16(dB+o1,  g_w2h+b1); \
        CPA16(dBl+o0, g_w2l+b0); CPA16(dBl+o1, g_w2l+b1); \
    } else if (MODE == 2) { \
        const __nv_bfloat16* sh_ = ((c) < 8) ? g_xch : g_xnh; \
        const __nv_bfloat16* sl_ = ((c) < 8) ? g_xcl : g_xnl; \
        int kk_ = ((c) & 7)*32; \
        size_t a0 = (size_t)(row0+r0_)*256 + kk_ + u_*8, a1 = a0 + 64*256; \
        CPA16(dA+o0,  sh_+a0); CPA16(dA+o1,  sh_+a1); \
        CPA16(dAl+o0, sl_+a0); CPA16(dAl+o1, sl_+a1); \
        size_t b0 = (size_t)(col0+r0_)*512 + (c)*32 + u_*8, b1 = b0 + 64*512; \
        CPA16(dB+o0,  g_wihh+b0); CPA16(dB+o1,  g_wihh+b1); \
        CPA16(dBl+o0, g_wihl+b0); CPA16(dBl+o1, g_wihl+b1); \
    } else { \
        size_t a0 = (size_t)(row0+r0_)*256 + (c)*32 + u_*8, a1 = a0 + 64*256; \
        CPA16(dA+o0,  g_xh+a0); CPA16(dA+o1,  g_xh+a1); \
        CPA16(dAl+o0, g_xl+a0); CPA16(dAl+o1, g_xl+a1); \
        size_t b0 = (size_t)(col0+r0_)*256 + (c)*32 + u_*8, b1 = b0 + 64*256; \
        CPA16(dB+o0,  g_whhh+b0); CPA16(dB+o1,  g_whhh+b1); \
        CPA16(dBl+o0, g_whhl+b0); CPA16(dBl+o1, g_whhl+b1); \
    } }

#define COMPUTE(s) { \
    _Pragma("unroll") \
    for (int ks = 0; ks < 2; ks++) { \
        uint32_t Ah[4][4], Al[4][4], Bh[2][4], Bl[2][4]; \
        _Pragma("unroll") \
        for (int mi = 0; mi < 4; mi++) { \
            uint32_t ad = sb + SM_AHI(s) + (warp_m*64 + mi*16)*PITCH + ks*32 + aOff; \
            LDMX4(Ah[mi][0],Ah[mi][1],Ah[mi][2],Ah[mi][3], ad); \
            ad = sb + SM_ALO(s) + (warp_m*64 + mi*16)*PITCH + ks*32 + aOff; \
            LDMX4(Al[mi][0],Al[mi][1],Al[mi][2],Al[mi][3], ad); \
        } \
        _Pragma("unroll") \
        for (int pj = 0; pj < 2; pj++) { \
            uint32_t bd = sb + SM_BHI(s) + (warp_n*32 + pj*16)*PITCH + ks*32 + bOff; \
            LDMX4(Bh[pj][0],Bh[pj][1],Bh[pj][2],Bh[pj][3], bd); \
            bd = sb + SM_BLO(s) + (warp_n*32 + pj*16)*PITCH + ks*32 + bOff; \
            LDMX4(Bl[pj][0],Bl[pj][1],Bl[pj][2],Bl[pj][3], bd); \
        } \
        _Pragma("unroll") \
        for (int mi = 0; mi < 4; mi++) \
            _Pragma("unroll") \
            for (int pj = 0; pj < 2; pj++) \
                _Pragma("unroll") \
                for (int h = 0; h < 2; h++) { \
                    float* D = acc[mi][pj*2 + h]; \
                    MMA_BF16(D, Ah[mi], Bh[pj][h*2], Bh[pj][h*2+1]); \
                    MMA_BF16(D, Ah[mi], Bl[pj][h*2], Bl[pj][h*2+1]); \
                    MMA_BF16(D, Al[mi], Bh[pj][h*2], Bh[pj][h*2+1]); \
                } \
    } }

    CPA_TILE(0, 0); CPCOMMIT();
    CPA_TILE(1, 1); CPCOMMIT();
    for (int c = 0; c < NC; c++) {
        if (c + 2 < NC) { int sl = (c+2) % 3; CPA_TILE(c+2, sl); }
        CPCOMMIT();
        CPWAIT(2);
        __syncthreads();
        COMPUTE(c % 3);
        __syncthreads();
    }
#undef CPA_TILE
#undef COMPUTE

    // ---------------- epilogue ----------------
    #pragma unroll
    for (int mi = 0; mi < 4; mi++) {
        #pragma unroll
        for (int nj = 0; nj < 4; nj++) {
            int c = col0 + warp_n*32 + nj*8 + tid4*2;
            size_t r1 = (size_t)row0 + warp_m*64 + mi*16 + gid;
            size_t r2 = r1 + 8;
            float v00 = acc[mi][nj][0], v01 = acc[mi][nj][1];
            float v10 = acc[mi][nj][2], v11 = acc[mi][nj][3];
            if (MODE == 0) {
                if (c < 256) {
                    float sc0 = g_sc1[c], sc1 = g_sc1[c+1];
                    float sh0 = g_sh1[c], sh1 = g_sh1[c+1];
                    uint32_t lo, hi;
                    hi = pksplit(fmaxf(v00*sc0+sh0,0.f), fmaxf(v01*sc1+sh1,0.f), lo);
                    *(uint32_t*)&g_h1h[r1*256 + c] = hi; *(uint32_t*)&g_h1l[r1*256 + c] = lo;
                    hi = pksplit(fmaxf(v10*sc0+sh0,0.f), fmaxf(v11*sc1+sh1,0.f), lo);
                    *(uint32_t*)&g_h1h[r2*256 + c] = hi; *(uint32_t*)&g_h1l[r2*256 + c] = lo;
                } else {
                    int cc = c - 256;
                    float b0 = g_bmsg[cc], b1 = g_bmsg[cc+1];
                    uint32_t lo, hi;
                    hi = pksplit(fmaxf(v00+b0,0.f), fmaxf(v01+b1,0.f), lo);
                    *(uint32_t*)&g_msgh[r1*256 + cc] = hi; *(uint32_t*)&g_msgl[r1*256 + cc] = lo;
                    hi = pksplit(fmaxf(v10+b0,0.f), fmaxf(v11+b1,0.f), lo);
                    *(uint32_t*)&g_msgh[r2*256 + cc] = hi; *(uint32_t*)&g_msgl[r2*256 + cc] = lo;
                }
            } else if (MODE == 1) {
                float sh0 = g_sh2[c], sh1 = g_sh2[c+1];
                uint32_t lo, hi;
                float a0 = fmaxf(v00 + sh0 + x[r1*256+c],   0.f);
                float a1 = fmaxf(v01 + sh1 + x[r1*256+c+1], 0.f);
                hi = pksplit(a0, a1, lo);
                *(uint32_t*)&g_xch[r1*256 + c] = hi; *(uint32_t*)&g_xcl[r1*256 + c] = lo;
                a0 = fmaxf(v10 + sh0 + x[r2*256+c],   0.f);
                a1 = fmaxf(v11 + sh1 + x[r2*256+c+1], 0.f);
                hi = pksplit(a0, a1, lo);
                *(uint32_t*)&g_xch[r2*256 + c] = hi; *(uint32_t*)&g_xcl[r2*256 + c] = lo;
            } else if (MODE == 2) {
                *(float2*)&g_gi[r1*768 + c] = make_float2(v00, v01);
                *(float2*)&g_gi[r2*768 + c] = make_float2(v10, v11);
            } else {
                *(float2*)&g_gh[r1*768 + c] = make_float2(v00, v01);
                *(float2*)&g_gh[r2*768 + c] = make_float2(v10, v11);
            }
        }
    }
}

// ---------------- s / sq ---------------------------------------------------
__global__ void skernel(const float* __restrict__ x,
                        const float* __restrict__ w_se,
                        const float* __restrict__ b_se) {
    int row = blockIdx.x * 8 + (threadIdx.x >> 5);
    int lane = threadIdx.x & 31;
    float p0=0.f, p1=0.f, p2=0.f;
    for (int k = lane; k < DIM; k += 32) {
        float xv = x[(size_t)row*DIM + k];
        p0 += xv * w_se[k];
        p1 += xv * w_se[DIM + k];
        p2 += xv * w_se[2*DIM + k];
    }
    #pragma unroll
    for (int off = 16; off > 0; off >>= 1) {
        p0 += __shfl_down_sync(0xffffffffu, p0, off);
        p1 += __shfl_down_sync(0xffffffffu, p1, off);
        p2 += __shfl_down_sync(0xffffffffu, p2, off);
    }
    if (lane == 0) {
        p0 += b_se[0]; p1 += b_se[1]; p2 += b_se[2];
        g_s[row*4+0] = p0; g_s[row*4+1] = p1; g_s[row*4+2] = p2;
        g_s[row*4+3] = p0*p0 + p1*p1 + p2*p2;
    }
}

// ---------------- tensorized NMP ------------------------------------------
// block: 64 n-rows x 256 d-cols, m-chunks of 32. 8 warps = 2(n) x 4(d).
#define NWP  80                 // W smem pitch bytes (32 bf16 = 64B data)
#define NWH  0                  // 64*80 = 5120
#define NWL  5120
#define NMPITCH 528             // msg row pitch bytes (256 bf16 = 512B data)
#define NMH(s) (10240 + (s)*33792)
#define NML(s) (NMH(s) + 16896)
#define NSS  77824              // sSn: 256 floats
#define NSM  78848              // sSm: 128 floats
#define NMP_SMEM 79872

__global__ void __launch_bounds__(256) nmp_kernel(const float* __restrict__ mask) {
    extern __shared__ char smem[];
    const uint32_t sb = smem_u32(smem);
    float* sSn = (float*)(smem + NSS);
    float* sSm = (float*)(smem + NSM);
    const int b  = blockIdx.y;
    const int n0 = blockIdx.x * 64;
    const int tid = threadIdx.x;
    const int wid = tid >> 5, lane = tid & 31;
    const int warp_n = wid & 1, warp_d = wid >> 1;
    const int gid = lane >> 2, tid4 = lane & 3;

    const uint32_t aOff  = (uint32_t)(lane & 15)*NWP + (uint32_t)(lane >> 4)*16;
    const uint32_t bOffT = (uint32_t)(lane & 15)*NMPITCH + (uint32_t)(lane >> 4)*16;

    const size_t mbase = ((size_t)b*NSEQ + n0) * NSEQ;
    sSn[tid] = g_s[((size_t)b*NSEQ + n0)*4 + tid];

    // msg cp.async: 8 x 16B per thread per chunk (hi 4, lo 4)
    const int mrow = tid >> 5;            // base row pattern (reused with +8q)
    const int mu   = tid & 31;            // 16B unit within 512B row

#define NMP_PREFETCH(c, s) { \
    uint32_t dh = sb + NMH(s), dl = sb + NML(s); \
    const __nv_bfloat16* srch = g_msgh + ((size_t)b*NSEQ + (c)*32)*256; \
    const __nv_bfloat16* srcl = g_msgl + ((size_t)b*NSEQ + (c)*32)*256; \
    _Pragma("unroll") \
    for (int q = 0; q < 4; q++) { \
        int row = mrow + q*8; \
        uint32_t o = (uint32_t)row*NMPITCH + (uint32_t)mu*16; \
        size_t gsrc = (size_t)row*256 + mu*8; \
        CPA16(dh + o, srch + gsrc); \
        CPA16(dl + o, srcl + gsrc); \
    } }

    NMP_PREFETCH(0, 0); CPCOMMIT();

    float acc[2][8][4] = {};
    const int rr = tid >> 2, mm0 = (tid & 3)*8;

    for (int c = 0; c < NSEQ/32; c++) {
        int s = c & 1;
        __syncthreads();                       // protect sW/sSm from prev MMA reads
        if (tid < 128) sSm[tid] = g_s[((size_t)b*NSEQ + c*32)*4 + tid];
        if (c+1 < NSEQ/32) { NMP_PREFETCH(c+1, 1-s); }
        CPCOMMIT();
        __syncthreads();                       // sSm ready
        // compute W tile 64x32 -> bf16 split in smem
        {
            float sn0 = sSn[rr*4+0], sn1 = sSn[rr*4+1], sn2 = sSn[rr*4+2], snq = sSn[rr*4+3];
            const float* mrow_p = &mask[mbase + (size_t)rr*NSEQ + c*32 + mm0];
            float4 mk0 = *(const float4*)mrow_p;
            float4 mk1 = *(const float4*)(mrow_p + 4);
            float v[8];
            #pragma unroll
            for (int q = 0; q < 8; q++) {
                int mm = mm0 + q;
                float dd = snq + sSm[mm*4+3]
                         - 2.0f*(sn0*sSm[mm*4+0] + sn1*sSm[mm*4+1] + sn2*sSm[mm*4+2]);
                float mk = (q < 4) ? (&mk0.x)[q] : (&mk1.x)[q-4];
                v[q] = __expf(-dd) * mk;
            }
            uint4 vh, vl;
            vh.x = pksplit(v[0], v[1], vl.x);
            vh.y = pksplit(v[2], v[3], vl.y);
            vh.z = pksplit(v[4], v[5], vl.z);
            vh.w = pksplit(v[6], v[7], vl.w);
            *(uint4*)(smem + NWH + rr*NWP + mm0*2) = vh;
            *(uint4*)(smem + NWL + rr*NWP + mm0*2) = vl;
        }
        CPWAIT(1);
        __syncthreads();                       // msg chunk c + W ready
        #pragma unroll
        for (int ks = 0; ks < 2; ks++) {
            uint32_t Ah[2][4], Al[2][4], Bh[4][4], Bl[4][4];
            #pragma unroll
            for (int mi = 0; mi < 2; mi++) {
                uint32_t ad = sb + NWH + (warp_n*32 + mi*16)*NWP + ks*32 + aOff;
                LDMX4(Ah[mi][0],Ah[mi][1],Ah[mi][2],Ah[mi][3], ad);
                ad = sb + NWL + (warp_n*32 + mi*16)*NWP + ks*32 + aOff;
                LDMX4(Al[mi][0],Al[mi][1],Al[mi][2],Al[mi][3], ad);
            }
            #pragma unroll
            for (int dj = 0; dj < 4; dj++) {
                uint32_t bd = sb + NMH(s) + (ks*16)*NMPITCH + (warp_d*64 + dj*16)*2 + bOffT;
                LDMX4T(Bh[dj][0],Bh[dj][1],Bh[dj][2],Bh[dj][3], bd);
                bd = sb + NML(s) + (ks*16)*NMPITCH + (warp_d*64 + dj*16)*2 + bOffT;
                LDMX4T(Bl[dj][0],Bl[dj][1],Bl[dj][2],Bl[dj][3], bd);
            }
            #pragma unroll
            for (int mi = 0; mi < 2; mi++)
                #pragma unroll
                for (int dj = 0; dj < 4; dj++)
                    #pragma unroll
                    for (int h = 0; h < 2; h++) {
                        float* D = acc[mi][dj*2 + h];
                        MMA_BF16(D, Ah[mi], Bh[dj][h*2], Bh[dj][h*2+1]);
                        MMA_BF16(D, Ah[mi], Bl[dj][h*2], Bl[dj][h*2+1]);
                        MMA_BF16(D, Al[mi], Bh[dj][h*2], Bh[dj][h*2+1]);
                    }
        }
    }
#undef NMP_PREFETCH

    // epilogue: write g_xnh/g_xnl
    #pragma unroll
    for (int mi = 0; mi < 2; mi++) {
        #pragma unroll
        for (int dj8 = 0; dj8 < 8; dj8++) {
            int d = warp_d*64 + dj8*8 + tid4*2;
            size_t r1 = (size_t)b*NSEQ + n0 + warp_n*32 + mi*16 + gid;
            size_t r2 = r1 + 8;
            uint32_t lo, hi;
            hi = pksplit(acc[mi][dj8][0], acc[mi][dj8][1], lo);
            *(uint32_t*)&g_xnh[r1*256 + d] = hi; *(uint32_t*)&g_xnl[r1*256 + d] = lo;
            hi = pksplit(acc[mi][dj8][2], acc[mi][dj8][3], lo);
            *(uint32_t*)&g_xnh[r2*256 + d] = hi; *(uint32_t*)&g_xnl[r2*256 + d] = lo;
        }
    }
}

// ---------------- gate epilogue ------------------------------------------
__global__ void gate_kernel(const float* __restrict__ x,
                            const float* __restrict__ b_ih,
                            const float* __restrict__ b_hh,
                            float* __restrict__ out) {
    int idx = blockIdx.x * blockDim.x + threadIdx.x;
    size_t r = idx >> 6;
    int c = (idx & 63) * 4;
    const float* gi = &g_gi[r*768];
    const float* gh = &g_gh[r*768];
    float4 gir = *(const float4*)&gi[c];
    float4 giz = *(const float4*)&gi[256 + c];
    float4 gin = *(const float4*)&gi[512 + c];
    float4 ghr = *(const float4*)&gh[c];
    float4 ghz = *(const float4*)&gh[256 + c];
    float4 ghn = *(const float4*)&gh[512 + c];
    float4 xv  = *(const float4*)&x[r*DIM + c];
    float4 o;
    #pragma unroll
    for (int q = 0; q < 4; q++) {
        float air = (&gir.x)[q] + b_ih[c+q]       + (&ghr.x)[q] + b_hh[c+q];
        float aiz = (&giz.x)[q] + b_ih[256 + c+q] + (&ghz.x)[q] + b_hh[256 + c+q];
        float rv = 1.0f/(1.0f + __expf(-air));
        float zv = 1.0f/(1.0f + __expf(-aiz));
        float nv = tanhf((&gin.x)[q] + b_ih[512 + c+q]
                       + rv*((&ghn.x)[q] + b_hh[512 + c+q]));
        (&o.x)[q] = (1.0f - zv)*nv + zv*(&xv.x)[q];
    }
    *(float4*)&out[r*DIM + c] = o;
}

// ---------------- launch --------------------------------------------------
extern "C" void kernel_launch(void* const* d_in, const int* in_sizes, int n_in,
                              void* d_out, int out_size) {
    const float* x       = (const float*)d_in[0];
    const float* mask    = (const float*)d_in[1];
    const float* w_se    = (const float*)d_in[2];
    const float* b_se    = (const float*)d_in[3];
    const float* conv1_w = (const float*)d_in[4];
    const float* bn1_g   = (const float*)d_in[5];
    const float* bn1_b   = (const float*)d_in[6];
    const float* bn1_m   = (const float*)d_in[7];
    const float* bn1_v   = (const float*)d_in[8];
    const float* conv2_w = (const float*)d_in[9];
    const float* bn2_g   = (const float*)d_in[10];
    const float* bn2_b   = (const float*)d_in[11];
    const float* bn2_m   = (const float*)d_in[12];
    const float* bn2_v   = (const float*)d_in[13];
    const float* w_msg   = (const float*)d_in[14];
    const float* b_msg   = (const float*)d_in[15];
    const float* w_ih    = (const float*)d_in[16];
    const float* b_ih    = (const float*)d_in[17];
    const float* w_hh    = (const float*)d_in[18];
    const float* b_hh    = (const float*)d_in[19];
    float* out = (float*)d_out;

    cudaFuncSetAttribute(mma_gemm<0>, cudaFuncAttributeMaxDynamicSharedMemorySize, GEMM_SMEM);
    cudaFuncSetAttribute(mma_gemm<1>, cudaFuncAttributeMaxDynamicSharedMemorySize, GEMM_SMEM);
    cudaFuncSetAttribute(mma_gemm<2>, cudaFuncAttributeMaxDynamicSharedMemorySize, GEMM_SMEM);
    cudaFuncSetAttribute(mma_gemm<3>, cudaFuncAttributeMaxDynamicSharedMemorySize, GEMM_SMEM);
    cudaFuncSetAttribute(nmp_kernel,  cudaFuncAttributeMaxDynamicSharedMemorySize, NMP_SMEM);

    repack_kernel<<<1024, 256>>>(x, conv1_w, w_msg, conv2_w,
                                 bn1_g, bn1_b, bn1_m, bn1_v,
                                 bn2_g, bn2_b, bn2_m, bn2_v,
                                 b_msg, w_ih, w_hh);

    mma_gemm<0><<<dim3(4, NROWS/128), 256, GEMM_SMEM>>>(x);    // front: h1 + msg

    skernel<<<NROWS/8, 256>>>(x, w_se, b_se);

    mma_gemm<1><<<dim3(2, NSEQ/128, BS), 256, GEMM_SMEM>>>(x); // conv2 -> xconv

    nmp_kernel<<<dim3(NSEQ/64, BS), 256, NMP_SMEM>>>(mask);    // -> xnmp (tensor)

    mma_gemm<2><<<dim3(6, NROWS/128), 256, GEMM_SMEM>>>(x);    // gi
    mma_gemm<3><<<dim3(6, NROWS/128), 256, GEMM_SMEM>>>(x);    // gh

    gate_kernel<<<NROWS*64/256, 256>>>(x, b_ih, b_hh, out);
}

// round 6
// speedup vs baseline: 2.6445x; 1.1945x over previous
#include <cuda_runtime.h>
#include <cuda_bf16.h>
#include <math.h>
#include <stdint.h>

#define BS   16
#define NSEQ 2048
#define DIM  256
#define NROWS (BS*NSEQ)   // 32768

// ---------------- scratch (device globals) --------------------------------
__device__ float g_s[NROWS*4];
__device__ float g_gi[(size_t)NROWS*768];
__device__ float g_gh[(size_t)NROWS*768];

// bf16 hi/lo split activations
__device__ __nv_bfloat16 g_xh[NROWS*DIM],  g_xl[NROWS*DIM];
__device__ __nv_bfloat16 g_h1h[NROWS*DIM], g_h1l[NROWS*DIM];
__device__ __nv_bfloat16 g_xch[NROWS*DIM], g_xcl[NROWS*DIM];
__device__ __nv_bfloat16 g_xnh[NROWS*DIM], g_xnl[NROWS*DIM];
__device__ __nv_bfloat16 g_msgh[NROWS*DIM], g_msgl[NROWS*DIM];

// bf16 hi/lo split weights ([out][in], K-major)
__device__ __nv_bfloat16 g_wfh[512*256],  g_wfl[512*256];
__device__ __nv_bfloat16 g_w2h[256*4352], g_w2l[256*4352];
__device__ __nv_bfloat16 g_wihh[768*512], g_wihl[768*512];
__device__ __nv_bfloat16 g_whhh[768*256], g_whhl[768*256];

// bn constants
__device__ float g_sc1[DIM], g_sh1[DIM], g_sh2[DIM], g_bmsg[DIM];

// ---------------- helpers --------------------------------------------------
__device__ __forceinline__ uint32_t smem_u32(const void* p) {
    uint32_t a;
    asm("{ .reg .u64 t; cvta.to.shared.u64 t, %1; cvt.u32.u64 %0, t; }"
        : "=r"(a) : "l"(p));
    return a;
}
__device__ __forceinline__ uint32_t pksplit(float a, float b, uint32_t& lo) {
    __nv_bfloat16 ha = __float2bfloat16(a), hb = __float2bfloat16(b);
    float la = a - __bfloat162float(ha), lb = b - __bfloat162float(hb);
    __nv_bfloat16 hla = __float2bfloat16(la), hlb = __float2bfloat16(lb);
    lo = (uint32_t)__bfloat16_as_ushort(hla) | ((uint32_t)__bfloat16_as_ushort(hlb) << 16);
    return (uint32_t)__bfloat16_as_ushort(ha) | ((uint32_t)__bfloat16_as_ushort(hb) << 16);
}

#define LDMX4(r0,r1,r2,r3,addr) \
    asm volatile("ldmatrix.sync.aligned.m8n8.x4.shared.b16 {%0,%1,%2,%3}, [%4];" \
        : "=r"(r0),"=r"(r1),"=r"(r2),"=r"(r3) : "r"(addr))
#define LDMX4T(r0,r1,r2,r3,addr) \
    asm volatile("ldmatrix.sync.aligned.m8n8.x4.trans.shared.b16 {%0,%1,%2,%3}, [%4];" \
        : "=r"(r0),"=r"(r1),"=r"(r2),"=r"(r3) : "r"(addr))
#define MMA_BF16(d, a, b0, b1) \
    asm volatile("mma.sync.aligned.m16n8k16.row.col.f32.bf16.bf16.f32 " \
        "{%0,%1,%2,%3}, {%4,%5,%6,%7}, {%8,%9}, {%0,%1,%2,%3};" \
        : "+f"((d)[0]),"+f"((d)[1]),"+f"((d)[2]),"+f"((d)[3]) \
        : "r"((a)[0]),"r"((a)[1]),"r"((a)[2]),"r"((a)[3]), "r"(b0),"r"(b1))

#define CPA16(dst, src) \
    asm volatile("cp.async.cg.shared.global [%0], [%1], 16;" :: "r"(dst), "l"(src))
#define CPA16Z(dst, src, sz) \
    asm volatile("cp.async.cg.shared.global [%0], [%1], 16, %2;" :: "r"(dst), "l"(src), "r"(sz))
#define CPCOMMIT() asm volatile("cp.async.commit_group;" ::: "memory")
#define CPWAIT(n)  asm volatile("cp.async.wait_group %0;" :: "n"(n) : "memory")

// ---------------- repack ---------------------------------------------------
__global__ void repack_kernel(const float* __restrict__ x,
                              const float* __restrict__ conv1_w,
                              const float* __restrict__ w_msg,
                              const float* __restrict__ conv2_w,
                              const float* __restrict__ bn1_g, const float* __restrict__ bn1_b,
                              const float* __restrict__ bn1_m, const float* __restrict__ bn1_v,
                              const float* __restrict__ bn2_g, const float* __restrict__ bn2_b,
                              const float* __restrict__ bn2_m, const float* __restrict__ bn2_v,
                              const float* __restrict__ b_msg,
                              const float* __restrict__ w_ih,
                              const float* __restrict__ w_hh) {
    int stride = gridDim.x * blockDim.x;
    int idx = blockIdx.x * blockDim.x + threadIdx.x;
    if (idx < DIM) {
        float sc = bn1_g[idx] * rsqrtf(bn1_v[idx] + 1e-5f);
        g_sc1[idx] = sc;
        g_sh1[idx] = bn1_b[idx] - bn1_m[idx]*sc;
        float sc2 = bn2_g[idx] * rsqrtf(bn2_v[idx] + 1e-5f);
        g_sh2[idx] = bn2_b[idx] - bn2_m[idx]*sc2;
        g_bmsg[idx] = b_msg[idx];
    }
    for (int i = idx; i < 512*256; i += stride) {
        int n = i >> 8, k = i & 255;
        float v = (n < 256) ? conv1_w[n*256 + k] : w_msg[(n-256)*256 + k];
        __nv_bfloat16 h = __float2bfloat16(v);
        g_wfh[i] = h; g_wfl[i] = __float2bfloat16(v - __bfloat162float(h));
    }
    for (int i = idx; i < 256*4352; i += stride) {
        int o = i / 4352, kk = i - o*4352;
        int tap = kk >> 8, ic = kk & 255;
        float sc = bn2_g[o] * rsqrtf(bn2_v[o] + 1e-5f);
        float v = conv2_w[(o*256 + ic)*17 + tap] * sc;
        __nv_bfloat16 h = __float2bfloat16(v);
        g_w2h[i] = h; g_w2l[i] = __float2bfloat16(v - __bfloat162float(h));
    }
    for (int i = idx; i < 768*512; i += stride) {
        float v = w_ih[i];
        __nv_bfloat16 h = __float2bfloat16(v);
        g_wihh[i] = h; g_wihl[i] = __float2bfloat16(v - __bfloat162float(h));
    }
    for (int i = idx; i < 768*256; i += stride) {
        float v = w_hh[i];
        __nv_bfloat16 h = __float2bfloat16(v);
        g_whhh[i] = h; g_whhl[i] = __float2bfloat16(v - __bfloat162float(h));
    }
    for (int i = idx; i < NROWS*DIM; i += stride) {
        float v = x[i];
        __nv_bfloat16 h = __float2bfloat16(v);
        g_xh[i] = h; g_xl[i] = __float2bfloat16(v - __bfloat162float(h));
    }
}

// ================= HMMA GEMM: cp.async 2-stage pipeline, 2 CTAs/SM ========
#define PITCH 80
#define ARR   10240
#define STAGE 40960
#define SM_AHI(s) ((s)*STAGE + 0)
#define SM_ALO(s) ((s)*STAGE + ARR)
#define SM_BHI(s) ((s)*STAGE + 2*ARR)
#define SM_BLO(s) ((s)*STAGE + 3*ARR)
#define GEMM_SMEM (2*STAGE)

template<int MODE>
__global__ void __launch_bounds__(256, 2) mma_gemm(const float* __restrict__ x) {
    extern __shared__ char smem[];
    const int tid  = threadIdx.x;
    const int wid  = tid >> 5, lane = tid & 31;
    const int warp_m = wid & 1;
    const int warp_n = wid >> 1;
    const int gid  = lane >> 2, tid4 = lane & 3;
    const uint32_t sb = smem_u32(smem);

    constexpr int KT = (MODE==0) ? 256 : (MODE==1) ? 4352 : (MODE==2) ? 512 : 256;
    constexpr int NC = KT / 32;
    const int col0 = blockIdx.x * 128;
    const int bz = blockIdx.z;
    const int t0 = blockIdx.y * 128;
    const int row0 = (MODE==1) ? (bz*NSEQ + t0) : t0;

    const uint32_t aOff = (uint32_t)(lane & 15)*PITCH + (uint32_t)(lane >> 4)*16;
    const uint32_t bOff = (uint32_t)(((lane >> 4) << 3) + (lane & 7))*PITCH
                        + (uint32_t)((lane >> 3) & 1)*16;

    const int r0_ = tid >> 2, u_ = tid & 3;
    const uint32_t o0 = (uint32_t)(r0_*PITCH + u_*16);
    const uint32_t o1 = o0 + 64*PITCH;

    float acc[4][4][4] = {};

#define CPA_TILE(c, s) { \
    uint32_t dA = sb + SM_AHI(s), dAl = sb + SM_ALO(s); \
    uint32_t dB = sb + SM_BHI(s), dBl = sb + SM_BLO(s); \
    if (MODE == 0) { \
        size_t a0 = (size_t)(row0+r0_)*256 + (c)*32 + u_*8, a1 = a0 + 64*256; \
        CPA16(dA+o0,  g_xh+a0); CPA16(dA+o1,  g_xh+a1); \
        CPA16(dAl+o0, g_xl+a0); CPA16(dAl+o1, g_xl+a1); \
        size_t b0 = (size_t)(col0+r0_)*256 + (c)*32 + u_*8, b1 = b0 + 64*256; \
        CPA16(dB+o0,  g_wfh+b0); CPA16(dB+o1,  g_wfh+b1); \
        CPA16(dBl+o0, g_wfl+b0); CPA16(dBl+o1, g_wfl+b1); \
    } else if (MODE == 1) { \
        int tap = (c) >> 3, kloc = ((c) & 7)*32; \
        int t1 = t0 + r0_ + tap - 8, t2 = t1 + 64; \
        uint32_t z1 = ((unsigned)t1 < (unsigned)NSEQ) ? 16u : 0u; \
        uint32_t z2 = ((unsigned)t2 < (unsigned)NSEQ) ? 16u : 0u; \
        int tc1 = min(max(t1, 0), NSEQ-1), tc2 = min(max(t2, 0), NSEQ-1); \
        size_t a0 = ((size_t)bz*NSEQ + tc1)*256 + kloc + u_*8; \
        size_t a1 = ((size_t)bz*NSEQ + tc2)*256 + kloc + u_*8; \
        CPA16Z(dA+o0,  g_h1h+a0, z1); CPA16Z(dA+o1,  g_h1h+a1, z2); \
        CPA16Z(dAl+o0, g_h1l+a0, z1); CPA16Z(dAl+o1, g_h1l+a1, z2); \
        size_t b0 = (size_t)(col0+r0_)*4352 + (c)*32 + u_*8, b1 = b0 + 64*4352; \
        CPA16(dB+o0,  g_w2h+b0); CPA16(dB+o1,  g_w2h+b1); \
        CPA16(dBl+o0, g_w2l+b0); CPA16(dBl+o1, g_w2l+b1); \
    } else if (MODE == 2) { \
        const __nv_bfloat16* sh_ = ((c) < 8) ? g_xch : g_xnh; \
        const __nv_bfloat16* sl_ = ((c) < 8) ? g_xcl : g_xnl; \
        int kk_ = ((c) & 7)*32; \
        size_t a0 = (size_t)(row0+r0_)*256 + kk_ + u_*8, a1 = a0 + 64*256; \
        CPA16(dA+o0,  sh_+a0); CPA16(dA+o1,  sh_+a1); \
        CPA16(dAl+o0, sl_+a0); CPA16(dAl+o1, sl_+a1); \
        size_t b0 = (size_t)(col0+r0_)*512 + (c)*32 + u_*8, b1 = b0 + 64*512; \
        CPA16(dB+o0,  g_wihh+b0); CPA16(dB+o1,  g_wihh+b1); \
        CPA16(dBl+o0, g_wihl+b0); CPA16(dBl+o1, g_wihl+b1); \
    } else { \
        size_t a0 = (size_t)(row0+r0_)*256 + (c)*32 + u_*8, a1 = a0 + 64*256; \
        CPA16(dA+o0,  g_xh+a0); CPA16(dA+o1,  g_xh+a1); \
        CPA16(dAl+o0, g_xl+a0); CPA16(dAl+o1, g_xl+a1); \
        size_t b0 = (size_t)(col0+r0_)*256 + (c)*32 + u_*8, b1 = b0 + 64*256; \
        CPA16(dB+o0,  g_whhh+b0); CPA16(dB+o1,  g_whhh+b1); \
        CPA16(dBl+o0, g_whhl+b0); CPA16(dBl+o1, g_whhl+b1); \
    } }

#define COMPUTE(s) { \
    _Pragma("unroll") \
    for (int ks = 0; ks < 2; ks++) { \
        uint32_t Ah[4][4], Al[4][4], Bh[2][4], Bl[2][4]; \
        _Pragma("unroll") \
        for (int mi = 0; mi < 4; mi++) { \
            uint32_t ad = sb + SM_AHI(s) + (warp_m*64 + mi*16)*PITCH + ks*32 + aOff; \
            LDMX4(Ah[mi][0],Ah[mi][1],Ah[mi][2],Ah[mi][3], ad); \
            ad = sb + SM_ALO(s) + (warp_m*64 + mi*16)*PITCH + ks*32 + aOff; \
            LDMX4(Al[mi][0],Al[mi][1],Al[mi][2],Al[mi][3], ad); \
        } \
        _Pragma("unroll") \
        for (int pj = 0; pj < 2; pj++) { \
            uint32_t bd = sb + SM_BHI(s) + (warp_n*32 + pj*16)*PITCH + ks*32 + bOff; \
            LDMX4(Bh[pj][0],Bh[pj][1],Bh[pj][2],Bh[pj][3], bd); \
            bd = sb + SM_BLO(s) + (warp_n*32 + pj*16)*PITCH + ks*32 + bOff; \
            LDMX4(Bl[pj][0],Bl[pj][1],Bl[pj][2],Bl[pj][3], bd); \
        } \
        _Pragma("unroll") \
        for (int mi = 0; mi < 4; mi++) \
            _Pragma("unroll") \
            for (int pj = 0; pj < 2; pj++) \
                _Pragma("unroll") \
                for (int h = 0; h < 2; h++) { \
                    float* D = acc[mi][pj*2 + h]; \
                    MMA_BF16(D, Ah[mi], Bh[pj][h*2], Bh[pj][h*2+1]); \
                    MMA_BF16(D, Ah[mi], Bl[pj][h*2], Bl[pj][h*2+1]); \
                    MMA_BF16(D, Al[mi], Bh[pj][h*2], Bh[pj][h*2+1]); \
                } \
    } }

    CPA_TILE(0, 0); CPCOMMIT();
    for (int c = 0; c < NC; c++) {
        if (c + 1 < NC) {
            CPA_TILE(c+1, (c+1) & 1); CPCOMMIT();
            CPWAIT(1);
        } else {
            CPWAIT(0);
        }
        __syncthreads();
        COMPUTE(c & 1);
        __syncthreads();
    }
#undef CPA_TILE
#undef COMPUTE

    // ---------------- epilogue ----------------
    #pragma unroll
    for (int mi = 0; mi < 4; mi++) {
        #pragma unroll
        for (int nj = 0; nj < 4; nj++) {
            int c = col0 + warp_n*32 + nj*8 + tid4*2;
            size_t r1 = (size_t)row0 + warp_m*64 + mi*16 + gid;
            size_t r2 = r1 + 8;
            float v00 = acc[mi][nj][0], v01 = acc[mi][nj][1];
            float v10 = acc[mi][nj][2], v11 = acc[mi][nj][3];
            if (MODE == 0) {
                if (c < 256) {
                    float sc0 = g_sc1[c], sc1 = g_sc1[c+1];
                    float sh0 = g_sh1[c], sh1 = g_sh1[c+1];
                    uint32_t lo, hi;
                    hi = pksplit(fmaxf(v00*sc0+sh0,0.f), fmaxf(v01*sc1+sh1,0.f), lo);
                    *(uint32_t*)&g_h1h[r1*256 + c] = hi; *(uint32_t*)&g_h1l[r1*256 + c] = lo;
                    hi = pksplit(fmaxf(v10*sc0+sh0,0.f), fmaxf(v11*sc1+sh1,0.f), lo);
                    *(uint32_t*)&g_h1h[r2*256 + c] = hi; *(uint32_t*)&g_h1l[r2*256 + c] = lo;
                } else {
                    int cc = c - 256;
                    float b0 = g_bmsg[cc], b1 = g_bmsg[cc+1];
                    uint32_t lo, hi;
                    hi = pksplit(fmaxf(v00+b0,0.f), fmaxf(v01+b1,0.f), lo);
                    *(uint32_t*)&g_msgh[r1*256 + cc] = hi; *(uint32_t*)&g_msgl[r1*256 + cc] = lo;
                    hi = pksplit(fmaxf(v10+b0,0.f), fmaxf(v11+b1,0.f), lo);
                    *(uint32_t*)&g_msgh[r2*256 + cc] = hi; *(uint32_t*)&g_msgl[r2*256 + cc] = lo;
                }
            } else if (MODE == 1) {
                float sh0 = g_sh2[c], sh1 = g_sh2[c+1];
                uint32_t lo, hi;
                float a0 = fmaxf(v00 + sh0 + x[r1*256+c],   0.f);
                float a1 = fmaxf(v01 + sh1 + x[r1*256+c+1], 0.f);
                hi = pksplit(a0, a1, lo);
                *(uint32_t*)&g_xch[r1*256 + c] = hi; *(uint32_t*)&g_xcl[r1*256 + c] = lo;
                a0 = fmaxf(v10 + sh0 + x[r2*256+c],   0.f);
                a1 = fmaxf(v11 + sh1 + x[r2*256+c+1], 0.f);
                hi = pksplit(a0, a1, lo);
                *(uint32_t*)&g_xch[r2*256 + c] = hi; *(uint32_t*)&g_xcl[r2*256 + c] = lo;
            } else if (MODE == 2) {
                *(float2*)&g_gi[r1*768 + c] = make_float2(v00, v01);
                *(float2*)&g_gi[r2*768 + c] = make_float2(v10, v11);
            } else {
                *(float2*)&g_gh[r1*768 + c] = make_float2(v00, v01);
                *(float2*)&g_gh[r2*768 + c] = make_float2(v10, v11);
            }
        }
    }
}

// ---------------- s / sq ---------------------------------------------------
__global__ void skernel(const float* __restrict__ x,
                        const float* __restrict__ w_se,
                        const float* __restrict__ b_se) {
    int row = blockIdx.x * 8 + (threadIdx.x >> 5);
    int lane = threadIdx.x & 31;
    float p0=0.f, p1=0.f, p2=0.f;
    for (int k = lane; k < DIM; k += 32) {
        float xv = x[(size_t)row*DIM + k];
        p0 += xv * w_se[k];
        p1 += xv * w_se[DIM + k];
        p2 += xv * w_se[2*DIM + k];
    }
    #pragma unroll
    for (int off = 16; off > 0; off >>= 1) {
        p0 += __shfl_down_sync(0xffffffffu, p0, off);
        p1 += __shfl_down_sync(0xffffffffu, p1, off);
        p2 += __shfl_down_sync(0xffffffffu, p2, off);
    }
    if (lane == 0) {
        p0 += b_se[0]; p1 += b_se[1]; p2 += b_se[2];
        g_s[row*4+0] = p0; g_s[row*4+1] = p1; g_s[row*4+2] = p2;
        g_s[row*4+3] = p0*p0 + p1*p1 + p2*p2;
    }
}

// ---------------- tensorized NMP ------------------------------------------
#define NWP  80
#define NWH  0
#define NWL  5120
#define NMPITCH 528
#define NMH(s) (10240 + (s)*33792)
#define NML(s) (NMH(s) + 16896)
#define NSS  77824
#define NSM  78848
#define NMP_SMEM 79872

__global__ void __launch_bounds__(256, 2) nmp_kernel(const float* __restrict__ mask) {
    extern __shared__ char smem[];
    const uint32_t sb = smem_u32(smem);
    float* sSn = (float*)(smem + NSS);
    float* sSm = (float*)(smem + NSM);
    const int b  = blockIdx.y;
    const int n0 = blockIdx.x * 64;
    const int tid = threadIdx.x;
    const int wid = tid >> 5, lane = tid & 31;
    const int warp_n = wid & 1, warp_d = wid >> 1;
    const int gid = lane >> 2, tid4 = lane & 3;

    const uint32_t aOff  = (uint32_t)(lane & 15)*NWP + (uint32_t)(lane >> 4)*16;
    const uint32_t bOffT = (uint32_t)(lane & 15)*NMPITCH + (uint32_t)(lane >> 4)*16;

    const size_t mbase = ((size_t)b*NSEQ + n0) * NSEQ;
    sSn[tid] = g_s[((size_t)b*NSEQ + n0)*4 + tid];

    const int mrow = tid >> 5;
    const int mu   = tid & 31;

#define NMP_PREFETCH(c, s) { \
    uint32_t dh = sb + NMH(s), dl = sb + NML(s); \
    const __nv_bfloat16* srch = g_msgh + ((size_t)b*NSEQ + (c)*32)*256; \
    const __nv_bfloat16* srcl = g_msgl + ((size_t)b*NSEQ + (c)*32)*256; \
    _Pragma("unroll") \
    for (int q = 0; q < 4; q++) { \
        int row = mrow + q*8; \
        uint32_t o = (uint32_t)row*NMPITCH + (uint32_t)mu*16; \
        size_t gsrc = (size_t)row*256 + mu*8; \
        CPA16(dh + o, srch + gsrc); \
        CPA16(dl + o, srcl + gsrc); \
    } }

    NMP_PREFETCH(0, 0); CPCOMMIT();

    float acc[2][8][4] = {};
    const int rr = tid >> 2, mm0 = (tid & 3)*8;

    for (int c = 0; c < NSEQ/32; c++) {
        int s = c & 1;
        __syncthreads();
        if (tid < 128) sSm[tid] = g_s[((size_t)b*NSEQ + c*32)*4 + tid];
        if (c+1 < NSEQ/32) { NMP_PREFETCH(c+1, 1-s); }
        CPCOMMIT();
        __syncthreads();
        {
            float sn0 = sSn[rr*4+0], sn1 = sSn[rr*4+1], sn2 = sSn[rr*4+2], snq = sSn[rr*4+3];
            const float* mrow_p = &mask[mbase + (size_t)rr*NSEQ + c*32 + mm0];
            float4 mk0 = *(const float4*)mrow_p;
            float4 mk1 = *(const float4*)(mrow_p + 4);
            float v[8];
            #pragma unroll
            for (int q = 0; q < 8; q++) {
                int mm = mm0 + q;
                float dd = snq + sSm[mm*4+3]
                         - 2.0f*(sn0*sSm[mm*4+0] + sn1*sSm[mm*4+1] + sn2*sSm[mm*4+2]);
                float mk = (q < 4) ? (&mk0.x)[q] : (&mk1.x)[q-4];
                v[q] = __expf(-dd) * mk;
            }
            uint4 vh, vl;
            vh.x = pksplit(v[0], v[1], vl.x);
            vh.y = pksplit(v[2], v[3], vl.y);
            vh.z = pksplit(v[4], v[5], vl.z);
            vh.w = pksplit(v[6], v[7], vl.w);
            *(uint4*)(smem + NWH + rr*NWP + mm0*2) = vh;
            *(uint4*)(smem + NWL + rr*NWP + mm0*2) = vl;
        }
        CPWAIT(1);
        __syncthreads();
        #pragma unroll
        for (int ks = 0; ks < 2; ks++) {
            uint32_t Ah[2][4], Al[2][4], Bh[4][4], Bl[4][4];
            #pragma unroll
            for (int mi = 0; mi < 2; mi++) {
                uint32_t ad = sb + NWH + (warp_n*32 + mi*16)*NWP + ks*32 + aOff;
                LDMX4(Ah[mi][0],Ah[mi][1],Ah[mi][2],Ah[mi][3], ad);
                ad = sb + NWL + (warp_n*32 + mi*16)*NWP + ks*32 + aOff;
                LDMX4(Al[mi][0],Al[mi][1],Al[mi][2],Al[mi][3], ad);
            }
            #pragma unroll
            for (int dj = 0; dj < 4; dj++) {
                uint32_t bd = sb + NMH(s) + (ks*16)*NMPITCH + (warp_d*64 + dj*16)*2 + bOffT;
                LDMX4T(Bh[dj][0],Bh[dj][1],Bh[dj][2],Bh[dj][3], bd);
                bd = sb + NML(s) + (ks*16)*NMPITCH + (warp_d*64 + dj*16)*2 + bOffT;
                LDMX4T(Bl[dj][0],Bl[dj][1],Bl[dj][2],Bl[dj][3], bd);
            }
            #pragma unroll
            for (int mi = 0; mi < 2; mi++)
                #pragma unroll
                for (int dj = 0; dj < 4; dj++)
                    #pragma unroll
                    for (int h = 0; h < 2; h++) {
                        float* D = acc[mi][dj*2 + h];
                        MMA_BF16(D, Ah[mi], Bh[dj][h*2], Bh[dj][h*2+1]);
                        MMA_BF16(D, Ah[mi], Bl[dj][h*2], Bl[dj][h*2+1]);
                        MMA_BF16(D, Al[mi], Bh[dj][h*2], Bh[dj][h*2+1]);
                    }
        }
    }
#undef NMP_PREFETCH

    #pragma unroll
    for (int mi = 0; mi < 2; mi++) {
        #pragma unroll
        for (int dj8 = 0; dj8 < 8; dj8++) {
            int d = warp_d*64 + dj8*8 + tid4*2;
            size_t r1 = (size_t)b*NSEQ + n0 + warp_n*32 + mi*16 + gid;
            size_t r2 = r1 + 8;
            uint32_t lo, hi;
            hi = pksplit(acc[mi][dj8][0], acc[mi][dj8][1], lo);
            *(uint32_t*)&g_xnh[r1*256 + d] = hi; *(uint32_t*)&g_xnl[r1*256 + d] = lo;
            hi = pksplit(acc[mi][dj8][2], acc[mi][dj8][3], lo);
            *(uint32_t*)&g_xnh[r2*256 + d] = hi; *(uint32_t*)&g_xnl[r2*256 + d] = lo;
        }
    }
}

// ---------------- gate epilogue ------------------------------------------
__global__ void gate_kernel(const float* __restrict__ x,
                            const float* __restrict__ b_ih,
                            const float* __restrict__ b_hh,
                            float* __restrict__ out) {
    int idx = blockIdx.x * blockDim.x + threadIdx.x;
    size_t r = idx >> 6;
    int c = (idx & 63) * 4;
    const float* gi = &g_gi[r*768];
    const float* gh = &g_gh[r*768];
    float4 gir = *(const float4*)&gi[c];
    float4 giz = *(const float4*)&gi[256 + c];
    float4 gin = *(const float4*)&gi[512 + c];
    float4 ghr = *(const float4*)&gh[c];
    float4 ghz = *(const float4*)&gh[256 + c];
    float4 ghn = *(const float4*)&gh[512 + c];
    float4 xv  = *(const float4*)&x[r*DIM + c];
    float4 o;
    #pragma unroll
    for (int q = 0; q < 4; q++) {
        float air = (&gir.x)[q] + b_ih[c+q]       + (&ghr.x)[q] + b_hh[c+q];
        float aiz = (&giz.x)[q] + b_ih[256 + c+q] + (&ghz.x)[q] + b_hh[256 + c+q];
        float rv = 1.0f/(1.0f + __expf(-air));
        float zv = 1.0f/(1.0f + __expf(-aiz));
        float nv = tanhf((&gin.x)[q] + b_ih[512 + c+q]
                       + rv*((&ghn.x)[q] + b_hh[512 + c+q]));
        (&o.x)[q] = (1.0f - zv)*nv + zv*(&xv.x)[q];
    }
    *(float4*)&out[r*DIM + c] = o;
}

// ---------------- launch --------------------------------------------------
extern "C" void kernel_launch(void* const* d_in, const int* in_sizes, int n_in,
                              void* d_out, int out_size) {
    const float* x       = (const float*)d_in[0];
    const float* mask    = (const float*)d_in[1];
    const float* w_se    = (const float*)d_in[2];
    const float* b_se    = (const float*)d_in[3];
    const float* conv1_w = (const float*)d_in[4];
    const float* bn1_g   = (const float*)d_in[5];
    const float* bn1_b   = (const float*)d_in[6];
    const float* bn1_m   = (const float*)d_in[7];
    const float* bn1_v   = (const float*)d_in[8];
    const float* conv2_w = (const float*)d_in[9];
    const float* bn2_g   = (const float*)d_in[10];
    const float* bn2_b   = (const float*)d_in[11];
    const float* bn2_m   = (const float*)d_in[12];
    const float* bn2_v   = (const float*)d_in[13];
    const float* w_msg   = (const float*)d_in[14];
    const float* b_msg   = (const float*)d_in[15];
    const float* w_ih    = (const float*)d_in[16];
    const float* b_ih    = (const float*)d_in[17];
    const float* w_hh    = (const float*)d_in[18];
    const float* b_hh    = (const float*)d_in[19];
    float* out = (float*)d_out;

    cudaFuncSetAttribute(mma_gemm<0>, cudaFuncAttributeMaxDynamicSharedMemorySize, GEMM_SMEM);
    cudaFuncSetAttribute(mma_gemm<1>, cudaFuncAttributeMaxDynamicSharedMemorySize, GEMM_SMEM);
    cudaFuncSetAttribute(mma_gemm<2>, cudaFuncAttributeMaxDynamicSharedMemorySize, GEMM_SMEM);
    cudaFuncSetAttribute(mma_gemm<3>, cudaFuncAttributeMaxDynamicSharedMemorySize, GEMM_SMEM);
    cudaFuncSetAttribute(nmp_kernel,  cudaFuncAttributeMaxDynamicSharedMemorySize, NMP_SMEM);

    repack_kernel<<<1024, 256>>>(x, conv1_w, w_msg, conv2_w,
                                 bn1_g, bn1_b, bn1_m, bn1_v,
                                 bn2_g, bn2_b, bn2_m, bn2_v,
                                 b_msg, w_ih, w_hh);

    mma_gemm<0><<<dim3(4, NROWS/128), 256, GEMM_SMEM>>>(x);    // front: h1 + msg

    skernel<<<NROWS/8, 256>>>(x, w_se, b_se);

    mma_gemm<1><<<dim3(2, NSEQ/128, BS), 256, GEMM_SMEM>>>(x); // conv2 -> xconv

    nmp_kernel<<<dim3(NSEQ/64, BS), 256, NMP_SMEM>>>(mask);    // -> xnmp (tensor)

    mma_gemm<2><<<dim3(6, NROWS/128), 256, GEMM_SMEM>>>(x);    // gi
    mma_gemm<3><<<dim3(6, NROWS/128), 256, GEMM_SMEM>>>(x);    // gh

    gate_kernel<<<NROWS*64/256, 256>>>(x, b_ih, b_hh, out);
}

// round 8
// speedup vs baseline: 2.9983x; 1.1338x over previous
#include <cuda_runtime.h>
#include <cuda_fp16.h>
#include <math.h>
#include <stdint.h>

#define BS   16
#define NSEQ 2048
#define DIM  256
#define NROWS (BS*NSEQ)   // 32768

// ---------------- scratch (device globals) --------------------------------
__device__ float g_s2[NROWS*8];          // [u0,u1,u2,q'] [s0,s1,s2,q']
__device__ float g_gi[(size_t)NROWS*768];
__device__ float g_gh[(size_t)NROWS*768];

// fp16 hi/lo split activations
__device__ __half g_xh[NROWS*DIM],  g_xl[NROWS*DIM];
__device__ __half g_h1h[NROWS*DIM], g_h1l[NROWS*DIM];
__device__ __half g_xch[NROWS*DIM], g_xcl[NROWS*DIM];
__device__ __half g_xnh[NROWS*DIM], g_xnl[NROWS*DIM];
__device__ __half g_msg[NROWS*DIM];      // single fp16 (positive, nmp B operand)

// fp16 hi/lo split weights ([out][in], K-major)
__device__ __half g_wfh[512*256],  g_wfl[512*256];
__device__ __half g_w2h[256*4352], g_w2l[256*4352];
__device__ __half g_wihh[768*512], g_wihl[768*512];
__device__ __half g_whhh[768*256], g_whhl[768*256];

// bn constants
__device__ float g_sc1[DIM], g_sh1[DIM], g_sh2[DIM], g_bmsg[DIM];

// ---------------- helpers --------------------------------------------------
__device__ __forceinline__ uint32_t smem_u32(const void* p) {
    uint32_t a;
    asm("{ .reg .u64 t; cvta.to.shared.u64 t, %1; cvt.u32.u64 %0, t; }"
        : "=r"(a) : "l"(p));
    return a;
}
__device__ __forceinline__ uint32_t pkh(float a, float b) {
    __half2 h = __floats2half2_rn(a, b);
    return *(uint32_t*)&h;
}
__device__ __forceinline__ uint32_t pksplit_h(float a, float b, uint32_t& lo) {
    __half ha = __float2half_rn(a), hb = __float2half_rn(b);
    lo = pkh(a - __half2float(ha), b - __half2float(hb));
    __half2 h2; h2.x = ha; h2.y = hb;
    return *(uint32_t*)&h2;
}

#define LDMX4(r0,r1,r2,r3,addr) \
    asm volatile("ldmatrix.sync.aligned.m8n8.x4.shared.b16 {%0,%1,%2,%3}, [%4];" \
        : "=r"(r0),"=r"(r1),"=r"(r2),"=r"(r3) : "r"(addr))
#define LDMX4T(r0,r1,r2,r3,addr) \
    asm volatile("ldmatrix.sync.aligned.m8n8.x4.trans.shared.b16 {%0,%1,%2,%3}, [%4];" \
        : "=r"(r0),"=r"(r1),"=r"(r2),"=r"(r3) : "r"(addr))
#define MMA_F16(d, a, b0, b1) \
    asm volatile("mma.sync.aligned.m16n8k16.row.col.f32.f16.f16.f32 " \
        "{%0,%1,%2,%3}, {%4,%5,%6,%7}, {%8,%9}, {%0,%1,%2,%3};" \
        : "+f"((d)[0]),"+f"((d)[1]),"+f"((d)[2]),"+f"((d)[3]) \
        : "r"((a)[0]),"r"((a)[1]),"r"((a)[2]),"r"((a)[3]), "r"(b0),"r"(b1))

#define CPA16(dst, src) \
    asm volatile("cp.async.cg.shared.global [%0], [%1], 16;" :: "r"(dst), "l"(src))
#define CPA16Z(dst, src, sz) \
    asm volatile("cp.async.cg.shared.global [%0], [%1], 16, %2;" :: "r"(dst), "l"(src), "r"(sz))
#define CPCOMMIT() asm volatile("cp.async.commit_group;" ::: "memory")
#define CPWAIT(n)  asm volatile("cp.async.wait_group %0;" :: "n"(n) : "memory")

// ---------------- repack ---------------------------------------------------
__global__ void repack_kernel(const float* __restrict__ x,
                              const float* __restrict__ conv1_w,
                              const float* __restrict__ w_msg,
                              const float* __restrict__ conv2_w,
                              const float* __restrict__ bn1_g, const float* __restrict__ bn1_b,
                              const float* __restrict__ bn1_m, const float* __restrict__ bn1_v,
                              const float* __restrict__ bn2_g, const float* __restrict__ bn2_b,
                              const float* __restrict__ bn2_m, const float* __restrict__ bn2_v,
                              const float* __restrict__ b_msg,
                              const float* __restrict__ w_ih,
                              const float* __restrict__ w_hh) {
    int stride = gridDim.x * blockDim.x;
    int idx = blockIdx.x * blockDim.x + threadIdx.x;
    if (idx < DIM) {
        float sc = bn1_g[idx] * rsqrtf(bn1_v[idx] + 1e-5f);
        g_sc1[idx] = sc;
        g_sh1[idx] = bn1_b[idx] - bn1_m[idx]*sc;
        float sc2 = bn2_g[idx] * rsqrtf(bn2_v[idx] + 1e-5f);
        g_sh2[idx] = bn2_b[idx] - bn2_m[idx]*sc2;
        g_bmsg[idx] = b_msg[idx];
    }
    for (int i = idx; i < 512*256; i += stride) {
        int n = i >> 8, k = i & 255;
        float v = (n < 256) ? conv1_w[n*256 + k] : w_msg[(n-256)*256 + k];
        __half h = __float2half_rn(v);
        g_wfh[i] = h; g_wfl[i] = __float2half_rn(v - __half2float(h));
    }
    for (int i = idx; i < 256*4352; i += stride) {
        int o = i / 4352, kk = i - o*4352;
        int tap = kk >> 8, ic = kk & 255;
        float sc = bn2_g[o] * rsqrtf(bn2_v[o] + 1e-5f);
        float v = conv2_w[(o*256 + ic)*17 + tap] * sc;
        __half h = __float2half_rn(v);
        g_w2h[i] = h; g_w2l[i] = __float2half_rn(v - __half2float(h));
    }
    for (int i = idx; i < 768*512; i += stride) {
        float v = w_ih[i];
        __half h = __float2half_rn(v);
        g_wihh[i] = h; g_wihl[i] = __float2half_rn(v - __half2float(h));
    }
    for (int i = idx; i < 768*256; i += stride) {
        float v = w_hh[i];
        __half h = __float2half_rn(v);
        g_whhh[i] = h; g_whhl[i] = __float2half_rn(v - __half2float(h));
    }
    for (int i = idx; i < NROWS*DIM; i += stride) {
        float v = x[i];
        __half h = __float2half_rn(v);
        g_xh[i] = h; g_xl[i] = __float2half_rn(v - __half2float(h));
    }
}

// ======= HMMA GEMM: 256x128 CTA tile, 64x64 warp tile, split x split ======
#define PITCH 80
#define A_ARR 20480            // 256 rows * 80
#define B_ARR 10240            // 128 rows * 80
#define SM_AHI(s) ((s)*61440 + 0)
#define SM_ALO(s) ((s)*61440 + A_ARR)
#define SM_BHI(s) ((s)*61440 + 2*A_ARR)
#define SM_BLO(s) ((s)*61440 + 2*A_ARR + B_ARR)
#define GEMM_SMEM 122880

template<int MODE>
__global__ void __launch_bounds__(256, 1) mma_gemm(const float* __restrict__ x) {
    extern __shared__ char smem[];
    const int tid  = threadIdx.x;
    const int wid  = tid >> 5, lane = tid & 31;
    const int warp_m = wid & 3;        // 4 x 64 rows
    const int warp_n = wid >> 2;       // 2 x 64 cols
    const int gid  = lane >> 2, tid4 = lane & 3;
    const uint32_t sb = smem_u32(smem);

    constexpr int KT = (MODE==0) ? 256 : (MODE==1) ? 4352 : (MODE==2) ? 512 : 256;
    constexpr int NC = KT / 32;
    const int col0 = blockIdx.x * 128;
    const int bz = blockIdx.z;
    const int t0 = blockIdx.y * 256;
    const int row0 = (MODE==1) ? (bz*NSEQ + t0) : t0;

    const uint32_t aOff = (uint32_t)(lane & 15)*PITCH + (uint32_t)(lane >> 4)*16;
    const uint32_t bOff = (uint32_t)(((lane >> 4) << 3) + (lane & 7))*PITCH
                        + (uint32_t)((lane >> 3) & 1)*16;

    const int r0_ = tid >> 2, u_ = tid & 3;

    float acc[4][8][4] = {};

#define CPA_TILE(c, s) { \
    uint32_t dAh = sb + SM_AHI(s), dAl = sb + SM_ALO(s); \
    uint32_t dBh = sb + SM_BHI(s), dBl = sb + SM_BLO(s); \
    _Pragma("unroll") \
    for (int g = 0; g < 4; g++) { \
        int arow = r0_ + 64*g; \
        uint32_t o = (uint32_t)(arow*PITCH + u_*16); \
        if (MODE == 0 || MODE == 3) { \
            size_t a0 = (size_t)(row0+arow)*256 + (c)*32 + u_*8; \
            CPA16(dAh+o, g_xh+a0); CPA16(dAl+o, g_xl+a0); \
        } else if (MODE == 1) { \
            int tap = (c) >> 3, kloc = ((c) & 7)*32; \
            int t1 = t0 + arow + tap - 8; \
            uint32_t z1 = ((unsigned)t1 < (unsigned)NSEQ) ? 16u : 0u; \
            int tc1 = min(max(t1, 0), NSEQ-1); \
            size_t a0 = ((size_t)bz*NSEQ + tc1)*256 + kloc + u_*8; \
            CPA16Z(dAh+o, g_h1h+a0, z1); CPA16Z(dAl+o, g_h1l+a0, z1); \
        } else { \
            const __half* sh_ = ((c) < 8) ? g_xch : g_xnh; \
            const __half* sl_ = ((c) < 8) ? g_xcl : g_xnl; \
            int kk_ = ((c) & 7)*32; \
            size_t a0 = (size_t)(row0+arow)*256 + kk_ + u_*8; \
            CPA16(dAh+o, sh_+a0); CPA16(dAl+o, sl_+a0); \
        } \
    } \
    _Pragma("unroll") \
    for (int g = 0; g < 2; g++) { \
        int brow = r0_ + 64*g; \
        uint32_t o = (uint32_t)(brow*PITCH + u_*16); \
        if (MODE == 0) { \
            size_t b0 = (size_t)(col0+brow)*256 + (c)*32 + u_*8; \
            CPA16(dBh+o, g_wfh+b0); CPA16(dBl+o, g_wfl+b0); \
        } else if (MODE == 1) { \
            size_t b0 = (size_t)(col0+brow)*4352 + (c)*32 + u_*8; \
            CPA16(dBh+o, g_w2h+b0); CPA16(dBl+o, g_w2l+b0); \
        } else if (MODE == 2) { \
            size_t b0 = (size_t)(col0+brow)*512 + (c)*32 + u_*8; \
            CPA16(dBh+o, g_wihh+b0); CPA16(dBl+o, g_wihl+b0); \
        } else { \
            size_t b0 = (size_t)(col0+brow)*256 + (c)*32 + u_*8; \
            CPA16(dBh+o, g_whhh+b0); CPA16(dBl+o, g_whhl+b0); \
        } \
    } }

#define COMPUTE(s) { \
    _Pragma("unroll") \
    for (int ks = 0; ks < 2; ks++) { \
        uint32_t Ah[4][4], Al[4][4]; \
        _Pragma("unroll") \
        for (int mi = 0; mi < 4; mi++) { \
            uint32_t ad = sb + SM_AHI(s) + (warp_m*64 + mi*16)*PITCH + ks*32 + aOff; \
            LDMX4(Ah[mi][0],Ah[mi][1],Ah[mi][2],Ah[mi][3], ad); \
            ad = sb + SM_ALO(s) + (warp_m*64 + mi*16)*PITCH + ks*32 + aOff; \
            LDMX4(Al[mi][0],Al[mi][1],Al[mi][2],Al[mi][3], ad); \
        } \
        _Pragma("unroll") \
        for (int pj = 0; pj < 4; pj++) { \
            uint32_t Bh[4], Bl[4]; \
            uint32_t bd = sb + SM_BHI(s) + (warp_n*64 + pj*16)*PITCH + ks*32 + bOff; \
            LDMX4(Bh[0],Bh[1],Bh[2],Bh[3], bd); \
            bd = sb + SM_BLO(s) + (warp_n*64 + pj*16)*PITCH + ks*32 + bOff; \
            LDMX4(Bl[0],Bl[1],Bl[2],Bl[3], bd); \
            _Pragma("unroll") \
            for (int mi = 0; mi < 4; mi++) \
                _Pragma("unroll") \
                for (int h = 0; h < 2; h++) { \
                    float* D = acc[mi][pj*2 + h]; \
                    MMA_F16(D, Ah[mi], Bh[h*2], Bh[h*2+1]); \
                    MMA_F16(D, Ah[mi], Bl[h*2], Bl[h*2+1]); \
                    MMA_F16(D, Al[mi], Bh[h*2], Bh[h*2+1]); \
                } \
        } \
    } }

    CPA_TILE(0, 0); CPCOMMIT();
    for (int c = 0; c < NC; c++) {
        if (c + 1 < NC) {
            CPA_TILE(c+1, (c+1) & 1); CPCOMMIT();
            CPWAIT(1);
        } else {
            CPWAIT(0);
        }
        __syncthreads();
        COMPUTE(c & 1);
        __syncthreads();
    }
#undef CPA_TILE
#undef COMPUTE

    // ---------------- epilogue ----------------
    #pragma unroll
    for (int mi = 0; mi < 4; mi++) {
        #pragma unroll
        for (int nj = 0; nj < 8; nj++) {
            int c = col0 + warp_n*64 + nj*8 + tid4*2;
            size_t r1 = (size_t)row0 + warp_m*64 + mi*16 + gid;
            size_t r2 = r1 + 8;
            float v00 = acc[mi][nj][0], v01 = acc[mi][nj][1];
            float v10 = acc[mi][nj][2], v11 = acc[mi][nj][3];
            if (MODE == 0) {
                if (col0 < 256) {
                    float sc0 = g_sc1[c], sc1 = g_sc1[c+1];
                    float sh0 = g_sh1[c], sh1 = g_sh1[c+1];
                    uint32_t lo, hi;
                    hi = pksplit_h(fmaxf(v00*sc0+sh0,0.f), fmaxf(v01*sc1+sh1,0.f), lo);
                    *(uint32_t*)&g_h1h[r1*256 + c] = hi; *(uint32_t*)&g_h1l[r1*256 + c] = lo;
                    hi = pksplit_h(fmaxf(v10*sc0+sh0,0.f), fmaxf(v11*sc1+sh1,0.f), lo);
                    *(uint32_t*)&g_h1h[r2*256 + c] = hi; *(uint32_t*)&g_h1l[r2*256 + c] = lo;
                } else {
                    int cc = c - 256;
                    float b0 = g_bmsg[cc], b1 = g_bmsg[cc+1];
                    *(uint32_t*)&g_msg[r1*256 + cc] = pkh(fmaxf(v00+b0,0.f), fmaxf(v01+b1,0.f));
                    *(uint32_t*)&g_msg[r2*256 + cc] = pkh(fmaxf(v10+b0,0.f), fmaxf(v11+b1,0.f));
                }
            } else if (MODE == 1) {
                float sh0 = g_sh2[c], sh1 = g_sh2[c+1];
                uint32_t lo, hi;
                float a0 = fmaxf(v00 + sh0 + x[r1*256+c],   0.f);
                float a1 = fmaxf(v01 + sh1 + x[r1*256+c+1], 0.f);
                hi = pksplit_h(a0, a1, lo);
                *(uint32_t*)&g_xch[r1*256 + c] = hi; *(uint32_t*)&g_xcl[r1*256 + c] = lo;
                a0 = fmaxf(v10 + sh0 + x[r2*256+c],   0.f);
                a1 = fmaxf(v11 + sh1 + x[r2*256+c+1], 0.f);
                hi = pksplit_h(a0, a1, lo);
                *(uint32_t*)&g_xch[r2*256 + c] = hi; *(uint32_t*)&g_xcl[r2*256 + c] = lo;
            } else if (MODE == 2) {
                *(float2*)&g_gi[r1*768 + c] = make_float2(v00, v01);
                *(float2*)&g_gi[r2*768 + c] = make_float2(v10, v11);
            } else {
                *(float2*)&g_gh[r1*768 + c] = make_float2(v00, v01);
                *(float2*)&g_gh[r2*768 + c] = make_float2(v10, v11);
            }
        }
    }
}

// ---------------- s projection -> (u, q') and (s, q') ---------------------
__global__ void skernel(const float* __restrict__ x,
                        const float* __restrict__ w_se,
                        const float* __restrict__ b_se) {
    int row = blockIdx.x * 8 + (threadIdx.x >> 5);
    int lane = threadIdx.x & 31;
    float p0=0.f, p1=0.f, p2=0.f;
    for (int k = lane; k < DIM; k += 32) {
        float xv = x[(size_t)row*DIM + k];
        p0 += xv * w_se[k];
        p1 += xv * w_se[DIM + k];
        p2 += xv * w_se[2*DIM + k];
    }
    #pragma unroll
    for (int off = 16; off > 0; off >>= 1) {
        p0 += __shfl_down_sync(0xffffffffu, p0, off);
        p1 += __shfl_down_sync(0xffffffffu, p1, off);
        p2 += __shfl_down_sync(0xffffffffu, p2, off);
    }
    if (lane == 0) {
        const float L2E = 1.4426950408889634f;
        p0 += b_se[0]; p1 += b_se[1]; p2 += b_se[2];
        float sq = p0*p0 + p1*p1 + p2*p2;
        float qp = -L2E * sq;
        g_s2[row*8+0] = 2.0f*L2E*p0;
        g_s2[row*8+1] = 2.0f*L2E*p1;
        g_s2[row*8+2] = 2.0f*L2E*p2;
        g_s2[row*8+3] = qp;
        g_s2[row*8+4] = p0;
        g_s2[row*8+5] = p1;
        g_s2[row*8+6] = p2;
        g_s2[row*8+7] = qp;
    }
}

// ---------------- tensorized NMP: W fp16 single x msg fp16 single ---------
#define NWP  80
#define NWH  0                         // W: 64*80 = 5120
#define NMPITCH 528
#define NMH(s) (5120 + (s)*16896)      // msg stages: 5120, 22016
#define NSMH 38912                     // 4*32 halfs = 256B
#define NMP_SMEM 39168

__global__ void __launch_bounds__(256, 2) nmp_kernel(const float* __restrict__ mask) {
    extern __shared__ char smem[];
    const uint32_t sb = smem_u32(smem);
    __half* sSmH = (__half*)(smem + NSMH);
    const int b  = blockIdx.y;
    const int n0 = blockIdx.x * 64;
    const int tid = threadIdx.x;
    const int wid = tid >> 5, lane = tid & 31;
    const int warp_n = wid & 1, warp_d = wid >> 1;
    const int gid = lane >> 2, tid4 = lane & 3;

    const uint32_t aOff  = (uint32_t)(lane & 15)*NWP + (uint32_t)(lane >> 4)*16;
    const uint32_t bOffT = (uint32_t)(lane & 15)*NMPITCH + (uint32_t)(lane >> 4)*16;

    const size_t mbase = ((size_t)b*NSEQ + n0) * NSEQ;
    const int rr = tid >> 2, mm0 = (tid & 3)*8;

    // per-thread row-i constants (half2 broadcasts)
    __half2 u0i, u1i, u2i, qi2;
    {
        const float* sp = &g_s2[((size_t)b*NSEQ + n0 + rr)*8];
        u0i = __float2half2_rn(sp[0]);
        u1i = __float2half2_rn(sp[1]);
        u2i = __float2half2_rn(sp[2]);
        qi2 = __float2half2_rn(sp[3]);
    }

    const int mrow = tid >> 5;
    const int mu   = tid & 31;

#define NMP_PREFETCH(c, s) { \
    uint32_t dh = sb + NMH(s); \
    const __half* srch = g_msg + ((size_t)b*NSEQ + (c)*32)*256; \
    _Pragma("unroll") \
    for (int q = 0; q < 4; q++) { \
        int row = mrow + q*8; \
        CPA16(dh + (uint32_t)row*NMPITCH + (uint32_t)mu*16, srch + (size_t)row*256 + mu*8); \
    } }

    NMP_PREFETCH(0, 0); CPCOMMIT();

    float acc[2][8][4] = {};

    for (int c = 0; c < NSEQ/32; c++) {
        int s = c & 1;
        __syncthreads();   // protect sW/sSmH from previous MMA/compute reads
        if (tid < 128) {
            int j = tid >> 2, comp = tid & 3;
            sSmH[comp*32 + j] =
                __float2half_rn(g_s2[((size_t)b*NSEQ + c*32 + j)*8 + 4 + comp]);
        }
        if (c+1 < NSEQ/32) { NMP_PREFETCH(c+1, 1-s); }
        CPCOMMIT();
        __syncthreads();   // sSmH ready
        {
            const float* mrow_p = &mask[mbase + (size_t)rr*NSEQ + c*32 + mm0];
            float4 mk0 = *(const float4*)mrow_p;
            float4 mk1 = *(const float4*)(mrow_p + 4);
            uint32_t wv[4];
            #pragma unroll
            for (int p = 0; p < 4; p++) {
                int mm = mm0 + 2*p;
                __half2 s0p = *(__half2*)&sSmH[      mm];
                __half2 s1p = *(__half2*)&sSmH[32  + mm];
                __half2 s2p = *(__half2*)&sSmH[64  + mm];
                __half2 qjp = *(__half2*)&sSmH[96  + mm];
                __half2 t2 = __hfma2(u0i, s0p, qjp);
                t2 = __hfma2(u1i, s1p, t2);
                t2 = __hfma2(u2i, s2p, t2);
                t2 = __hadd2(t2, qi2);
                uint32_t e2;
                asm("ex2.approx.f16x2 %0, %1;" : "=r"(e2) : "r"(*(uint32_t*)&t2));
                float mka = (p < 2) ? ((p == 0) ? mk0.x : mk0.z) : ((p == 2) ? mk1.x : mk1.z);
                float mkb = (p < 2) ? ((p == 0) ? mk0.y : mk0.w) : ((p == 2) ? mk1.y : mk1.w);
                __half2 mh = __floats2half2_rn(mka, mkb);
                __half2 w2 = __hmul2(*(__half2*)&e2, mh);
                wv[p] = *(uint32_t*)&w2;
            }
            *(uint4*)(smem + NWH + rr*NWP + mm0*2) = make_uint4(wv[0],wv[1],wv[2],wv[3]);
        }
        CPWAIT(1);
        __syncthreads();   // msg chunk c + W ready
        #pragma unroll
        for (int ks = 0; ks < 2; ks++) {
            uint32_t Aw[2][4], Bm[4][4];
            #pragma unroll
            for (int mi = 0; mi < 2; mi++) {
                uint32_t ad = sb + NWH + (warp_n*32 + mi*16)*NWP + ks*32 + aOff;
                LDMX4(Aw[mi][0],Aw[mi][1],Aw[mi][2],Aw[mi][3], ad);
            }
            #pragma unroll
            for (int dj = 0; dj < 4; dj++) {
                uint32_t bd = sb + NMH(s) + (ks*16)*NMPITCH + (warp_d*64 + dj*16)*2 + bOffT;
                LDMX4T(Bm[dj][0],Bm[dj][1],Bm[dj][2],Bm[dj][3], bd);
            }
            #pragma unroll
            for (int mi = 0; mi < 2; mi++)
                #pragma unroll
                for (int dj = 0; dj < 4; dj++)
                    #pragma unroll
                    for (int h = 0; h < 2; h++)
                        MMA_F16(acc[mi][dj*2 + h], Aw[mi], Bm[dj][h*2], Bm[dj][h*2+1]);
        }
    }
#undef NMP_PREFETCH

    #pragma unroll
    for (int mi = 0; mi < 2; mi++) {
        #pragma unroll
        for (int dj8 = 0; dj8 < 8; dj8++) {
            int d = warp_d*64 + dj8*8 + tid4*2;
            size_t r1 = (size_t)b*NSEQ + n0 + warp_n*32 + mi*16 + gid;
            size_t r2 = r1 + 8;
            uint32_t lo, hi;
            hi = pksplit_h(acc[mi][dj8][0], acc[mi][dj8][1], lo);
            *(uint32_t*)&g_xnh[r1*256 + d] = hi; *(uint32_t*)&g_xnl[r1*256 + d] = lo;
            hi = pksplit_h(acc[mi][dj8][2], acc[mi][dj8][3], lo);
            *(uint32_t*)&g_xnh[r2*256 + d] = hi; *(uint32_t*)&g_xnl[r2*256 + d] = lo;
        }
    }
}

// ---------------- gate epilogue ------------------------------------------
__global__ void gate_kernel(const float* __restrict__ x,
                            const float* __restrict__ b_ih,
                            const float* __restrict__ b_hh,
                            float* __restrict__ out) {
    int idx = blockIdx.x * blockDim.x + threadIdx.x;
    size_t r = idx >> 6;
    int c = (idx & 63) * 4;
    const float* gi = &g_gi[r*768];
    const float* gh = &g_gh[r*768];
    float4 gir = *(const float4*)&gi[c];
    float4 giz = *(const float4*)&gi[256 + c];
    float4 gin = *(const float4*)&gi[512 + c];
    float4 ghr = *(const float4*)&gh[c];
    float4 ghz = *(const float4*)&gh[256 + c];
    float4 ghn = *(const float4*)&gh[512 + c];
    float4 xv  = *(const float4*)&x[r*DIM + c];
    float4 o;
    #pragma unroll
    for (int q = 0; q < 4; q++) {
        float air = (&gir.x)[q] + b_ih[c+q]       + (&ghr.x)[q] + b_hh[c+q];
        float aiz = (&giz.x)[q] + b_ih[256 + c+q] + (&ghz.x)[q] + b_hh[256 + c+q];
        float rv = 1.0f/(1.0f + __expf(-air));
        float zv = 1.0f/(1.0f + __expf(-aiz));
        float nv = tanhf((&gin.x)[q] + b_ih[512 + c+q]
                       + rv*((&ghn.x)[q] + b_hh[512 + c+q]));
        (&o.x)[q] = (1.0f - zv)*nv + zv*(&xv.x)[q];
    }
    *(float4*)&out[r*DIM + c] = o;
}

// ---------------- launch --------------------------------------------------
extern "C" void kernel_launch(void* const* d_in, const int* in_sizes, int n_in,
                              void* d_out, int out_size) {
    const float* x       = (const float*)d_in[0];
    const float* mask    = (const float*)d_in[1];
    const float* w_se    = (const float*)d_in[2];
    const float* b_se    = (const float*)d_in[3];
    const float* conv1_w = (const float*)d_in[4];
    const float* bn1_g   = (const float*)d_in[5];
    const float* bn1_b   = (const float*)d_in[6];
    const float* bn1_m   = (const float*)d_in[7];
    const float* bn1_v   = (const float*)d_in[8];
    const float* conv2_w = (const float*)d_in[9];
    const float* bn2_g   = (const float*)d_in[10];
    const float* bn2_b   = (const float*)d_in[11];
    const float* bn2_m   = (const float*)d_in[12];
    const float* bn2_v   = (const float*)d_in[13];
    const float* w_msg   = (const float*)d_in[14];
    const float* b_msg   = (const float*)d_in[15];
    const float* w_ih    = (const float*)d_in[16];
    const float* b_ih    = (const float*)d_in[17];
    const float* w_hh    = (const float*)d_in[18];
    const float* b_hh    = (const float*)d_in[19];
    float* out = (float*)d_out;

    cudaFuncSetAttribute(mma_gemm<0>, cudaFuncAttributeMaxDynamicSharedMemorySize, GEMM_SMEM);
    cudaFuncSetAttribute(mma_gemm<1>, cudaFuncAttributeMaxDynamicSharedMemorySize, GEMM_SMEM);
    cudaFuncSetAttribute(mma_gemm<2>, cudaFuncAttributeMaxDynamicSharedMemorySize, GEMM_SMEM);
    cudaFuncSetAttribute(mma_gemm<3>, cudaFuncAttributeMaxDynamicSharedMemorySize, GEMM_SMEM);
    cudaFuncSetAttribute(nmp_kernel,  cudaFuncAttributeMaxDynamicSharedMemorySize, NMP_SMEM);

    repack_kernel<<<1024, 256>>>(x, conv1_w, w_msg, conv2_w,
                                 bn1_g, bn1_b, bn1_m, bn1_v,
                                 bn2_g, bn2_b, bn2_m, bn2_v,
                                 b_msg, w_ih, w_hh);

    mma_gemm<0><<<dim3(4, NROWS/256), 256, GEMM_SMEM>>>(x);      // front: h1 + msg

    skernel<<<NROWS/8, 256>>>(x, w_se, b_se);

    mma_gemm<1><<<dim3(2, NSEQ/256, BS), 256, GEMM_SMEM>>>(x);   // conv2 -> xc

    nmp_kernel<<<dim3(NSEQ/64, BS), 256, NMP_SMEM>>>(mask);      // -> xn

    mma_gemm<2><<<dim3(6, NROWS/256), 256, GEMM_SMEM>>>(x);      // gi
    mma_gemm<3><<<dim3(6, NROWS/256), 256, GEMM_SMEM>>>(x);      // gh

    gate_kernel<<<NROWS*64/256, 256>>>(x, b_ih, b_hh, out);
}

// round 9
// speedup vs baseline: 3.0839x; 1.0286x over previous
#include <cuda_runtime.h>
#include <cuda_fp16.h>
#include <math.h>
#include <stdint.h>

#define BS   16
#define NSEQ 2048
#define DIM  256
#define NROWS (BS*NSEQ)   // 32768

// ---------------- scratch (device globals) --------------------------------
__device__ float g_s2[NROWS*8];          // [u0,u1,u2,q'] [s0,s1,s2,q']
__device__ __half g_gi[(size_t)NROWS*768];
__device__ __half g_gh[(size_t)NROWS*768];

// fp16 hi/lo split activations
__device__ __half g_xh[NROWS*DIM],  g_xl[NROWS*DIM];
__device__ __half g_h1h[NROWS*DIM], g_h1l[NROWS*DIM];
__device__ __half g_xch[NROWS*DIM], g_xcl[NROWS*DIM];
__device__ __half g_xnh[NROWS*DIM], g_xnl[NROWS*DIM];
__device__ __half g_msg[NROWS*DIM];      // single fp16 (positive, nmp B operand)

// fp16 hi/lo split weights ([out][in], K-major)
__device__ __half g_wfh[512*256],  g_wfl[512*256];
__device__ __half g_w2h[256*4352], g_w2l[256*4352];
__device__ __half g_wihh[768*512], g_wihl[768*512];
__device__ __half g_whhh[768*256], g_whhl[768*256];

// bn constants
__device__ float g_sc1[DIM], g_sh1[DIM], g_sh2[DIM], g_bmsg[DIM];

// ---------------- helpers --------------------------------------------------
__device__ __forceinline__ uint32_t smem_u32(const void* p) {
    uint32_t a;
    asm("{ .reg .u64 t; cvta.to.shared.u64 t, %1; cvt.u32.u64 %0, t; }"
        : "=r"(a) : "l"(p));
    return a;
}
__device__ __forceinline__ uint32_t pkh(float a, float b) {
    __half2 h = __floats2half2_rn(a, b);
    return *(uint32_t*)&h;
}
__device__ __forceinline__ uint32_t pksplit_h(float a, float b, uint32_t& lo) {
    __half ha = __float2half_rn(a), hb = __float2half_rn(b);
    lo = pkh(a - __half2float(ha), b - __half2float(hb));
    __half2 h2; h2.x = ha; h2.y = hb;
    return *(uint32_t*)&h2;
}

#define LDMX4(r0,r1,r2,r3,addr) \
    asm volatile("ldmatrix.sync.aligned.m8n8.x4.shared.b16 {%0,%1,%2,%3}, [%4];" \
        : "=r"(r0),"=r"(r1),"=r"(r2),"=r"(r3) : "r"(addr))
#define LDMX4T(r0,r1,r2,r3,addr) \
    asm volatile("ldmatrix.sync.aligned.m8n8.x4.trans.shared.b16 {%0,%1,%2,%3}, [%4];" \
        : "=r"(r0),"=r"(r1),"=r"(r2),"=r"(r3) : "r"(addr))
#define MMA_F16(d, a, b0, b1) \
    asm volatile("mma.sync.aligned.m16n8k16.row.col.f32.f16.f16.f32 " \
        "{%0,%1,%2,%3}, {%4,%5,%6,%7}, {%8,%9}, {%0,%1,%2,%3};" \
        : "+f"((d)[0]),"+f"((d)[1]),"+f"((d)[2]),"+f"((d)[3]) \
        : "r"((a)[0]),"r"((a)[1]),"r"((a)[2]),"r"((a)[3]), "r"(b0),"r"(b1))

#define CPA16(dst, src) \
    asm volatile("cp.async.cg.shared.global [%0], [%1], 16;" :: "r"(dst), "l"(src))
#define CPA16Z(dst, src, sz) \
    asm volatile("cp.async.cg.shared.global [%0], [%1], 16, %2;" :: "r"(dst), "l"(src), "r"(sz))
#define CPCOMMIT() asm volatile("cp.async.commit_group;" ::: "memory")
#define CPWAIT(n)  asm volatile("cp.async.wait_group %0;" :: "n"(n) : "memory")

// ---------------- repack ---------------------------------------------------
__global__ void repack_kernel(const float* __restrict__ x,
                              const float* __restrict__ conv1_w,
                              const float* __restrict__ w_msg,
                              const float* __restrict__ conv2_w,
                              const float* __restrict__ bn1_g, const float* __restrict__ bn1_b,
                              const float* __restrict__ bn1_m, const float* __restrict__ bn1_v,
                              const float* __restrict__ bn2_g, const float* __restrict__ bn2_b,
                              const float* __restrict__ bn2_m, const float* __restrict__ bn2_v,
                              const float* __restrict__ b_msg,
                              const float* __restrict__ w_ih,
                              const float* __restrict__ w_hh) {
    int stride = gridDim.x * blockDim.x;
    int idx = blockIdx.x * blockDim.x + threadIdx.x;
    if (idx < DIM) {
        float sc = bn1_g[idx] * rsqrtf(bn1_v[idx] + 1e-5f);
        g_sc1[idx] = sc;
        g_sh1[idx] = bn1_b[idx] - bn1_m[idx]*sc;
        float sc2 = bn2_g[idx] * rsqrtf(bn2_v[idx] + 1e-5f);
        g_sh2[idx] = bn2_b[idx] - bn2_m[idx]*sc2;
        g_bmsg[idx] = b_msg[idx];
    }
    for (int i = idx; i < 512*256; i += stride) {
        int n = i >> 8, k = i & 255;
        float v = (n < 256) ? conv1_w[n*256 + k] : w_msg[(n-256)*256 + k];
        __half h = __float2half_rn(v);
        g_wfh[i] = h; g_wfl[i] = __float2half_rn(v - __half2float(h));
    }
    for (int i = idx; i < 256*4352; i += stride) {
        int o = i / 4352, kk = i - o*4352;
        int tap = kk >> 8, ic = kk & 255;
        float sc = bn2_g[o] * rsqrtf(bn2_v[o] + 1e-5f);
        float v = conv2_w[(o*256 + ic)*17 + tap] * sc;
        __half h = __float2half_rn(v);
        g_w2h[i] = h; g_w2l[i] = __float2half_rn(v - __half2float(h));
    }
    for (int i = idx; i < 768*512; i += stride) {
        float v = w_ih[i];
        __half h = __float2half_rn(v);
        g_wihh[i] = h; g_wihl[i] = __float2half_rn(v - __half2float(h));
    }
    for (int i = idx; i < 768*256; i += stride) {
        float v = w_hh[i];
        __half h = __float2half_rn(v);
        g_whhh[i] = h; g_whhl[i] = __float2half_rn(v - __half2float(h));
    }
    for (int i = idx; i < NROWS*DIM; i += stride) {
        float v = x[i];
        __half h = __float2half_rn(v);
        g_xh[i] = h; g_xl[i] = __float2half_rn(v - __half2float(h));
    }
}

// == HMMA GEMM: 256x128 CTA tile, 64x64 warp tile, 3-stage, 1 barrier/chunk =
#define PITCH 80
#define A_ARR 20480            // 256 rows * 80
#define B_ARR 10240            // 128 rows * 80
#define SM_AHI(s) ((s)*61440 + 0)
#define SM_ALO(s) ((s)*61440 + A_ARR)
#define SM_BHI(s) ((s)*61440 + 2*A_ARR)
#define SM_BLO(s) ((s)*61440 + 2*A_ARR + B_ARR)
#define GEMM_SMEM 184320

template<int MODE>
__global__ void __launch_bounds__(256, 1) mma_gemm(const float* __restrict__ x) {
    extern __shared__ char smem[];
    const int tid  = threadIdx.x;
    const int wid  = tid >> 5, lane = tid & 31;
    const int warp_m = wid & 3;        // 4 x 64 rows
    const int warp_n = wid >> 2;       // 2 x 64 cols
    const int gid  = lane >> 2, tid4 = lane & 3;
    const uint32_t sb = smem_u32(smem);

    constexpr int KT = (MODE==0) ? 256 : (MODE==1) ? 4352 : (MODE==2) ? 512 : 256;
    constexpr int NC = KT / 32;
    const int col0 = blockIdx.x * 128;
    const int bz = blockIdx.z;
    const int t0 = blockIdx.y * 256;
    const int row0 = (MODE==1) ? (bz*NSEQ + t0) : t0;

    const uint32_t aOff = (uint32_t)(lane & 15)*PITCH + (uint32_t)(lane >> 4)*16;
    const uint32_t bOff = (uint32_t)(((lane >> 4) << 3) + (lane & 7))*PITCH
                        + (uint32_t)((lane >> 3) & 1)*16;

    const int r0_ = tid >> 2, u_ = tid & 3;

    float acc[4][8][4] = {};

#define CPA_TILE(c, s) { \
    uint32_t dAh = sb + SM_AHI(s), dAl = sb + SM_ALO(s); \
    uint32_t dBh = sb + SM_BHI(s), dBl = sb + SM_BLO(s); \
    _Pragma("unroll") \
    for (int g = 0; g < 4; g++) { \
        int arow = r0_ + 64*g; \
        uint32_t o = (uint32_t)(arow*PITCH + u_*16); \
        if (MODE == 0 || MODE == 3) { \
            size_t a0 = (size_t)(row0+arow)*256 + (c)*32 + u_*8; \
            CPA16(dAh+o, g_xh+a0); CPA16(dAl+o, g_xl+a0); \
        } else if (MODE == 1) { \
            int tap = (c) >> 3, kloc = ((c) & 7)*32; \
            int t1 = t0 + arow + tap - 8; \
            uint32_t z1 = ((unsigned)t1 < (unsigned)NSEQ) ? 16u : 0u; \
            int tc1 = min(max(t1, 0), NSEQ-1); \
            size_t a0 = ((size_t)bz*NSEQ + tc1)*256 + kloc + u_*8; \
            CPA16Z(dAh+o, g_h1h+a0, z1); CPA16Z(dAl+o, g_h1l+a0, z1); \
        } else { \
            const __half* sh_ = ((c) < 8) ? g_xch : g_xnh; \
            const __half* sl_ = ((c) < 8) ? g_xcl : g_xnl; \
            int kk_ = ((c) & 7)*32; \
            size_t a0 = (size_t)(row0+arow)*256 + kk_ + u_*8; \
            CPA16(dAh+o, sh_+a0); CPA16(dAl+o, sl_+a0); \
        } \
    } \
    _Pragma("unroll") \
    for (int g = 0; g < 2; g++) { \
        int brow = r0_ + 64*g; \
        uint32_t o = (uint32_t)(brow*PITCH + u_*16); \
        if (MODE == 0) { \
            size_t b0 = (size_t)(col0+brow)*256 + (c)*32 + u_*8; \
            CPA16(dBh+o, g_wfh+b0); CPA16(dBl+o, g_wfl+b0); \
        } else if (MODE == 1) { \
            size_t b0 = (size_t)(col0+brow)*4352 + (c)*32 + u_*8; \
            CPA16(dBh+o, g_w2h+b0); CPA16(dBl+o, g_w2l+b0); \
        } else if (MODE == 2) { \
            size_t b0 = (size_t)(col0+brow)*512 + (c)*32 + u_*8; \
            CPA16(dBh+o, g_wihh+b0); CPA16(dBl+o, g_wihl+b0); \
        } else { \
            size_t b0 = (size_t)(col0+brow)*256 + (c)*32 + u_*8; \
            CPA16(dBh+o, g_whhh+b0); CPA16(dBl+o, g_whhl+b0); \
        } \
    } }

#define COMPUTE(s) { \
    _Pragma("unroll") \
    for (int ks = 0; ks < 2; ks++) { \
        uint32_t Ah[4][4], Al[4][4]; \
        _Pragma("unroll") \
        for (int mi = 0; mi < 4; mi++) { \
            uint32_t ad = sb + SM_AHI(s) + (warp_m*64 + mi*16)*PITCH + ks*32 + aOff; \
            LDMX4(Ah[mi][0],Ah[mi][1],Ah[mi][2],Ah[mi][3], ad); \
            ad = sb + SM_ALO(s) + (warp_m*64 + mi*16)*PITCH + ks*32 + aOff; \
            LDMX4(Al[mi][0],Al[mi][1],Al[mi][2],Al[mi][3], ad); \
        } \
        _Pragma("unroll") \
        for (int pj = 0; pj < 4; pj++) { \
            uint32_t Bh[4], Bl[4]; \
            uint32_t bd = sb + SM_BHI(s) + (warp_n*64 + pj*16)*PITCH + ks*32 + bOff; \
            LDMX4(Bh[0],Bh[1],Bh[2],Bh[3], bd); \
            bd = sb + SM_BLO(s) + (warp_n*64 + pj*16)*PITCH + ks*32 + bOff; \
            LDMX4(Bl[0],Bl[1],Bl[2],Bl[3], bd); \
            _Pragma("unroll") \
            for (int mi = 0; mi < 4; mi++) \
                _Pragma("unroll") \
                for (int h = 0; h < 2; h++) { \
                    float* D = acc[mi][pj*2 + h]; \
                    MMA_F16(D, Ah[mi], Bh[h*2], Bh[h*2+1]); \
                    MMA_F16(D, Ah[mi], Bl[h*2], Bl[h*2+1]); \
                    MMA_F16(D, Al[mi], Bh[h*2], Bh[h*2+1]); \
                } \
        } \
    } }

    CPA_TILE(0, 0); CPCOMMIT();
    CPA_TILE(1, 1); CPCOMMIT();
    for (int c = 0; c < NC; c++) {
        if (c + 1 < NC) { CPWAIT(1); } else { CPWAIT(0); }
        __syncthreads();
        if (c + 2 < NC) { CPA_TILE(c+2, (c+2)%3); CPCOMMIT(); }
        COMPUTE(c%3);
    }
#undef CPA_TILE
#undef COMPUTE

    // ---------------- epilogue ----------------
    #pragma unroll
    for (int mi = 0; mi < 4; mi++) {
        #pragma unroll
        for (int nj = 0; nj < 8; nj++) {
            int c = col0 + warp_n*64 + nj*8 + tid4*2;
            size_t r1 = (size_t)row0 + warp_m*64 + mi*16 + gid;
            size_t r2 = r1 + 8;
            float v00 = acc[mi][nj][0], v01 = acc[mi][nj][1];
            float v10 = acc[mi][nj][2], v11 = acc[mi][nj][3];
            if (MODE == 0) {
                if (col0 < 256) {
                    float sc0 = g_sc1[c], sc1 = g_sc1[c+1];
                    float sh0 = g_sh1[c], sh1 = g_sh1[c+1];
                    uint32_t lo, hi;
                    hi = pksplit_h(fmaxf(v00*sc0+sh0,0.f), fmaxf(v01*sc1+sh1,0.f), lo);
                    *(uint32_t*)&g_h1h[r1*256 + c] = hi; *(uint32_t*)&g_h1l[r1*256 + c] = lo;
                    hi = pksplit_h(fmaxf(v10*sc0+sh0,0.f), fmaxf(v11*sc1+sh1,0.f), lo);
                    *(uint32_t*)&g_h1h[r2*256 + c] = hi; *(uint32_t*)&g_h1l[r2*256 + c] = lo;
                } else {
                    int cc = c - 256;
                    float b0 = g_bmsg[cc], b1 = g_bmsg[cc+1];
                    *(uint32_t*)&g_msg[r1*256 + cc] = pkh(fmaxf(v00+b0,0.f), fmaxf(v01+b1,0.f));
                    *(uint32_t*)&g_msg[r2*256 + cc] = pkh(fmaxf(v10+b0,0.f), fmaxf(v11+b1,0.f));
                }
            } else if (MODE == 1) {
                float sh0 = g_sh2[c], sh1 = g_sh2[c+1];
                uint32_t lo, hi;
                float a0 = fmaxf(v00 + sh0 + x[r1*256+c],   0.f);
                float a1 = fmaxf(v01 + sh1 + x[r1*256+c+1], 0.f);
                hi = pksplit_h(a0, a1, lo);
                *(uint32_t*)&g_xch[r1*256 + c] = hi; *(uint32_t*)&g_xcl[r1*256 + c] = lo;
                a0 = fmaxf(v10 + sh0 + x[r2*256+c],   0.f);
                a1 = fmaxf(v11 + sh1 + x[r2*256+c+1], 0.f);
                hi = pksplit_h(a0, a1, lo);
                *(uint32_t*)&g_xch[r2*256 + c] = hi; *(uint32_t*)&g_xcl[r2*256 + c] = lo;
            } else if (MODE == 2) {
                *(uint32_t*)&g_gi[r1*768 + c] = pkh(v00, v01);
                *(uint32_t*)&g_gi[r2*768 + c] = pkh(v10, v11);
            } else {
                *(uint32_t*)&g_gh[r1*768 + c] = pkh(v00, v01);
                *(uint32_t*)&g_gh[r2*768 + c] = pkh(v10, v11);
            }
        }
    }
}

// ---------------- s projection -> (u, q') and (s, q') ---------------------
__global__ void skernel(const float* __restrict__ x,
                        const float* __restrict__ w_se,
                        const float* __restrict__ b_se) {
    int row = blockIdx.x * 8 + (threadIdx.x >> 5);
    int lane = threadIdx.x & 31;
    float p0=0.f, p1=0.f, p2=0.f;
    for (int k = lane; k < DIM; k += 32) {
        float xv = x[(size_t)row*DIM + k];
        p0 += xv * w_se[k];
        p1 += xv * w_se[DIM + k];
        p2 += xv * w_se[2*DIM + k];
    }
    #pragma unroll
    for (int off = 16; off > 0; off >>= 1) {
        p0 += __shfl_down_sync(0xffffffffu, p0, off);
        p1 += __shfl_down_sync(0xffffffffu, p1, off);
        p2 += __shfl_down_sync(0xffffffffu, p2, off);
    }
    if (lane == 0) {
        const float L2E = 1.4426950408889634f;
        p0 += b_se[0]; p1 += b_se[1]; p2 += b_se[2];
        float sq = p0*p0 + p1*p1 + p2*p2;
        float qp = -L2E * sq;
        g_s2[row*8+0] = 2.0f*L2E*p0;
        g_s2[row*8+1] = 2.0f*L2E*p1;
        g_s2[row*8+2] = 2.0f*L2E*p2;
        g_s2[row*8+3] = qp;
        g_s2[row*8+4] = p0;
        g_s2[row*8+5] = p1;
        g_s2[row*8+6] = p2;
        g_s2[row*8+7] = qp;
    }
}

// ---------------- tensorized NMP: 2 barriers/chunk, double-buffered -------
#define NWP  80
#define NWH(s)  ((s)*5120)             // W bufs: 0, 5120
#define NMPITCH 528
#define NMH(s) (10240 + (s)*16896)     // msg stages: 10240, 27136
#define NSMH(s) (44032 + (s)*256)      // sSm bufs
#define NMP_SMEM 44544

__global__ void __launch_bounds__(256, 2) nmp_kernel(const float* __restrict__ mask) {
    extern __shared__ char smem[];
    const uint32_t sb = smem_u32(smem);
    const int b  = blockIdx.y;
    const int n0 = blockIdx.x * 64;
    const int tid = threadIdx.x;
    const int wid = tid >> 5, lane = tid & 31;
    const int warp_n = wid & 1, warp_d = wid >> 1;
    const int gid = lane >> 2, tid4 = lane & 3;

    const uint32_t aOff  = (uint32_t)(lane & 15)*NWP + (uint32_t)(lane >> 4)*16;
    const uint32_t bOffT = (uint32_t)(lane & 15)*NMPITCH + (uint32_t)(lane >> 4)*16;

    const size_t mbase = ((size_t)b*NSEQ + n0) * NSEQ;
    const int rr = tid >> 2, mm0 = (tid & 3)*8;

    __half2 u0i, u1i, u2i, qi2;
    {
        const float* sp = &g_s2[((size_t)b*NSEQ + n0 + rr)*8];
        u0i = __float2half2_rn(sp[0]);
        u1i = __float2half2_rn(sp[1]);
        u2i = __float2half2_rn(sp[2]);
        qi2 = __float2half2_rn(sp[3]);
    }

    const int mrow = tid >> 5;
    const int mu   = tid & 31;

#define NMP_PREFETCH(c, s) { \
    uint32_t dh = sb + NMH(s); \
    const __half* srch = g_msg + ((size_t)b*NSEQ + (c)*32)*256; \
    _Pragma("unroll") \
    for (int q = 0; q < 4; q++) { \
        int row = mrow + q*8; \
        CPA16(dh + (uint32_t)row*NMPITCH + (uint32_t)mu*16, srch + (size_t)row*256 + mu*8); \
    } }

#define SSM_STORE(c, s) { \
    if (tid < 128) { \
        int j = tid >> 2, comp = tid & 3; \
        ((__half*)(smem + NSMH(s)))[comp*32 + j] = \
            __float2half_rn(g_s2[((size_t)b*NSEQ + (c)*32 + j)*8 + 4 + comp]); \
    } }

    SSM_STORE(0, 0);
    NMP_PREFETCH(0, 0); CPCOMMIT();

    float acc[2][8][4] = {};
    constexpr int NCn = NSEQ/32;

    for (int c = 0; c < NCn; c++) {
        int s = c & 1;
        __syncthreads();   // ends MMA(c-1); publishes sSm(c)
        if (c+1 < NCn) SSM_STORE(c+1, 1-s);
        {   // compute W(c) from sSm buf s -> W buf s
            const __half* sSmH = (const __half*)(smem + NSMH(s));
            const float* mrow_p = &mask[mbase + (size_t)rr*NSEQ + c*32 + mm0];
            float4 mk0 = *(const float4*)mrow_p;
            float4 mk1 = *(const float4*)(mrow_p + 4);
            uint32_t wv[4];
            #pragma unroll
            for (int p = 0; p < 4; p++) {
                int mm = mm0 + 2*p;
                __half2 s0p = *(__half2*)&sSmH[      mm];
                __half2 s1p = *(__half2*)&sSmH[32  + mm];
                __half2 s2p = *(__half2*)&sSmH[64  + mm];
                __half2 qjp = *(__half2*)&sSmH[96  + mm];
                __half2 t2 = __hfma2(u0i, s0p, qjp);
                t2 = __hfma2(u1i, s1p, t2);
                t2 = __hfma2(u2i, s2p, t2);
                t2 = __hadd2(t2, qi2);
                uint32_t e2;
                asm("ex2.approx.f16x2 %0, %1;" : "=r"(e2) : "r"(*(uint32_t*)&t2));
                float mka = (p < 2) ? ((p == 0) ? mk0.x : mk0.z) : ((p == 2) ? mk1.x : mk1.z);
                float mkb = (p < 2) ? ((p == 0) ? mk0.y : mk0.w) : ((p == 2) ? mk1.y : mk1.w);
                __half2 mh = __floats2half2_rn(mka, mkb);
                __half2 w2 = __hmul2(*(__half2*)&e2, mh);
                wv[p] = *(uint32_t*)&w2;
            }
            *(uint4*)(smem + NWH(s) + rr*NWP + mm0*2) = make_uint4(wv[0],wv[1],wv[2],wv[3]);
        }
        if (c+1 < NCn) { NMP_PREFETCH(c+1, 1-s); CPCOMMIT(); CPWAIT(1); }
        else           { CPWAIT(0); }
        __syncthreads();   // W(c), msg(c), and prefetch ordering
        #pragma unroll
        for (int ks = 0; ks < 2; ks++) {
            uint32_t Aw[2][4], Bm[4][4];
            #pragma unroll
            for (int mi = 0; mi < 2; mi++) {
                uint32_t ad = sb + NWH(s) + (warp_n*32 + mi*16)*NWP + ks*32 + aOff;
                LDMX4(Aw[mi][0],Aw[mi][1],Aw[mi][2],Aw[mi][3], ad);
            }
            #pragma unroll
            for (int dj = 0; dj < 4; dj++) {
                uint32_t bd = sb + NMH(s) + (ks*16)*NMPITCH + (warp_d*64 + dj*16)*2 + bOffT;
                LDMX4T(Bm[dj][0],Bm[dj][1],Bm[dj][2],Bm[dj][3], bd);
            }
            #pragma unroll
            for (int mi = 0; mi < 2; mi++)
                #pragma unroll
                for (int dj = 0; dj < 4; dj++)
                    #pragma unroll
                    for (int h = 0; h < 2; h++)
                        MMA_F16(acc[mi][dj*2 + h], Aw[mi], Bm[dj][h*2], Bm[dj][h*2+1]);
        }
    }
#undef NMP_PREFETCH
#undef SSM_STORE

    #pragma unroll
    for (int mi = 0; mi < 2; mi++) {
        #pragma unroll
        for (int dj8 = 0; dj8 < 8; dj8++) {
            int d = warp_d*64 + dj8*8 + tid4*2;
            size_t r1 = (size_t)b*NSEQ + n0 + warp_n*32 + mi*16 + gid;
            size_t r2 = r1 + 8;
            uint32_t lo, hi;
            hi = pksplit_h(acc[mi][dj8][0], acc[mi][dj8][1], lo);
            *(uint32_t*)&g_xnh[r1*256 + d] = hi; *(uint32_t*)&g_xnl[r1*256 + d] = lo;
            hi = pksplit_h(acc[mi][dj8][2], acc[mi][dj8][3], lo);
            *(uint32_t*)&g_xnh[r2*256 + d] = hi; *(uint32_t*)&g_xnl[r2*256 + d] = lo;
        }
    }
}

// ---------------- gate epilogue (fp16 gi/gh) ------------------------------
__global__ void gate_kernel(const float* __restrict__ x,
                            const float* __restrict__ b_ih,
                            const float* __restrict__ b_hh,
                            float* __restrict__ out) {
    int idx = blockIdx.x * blockDim.x + threadIdx.x;
    size_t r = idx >> 6;
    int c = (idx & 63) * 4;
    const __half* gi = &g_gi[r*768];
    const __half* gh = &g_gh[r*768];
    float4 xv  = *(const float4*)&x[r*DIM + c];
    float o4[4];
    #pragma unroll
    for (int p = 0; p < 2; p++) {
        int cc = c + 2*p;
        float2 gir = __half22float2(*(__half2*)&gi[cc]);
        float2 giz = __half22float2(*(__half2*)&gi[256 + cc]);
        float2 gin = __half22float2(*(__half2*)&gi[512 + cc]);
        float2 ghr = __half22float2(*(__half2*)&gh[cc]);
        float2 ghz = __half22float2(*(__half2*)&gh[256 + cc]);
        float2 ghn = __half22float2(*(__half2*)&gh[512 + cc]);
        #pragma unroll
        for (int q = 0; q < 2; q++) {
            int cq = cc + q;
            float air = ((q==0)?gir.x:gir.y) + b_ih[cq]     + ((q==0)?ghr.x:ghr.y) + b_hh[cq];
            float aiz = ((q==0)?giz.x:giz.y) + b_ih[256+cq] + ((q==0)?ghz.x:ghz.y) + b_hh[256+cq];
            float rv = 1.0f/(1.0f + __expf(-air));
            float zv = 1.0f/(1.0f + __expf(-aiz));
            float nv = tanhf(((q==0)?gin.x:gin.y) + b_ih[512+cq]
                           + rv*(((q==0)?ghn.x:ghn.y) + b_hh[512+cq]));
            o4[2*p+q] = (1.0f - zv)*nv + zv*(&xv.x)[2*p+q];
        }
    }
    *(float4*)&out[r*DIM + c] = make_float4(o4[0], o4[1], o4[2], o4[3]);
}

// ---------------- launch --------------------------------------------------
extern "C" void kernel_launch(void* const* d_in, const int* in_sizes, int n_in,
                              void* d_out, int out_size) {
    const float* x       = (const float*)d_in[0];
    const float* mask    = (const float*)d_in[1];
    const float* w_se    = (const float*)d_in[2];
    const float* b_se    = (const float*)d_in[3];
    const float* conv1_w = (const float*)d_in[4];
    const float* bn1_g   = (const float*)d_in[5];
    const float* bn1_b   = (const float*)d_in[6];
    const float* bn1_m   = (const float*)d_in[7];
    const float* bn1_v   = (const float*)d_in[8];
    const float* conv2_w = (const float*)d_in[9];
    const float* bn2_g   = (const float*)d_in[10];
    const float* bn2_b   = (const float*)d_in[11];
    const float* bn2_m   = (const float*)d_in[12];
    const float* bn2_v   = (const float*)d_in[13];
    const float* w_msg   = (const float*)d_in[14];
    const float* b_msg   = (const float*)d_in[15];
    const float* w_ih    = (const float*)d_in[16];
    const float* b_ih    = (const float*)d_in[17];
    const float* w_hh    = (const float*)d_in[18];
    const float* b_hh    = (const float*)d_in[19];
    float* out = (float*)d_out;

    cudaFuncSetAttribute(mma_gemm<0>, cudaFuncAttributeMaxDynamicSharedMemorySize, GEMM_SMEM);
    cudaFuncSetAttribute(mma_gemm<1>, cudaFuncAttributeMaxDynamicSharedMemorySize, GEMM_SMEM);
    cudaFuncSetAttribute(mma_gemm<2>, cudaFuncAttributeMaxDynamicSharedMemorySize, GEMM_SMEM);
    cudaFuncSetAttribute(mma_gemm<3>, cudaFuncAttributeMaxDynamicSharedMemorySize, GEMM_SMEM);
    cudaFuncSetAttribute(nmp_kernel,  cudaFuncAttributeMaxDynamicSharedMemorySize, NMP_SMEM);

    repack_kernel<<<1024, 256>>>(x, conv1_w, w_msg, conv2_w,
                                 bn1_g, bn1_b, bn1_m, bn1_v,
                                 bn2_g, bn2_b, bn2_m, bn2_v,
                                 b_msg, w_ih, w_hh);

    mma_gemm<0><<<dim3(4, NROWS/256), 256, GEMM_SMEM>>>(x);      // front: h1 + msg

    skernel<<<NROWS/8, 256>>>(x, w_se, b_se);

    mma_gemm<1><<<dim3(2, NSEQ/256, BS), 256, GEMM_SMEM>>>(x);   // conv2 -> xc

    nmp_kernel<<<dim3(NSEQ/64, BS), 256, NMP_SMEM>>>(mask);      // -> xn

    mma_gemm<2><<<dim3(6, NROWS/256), 256, GEMM_SMEM>>>(x);      // gi
    mma_gemm<3><<<dim3(6, NROWS/256), 256, GEMM_SMEM>>>(x);      // gh

    gate_kernel<<<NROWS*64/256, 256>>>(x, b_ih, b_hh, out);
}

// round 10
// speedup vs baseline: 3.5297x; 1.1446x over previous
#include <cuda_runtime.h>
#include <cuda_fp16.h>
#include <math.h>
#include <stdint.h>

#define BS   16
#define NSEQ 2048
#define DIM  256
#define NROWS (BS*NSEQ)   // 32768

// ---------------- scratch (device globals) --------------------------------
__device__ float g_s2[NROWS*8];          // [u0,u1,u2,q'] [s0,s1,s2,q']
__device__ __half g_gi[(size_t)NROWS*768];
__device__ __half g_gh[(size_t)NROWS*768];

// fp16 activations
__device__ __half g_xh[NROWS*DIM],  g_xl[NROWS*DIM];     // x split
__device__ __half g_h1s[NROWS*DIM];                      // h1 SINGLE fp16
__device__ __half g_xch[NROWS*DIM], g_xcl[NROWS*DIM];    // xconv split
__device__ __half g_xnh[NROWS*DIM], g_xnl[NROWS*DIM];    // xnmp split
__device__ __half g_msg[NROWS*DIM];                      // single fp16 (positive)

// fp16 hi/lo split weights ([out][in], K-major)
__device__ __half g_wfh[512*256],  g_wfl[512*256];
__device__ __half g_w2h[256*4352], g_w2l[256*4352];
__device__ __half g_wihh[768*512], g_wihl[768*512];
__device__ __half g_whhh[768*256], g_whhl[768*256];

// bn constants
__device__ float g_sc1[DIM], g_sh1[DIM], g_sh2[DIM], g_bmsg[DIM];

// ---------------- helpers --------------------------------------------------
__device__ __forceinline__ uint32_t smem_u32(const void* p) {
    uint32_t a;
    asm("{ .reg .u64 t; cvta.to.shared.u64 t, %1; cvt.u32.u64 %0, t; }"
        : "=r"(a) : "l"(p));
    return a;
}
__device__ __forceinline__ uint32_t pkh(float a, float b) {
    __half2 h = __floats2half2_rn(a, b);
    return *(uint32_t*)&h;
}
__device__ __forceinline__ uint32_t pksplit_h(float a, float b, uint32_t& lo) {
    __half ha = __float2half_rn(a), hb = __float2half_rn(b);
    lo = pkh(a - __half2float(ha), b - __half2float(hb));
    __half2 h2; h2.x = ha; h2.y = hb;
    return *(uint32_t*)&h2;
}

#define LDMX4(r0,r1,r2,r3,addr) \
    asm volatile("ldmatrix.sync.aligned.m8n8.x4.shared.b16 {%0,%1,%2,%3}, [%4];" \
        : "=r"(r0),"=r"(r1),"=r"(r2),"=r"(r3) : "r"(addr))
#define LDMX4T(r0,r1,r2,r3,addr) \
    asm volatile("ldmatrix.sync.aligned.m8n8.x4.trans.shared.b16 {%0,%1,%2,%3}, [%4];" \
        : "=r"(r0),"=r"(r1),"=r"(r2),"=r"(r3) : "r"(addr))
#define MMA_F16(d, a, b0, b1) \
    asm volatile("mma.sync.aligned.m16n8k16.row.col.f32.f16.f16.f32 " \
        "{%0,%1,%2,%3}, {%4,%5,%6,%7}, {%8,%9}, {%0,%1,%2,%3};" \
        : "+f"((d)[0]),"+f"((d)[1]),"+f"((d)[2]),"+f"((d)[3]) \
        : "r"((a)[0]),"r"((a)[1]),"r"((a)[2]),"r"((a)[3]), "r"(b0),"r"(b1))

#define CPA16(dst, src) \
    asm volatile("cp.async.cg.shared.global [%0], [%1], 16;" :: "r"(dst), "l"(src))
#define CPA16Z(dst, src, sz) \
    asm volatile("cp.async.cg.shared.global [%0], [%1], 16, %2;" :: "r"(dst), "l"(src), "r"(sz))
#define CPCOMMIT() asm volatile("cp.async.commit_group;" ::: "memory")
#define CPWAIT(n)  asm volatile("cp.async.wait_group %0;" :: "n"(n) : "memory")

// ---------------- repack ---------------------------------------------------
__global__ void repack_kernel(const float* __restrict__ x,
                              const float* __restrict__ conv1_w,
                              const float* __restrict__ w_msg,
                              const float* __restrict__ conv2_w,
                              const float* __restrict__ bn1_g, const float* __restrict__ bn1_b,
                              const float* __restrict__ bn1_m, const float* __restrict__ bn1_v,
                              const float* __restrict__ bn2_g, const float* __restrict__ bn2_b,
                              const float* __restrict__ bn2_m, const float* __restrict__ bn2_v,
                              const float* __restrict__ b_msg,
                              const float* __restrict__ w_ih,
                              const float* __restrict__ w_hh) {
    int stride = gridDim.x * blockDim.x;
    int idx = blockIdx.x * blockDim.x + threadIdx.x;
    if (idx < DIM) {
        float sc = bn1_g[idx] * rsqrtf(bn1_v[idx] + 1e-5f);
        g_sc1[idx] = sc;
        g_sh1[idx] = bn1_b[idx] - bn1_m[idx]*sc;
        float sc2 = bn2_g[idx] * rsqrtf(bn2_v[idx] + 1e-5f);
        g_sh2[idx] = bn2_b[idx] - bn2_m[idx]*sc2;
        g_bmsg[idx] = b_msg[idx];
    }
    for (int i = idx; i < 512*256; i += stride) {
        int n = i >> 8, k = i & 255;
        float v = (n < 256) ? conv1_w[n*256 + k] : w_msg[(n-256)*256 + k];
        __half h = __float2half_rn(v);
        g_wfh[i] = h; g_wfl[i] = __float2half_rn(v - __half2float(h));
    }
    for (int i = idx; i < 256*4352; i += stride) {
        int o = i / 4352, kk = i - o*4352;
        int tap = kk >> 8, ic = kk & 255;
        float sc = bn2_g[o] * rsqrtf(bn2_v[o] + 1e-5f);
        float v = conv2_w[(o*256 + ic)*17 + tap] * sc;
        __half h = __float2half_rn(v);
        g_w2h[i] = h; g_w2l[i] = __float2half_rn(v - __half2float(h));
    }
    for (int i = idx; i < 768*512; i += stride) {
        float v = w_ih[i];
        __half h = __float2half_rn(v);
        g_wihh[i] = h; g_wihl[i] = __float2half_rn(v - __half2float(h));
    }
    for (int i = idx; i < 768*256; i += stride) {
        float v = w_hh[i];
        __half h = __float2half_rn(v);
        g_whhh[i] = h; g_whhl[i] = __float2half_rn(v - __half2float(h));
    }
    for (int i = idx; i < NROWS*DIM; i += stride) {
        float v = x[i];
        __half h = __float2half_rn(v);
        g_xh[i] = h; g_xl[i] = __float2half_rn(v - __half2float(h));
    }
}

// == HMMA GEMM: 256x128 CTA tile, 64x64 warp tile, 3-stage, 1 barrier/chunk =
// MODE 1 (conv2): A single fp16 (2 MMAs). Other modes: A split (3 MMAs).
#define PITCH 80
#define A_ARR 20480            // 256 rows * 80
#define B_ARR 10240            // 128 rows * 80
#define SM_AHI(s) ((s)*61440 + 0)
#define SM_ALO(s) ((s)*61440 + A_ARR)
#define SM_BHI(s) ((s)*61440 + 2*A_ARR)
#define SM_BLO(s) ((s)*61440 + 2*A_ARR + B_ARR)
#define GEMM_SMEM 184320

template<int MODE>
__global__ void __launch_bounds__(256, 1) mma_gemm(const float* __restrict__ x) {
    extern __shared__ char smem[];
    const int tid  = threadIdx.x;
    const int wid  = tid >> 5, lane = tid & 31;
    const int warp_m = wid & 3;        // 4 x 64 rows
    const int warp_n = wid >> 2;       // 2 x 64 cols
    const int gid  = lane >> 2, tid4 = lane & 3;
    const uint32_t sb = smem_u32(smem);

    constexpr int KT = (MODE==0) ? 256 : (MODE==1) ? 4352 : (MODE==2) ? 512 : 256;
    constexpr int NC = KT / 32;
    const int col0 = blockIdx.x * 128;
    const int bz = blockIdx.z;
    const int t0 = blockIdx.y * 256;
    const int row0 = (MODE==1) ? (bz*NSEQ + t0) : t0;

    const uint32_t aOff = (uint32_t)(lane & 15)*PITCH + (uint32_t)(lane >> 4)*16;
    const uint32_t bOff = (uint32_t)(((lane >> 4) << 3) + (lane & 7))*PITCH
                        + (uint32_t)((lane >> 3) & 1)*16;

    const int r0_ = tid >> 2, u_ = tid & 3;

    float acc[4][8][4] = {};

#define CPA_TILE(c, s) { \
    uint32_t dAh = sb + SM_AHI(s), dAl = sb + SM_ALO(s); \
    uint32_t dBh = sb + SM_BHI(s), dBl = sb + SM_BLO(s); \
    _Pragma("unroll") \
    for (int g = 0; g < 4; g++) { \
        int arow = r0_ + 64*g; \
        uint32_t o = (uint32_t)(arow*PITCH + u_*16); \
        if (MODE == 0 || MODE == 3) { \
            size_t a0 = (size_t)(row0+arow)*256 + (c)*32 + u_*8; \
            CPA16(dAh+o, g_xh+a0); CPA16(dAl+o, g_xl+a0); \
        } else if (MODE == 1) { \
            int tap = (c) >> 3, kloc = ((c) & 7)*32; \
            int t1 = t0 + arow + tap - 8; \
            uint32_t z1 = ((unsigned)t1 < (unsigned)NSEQ) ? 16u : 0u; \
            int tc1 = min(max(t1, 0), NSEQ-1); \
            size_t a0 = ((size_t)bz*NSEQ + tc1)*256 + kloc + u_*8; \
            CPA16Z(dAh+o, g_h1s+a0, z1); \
        } else { \
            const __half* sh_ = ((c) < 8) ? g_xch : g_xnh; \
            const __half* sl_ = ((c) < 8) ? g_xcl : g_xnl; \
            int kk_ = ((c) & 7)*32; \
            size_t a0 = (size_t)(row0+arow)*256 + kk_ + u_*8; \
            CPA16(dAh+o, sh_+a0); CPA16(dAl+o, sl_+a0); \
        } \
    } \
    _Pragma("unroll") \
    for (int g = 0; g < 2; g++) { \
        int brow = r0_ + 64*g; \
        uint32_t o = (uint32_t)(brow*PITCH + u_*16); \
        if (MODE == 0) { \
            size_t b0 = (size_t)(col0+brow)*256 + (c)*32 + u_*8; \
            CPA16(dBh+o, g_wfh+b0); CPA16(dBl+o, g_wfl+b0); \
        } else if (MODE == 1) { \
            size_t b0 = (size_t)(col0+brow)*4352 + (c)*32 + u_*8; \
            CPA16(dBh+o, g_w2h+b0); CPA16(dBl+o, g_w2l+b0); \
        } else if (MODE == 2) { \
            size_t b0 = (size_t)(col0+brow)*512 + (c)*32 + u_*8; \
            CPA16(dBh+o, g_wihh+b0); CPA16(dBl+o, g_wihl+b0); \
        } else { \
            size_t b0 = (size_t)(col0+brow)*256 + (c)*32 + u_*8; \
            CPA16(dBh+o, g_whhh+b0); CPA16(dBl+o, g_whhl+b0); \
        } \
    } }

#define COMPUTE(s) { \
    _Pragma("unroll") \
    for (int ks = 0; ks < 2; ks++) { \
        uint32_t Ah[4][4], Al[4][4]; \
        _Pragma("unroll") \
        for (int mi = 0; mi < 4; mi++) { \
            uint32_t ad = sb + SM_AHI(s) + (warp_m*64 + mi*16)*PITCH + ks*32 + aOff; \
            LDMX4(Ah[mi][0],Ah[mi][1],Ah[mi][2],Ah[mi][3], ad); \
            if (MODE != 1) { \
                ad = sb + SM_ALO(s) + (warp_m*64 + mi*16)*PITCH + ks*32 + aOff; \
                LDMX4(Al[mi][0],Al[mi][1],Al[mi][2],Al[mi][3], ad); \
            } \
        } \
        _Pragma("unroll") \
        for (int pj = 0; pj < 4; pj++) { \
            uint32_t Bh[4], Bl[4]; \
            uint32_t bd = sb + SM_BHI(s) + (warp_n*64 + pj*16)*PITCH + ks*32 + bOff; \
            LDMX4(Bh[0],Bh[1],Bh[2],Bh[3], bd); \
            bd = sb + SM_BLO(s) + (warp_n*64 + pj*16)*PITCH + ks*32 + bOff; \
            LDMX4(Bl[0],Bl[1],Bl[2],Bl[3], bd); \
            _Pragma("unroll") \
            for (int mi = 0; mi < 4; mi++) \
                _Pragma("unroll") \
                for (int h = 0; h < 2; h++) { \
                    float* D = acc[mi][pj*2 + h]; \
                    MMA_F16(D, Ah[mi], Bh[h*2], Bh[h*2+1]); \
                    MMA_F16(D, Ah[mi], Bl[h*2], Bl[h*2+1]); \
                    if (MODE != 1) MMA_F16(D, Al[mi], Bh[h*2], Bh[h*2+1]); \
                } \
        } \
    } }

    CPA_TILE(0, 0); CPCOMMIT();
    CPA_TILE(1, 1); CPCOMMIT();
    for (int c = 0; c < NC; c++) {
        if (c + 1 < NC) { CPWAIT(1); } else { CPWAIT(0); }
        __syncthreads();
        if (c + 2 < NC) { CPA_TILE(c+2, (c+2)%3); CPCOMMIT(); }
        COMPUTE(c%3);
    }
#undef CPA_TILE
#undef COMPUTE

    // ---------------- epilogue ----------------
    #pragma unroll
    for (int mi = 0; mi < 4; mi++) {
        #pragma unroll
        for (int nj = 0; nj < 8; nj++) {
            int c = col0 + warp_n*64 + nj*8 + tid4*2;
            size_t r1 = (size_t)row0 + warp_m*64 + mi*16 + gid;
            size_t r2 = r1 + 8;
            float v00 = acc[mi][nj][0], v01 = acc[mi][nj][1];
            float v10 = acc[mi][nj][2], v11 = acc[mi][nj][3];
            if (MODE == 0) {
                if (col0 < 256) {
                    float sc0 = g_sc1[c], sc1 = g_sc1[c+1];
                    float sh0 = g_sh1[c], sh1 = g_sh1[c+1];
                    *(uint32_t*)&g_h1s[r1*256 + c] =
                        pkh(fmaxf(v00*sc0+sh0,0.f), fmaxf(v01*sc1+sh1,0.f));
                    *(uint32_t*)&g_h1s[r2*256 + c] =
                        pkh(fmaxf(v10*sc0+sh0,0.f), fmaxf(v11*sc1+sh1,0.f));
                } else {
                    int cc = c - 256;
                    float b0 = g_bmsg[cc], b1 = g_bmsg[cc+1];
                    *(uint32_t*)&g_msg[r1*256 + cc] = pkh(fmaxf(v00+b0,0.f), fmaxf(v01+b1,0.f));
                    *(uint32_t*)&g_msg[r2*256 + cc] = pkh(fmaxf(v10+b0,0.f), fmaxf(v11+b1,0.f));
                }
            } else if (MODE == 1) {
                float sh0 = g_sh2[c], sh1 = g_sh2[c+1];
                uint32_t lo, hi;
                float a0 = fmaxf(v00 + sh0 + x[r1*256+c],   0.f);
                float a1 = fmaxf(v01 + sh1 + x[r1*256+c+1], 0.f);
                hi = pksplit_h(a0, a1, lo);
                *(uint32_t*)&g_xch[r1*256 + c] = hi; *(uint32_t*)&g_xcl[r1*256 + c] = lo;
                a0 = fmaxf(v10 + sh0 + x[r2*256+c],   0.f);
                a1 = fmaxf(v11 + sh1 + x[r2*256+c+1], 0.f);
                hi = pksplit_h(a0, a1, lo);
                *(uint32_t*)&g_xch[r2*256 + c] = hi; *(uint32_t*)&g_xcl[r2*256 + c] = lo;
            } else if (MODE == 2) {
                *(uint32_t*)&g_gi[r1*768 + c] = pkh(v00, v01);
                *(uint32_t*)&g_gi[r2*768 + c] = pkh(v10, v11);
            } else {
                *(uint32_t*)&g_gh[r1*768 + c] = pkh(v00, v01);
                *(uint32_t*)&g_gh[r2*768 + c] = pkh(v10, v11);
            }
        }
    }
}

// ---------------- s projection -> (u, q') and (s, q') ---------------------
__global__ void skernel(const float* __restrict__ x,
                        const float* __restrict__ w_se,
                        const float* __restrict__ b_se) {
    int row = blockIdx.x * 8 + (threadIdx.x >> 5);
    int lane = threadIdx.x & 31;
    float p0=0.f, p1=0.f, p2=0.f;
    for (int k = lane; k < DIM; k += 32) {
        float xv = x[(size_t)row*DIM + k];
        p0 += xv * w_se[k];
        p1 += xv * w_se[DIM + k];
        p2 += xv * w_se[2*DIM + k];
    }
    #pragma unroll
    for (int off = 16; off > 0; off >>= 1) {
        p0 += __shfl_down_sync(0xffffffffu, p0, off);
        p1 += __shfl_down_sync(0xffffffffu, p1, off);
        p2 += __shfl_down_sync(0xffffffffu, p2, off);
    }
    if (lane == 0) {
        const float L2E = 1.4426950408889634f;
        p0 += b_se[0]; p1 += b_se[1]; p2 += b_se[2];
        float sq = p0*p0 + p1*p1 + p2*p2;
        float qp = -L2E * sq;
        g_s2[row*8+0] = 2.0f*L2E*p0;
        g_s2[row*8+1] = 2.0f*L2E*p1;
        g_s2[row*8+2] = 2.0f*L2E*p2;
        g_s2[row*8+3] = qp;
        g_s2[row*8+4] = p0;
        g_s2[row*8+5] = p1;
        g_s2[row*8+6] = p2;
        g_s2[row*8+7] = qp;
    }
}

// ---------------- tensorized NMP: fp32 t, f16x2 ex2, 1-MMA ---------------
#define NWP  80
#define NWH(s)  ((s)*5120)             // W bufs: 0, 5120
#define NMPITCH 528
#define NMH(s) (10240 + (s)*16896)     // msg stages: 10240, 27136
#define NSMF(s) (44032 + (s)*512)      // sSm float bufs (4*32 floats)
#define NMP_SMEM 45056

__global__ void __launch_bounds__(256, 2) nmp_kernel(const float* __restrict__ mask) {
    extern __shared__ char smem[];
    const uint32_t sb = smem_u32(smem);
    const int b  = blockIdx.y;
    const int n0 = blockIdx.x * 64;
    const int tid = threadIdx.x;
    const int wid = tid >> 5, lane = tid & 31;
    const int warp_n = wid & 1, warp_d = wid >> 1;
    const int gid = lane >> 2, tid4 = lane & 3;

    const uint32_t aOff  = (uint32_t)(lane & 15)*NWP + (uint32_t)(lane >> 4)*16;
    const uint32_t bOffT = (uint32_t)(lane & 15)*NMPITCH + (uint32_t)(lane >> 4)*16;

    const size_t mbase = ((size_t)b*NSEQ + n0) * NSEQ;
    const int rr = tid >> 2, mm0 = (tid & 3)*8;

    float u0i, u1i, u2i, qi;
    {
        const float* sp = &g_s2[((size_t)b*NSEQ + n0 + rr)*8];
        u0i = sp[0]; u1i = sp[1]; u2i = sp[2]; qi = sp[3];
    }

    const int mrow = tid >> 5;
    const int mu   = tid & 31;

#define NMP_PREFETCH(c, s) { \
    uint32_t dh = sb + NMH(s); \
    const __half* srch = g_msg + ((size_t)b*NSEQ + (c)*32)*256; \
    _Pragma("unroll") \
    for (int q = 0; q < 4; q++) { \
        int row = mrow + q*8; \
        CPA16(dh + (uint32_t)row*NMPITCH + (uint32_t)mu*16, srch + (size_t)row*256 + mu*8); \
    } }

#define SSM_STORE(c, s) { \
    if (tid < 128) { \
        int j = tid >> 2, comp = tid & 3; \
        ((float*)(smem + NSMF(s)))[comp*32 + j] = \
            g_s2[((size_t)b*NSEQ + (c)*32 + j)*8 + 4 + comp]; \
    } }

    SSM_STORE(0, 0);
    NMP_PREFETCH(0, 0); CPCOMMIT();

    float acc[2][8][4] = {};
    constexpr int NCn = NSEQ/32;
    const float L2E = 1.4426950408889634f;

    for (int c = 0; c < NCn; c++) {
        int s = c & 1;
        __syncthreads();   // ends MMA(c-1); publishes sSm(c)
        if (c+1 < NCn) SSM_STORE(c+1, 1-s);
        {   // compute W(c): t in fp32, ex2 in f16x2
            const float* sSmF = (const float*)(smem + NSMF(s));
            const float* mrow_p = &mask[mbase + (size_t)rr*NSEQ + c*32 + mm0];
            float4 mk0 = *(const float4*)mrow_p;
            float4 mk1 = *(const float4*)(mrow_p + 4);
            uint32_t wv[4];
            #pragma unroll
            for (int p = 0; p < 4; p++) {
                int mm = mm0 + 2*p;
                // t = u·s_j + q'_i + q'_j  (already log2-domain: u=2L2E·s_i, q'=-L2E·sq)
                float ta = fmaf(u0i, sSmF[mm],
                           fmaf(u1i, sSmF[32+mm],
                           fmaf(u2i, sSmF[64+mm], sSmF[96+mm] + qi)));
                float tb = fmaf(u0i, sSmF[mm+1],
                           fmaf(u1i, sSmF[32+mm+1],
                           fmaf(u2i, sSmF[64+mm+1], sSmF[96+mm+1] + qi)));
                __half2 t2 = __floats2half2_rn(ta, tb);
                uint32_t e2;
                asm("ex2.approx.f16x2 %0, %1;" : "=r"(e2) : "r"(*(uint32_t*)&t2));
                float mka = (p < 2) ? ((p == 0) ? mk0.x : mk0.z) : ((p == 2) ? mk1.x : mk1.z);
                float mkb = (p < 2) ? ((p == 0) ? mk0.y : mk0.w) : ((p == 2) ? mk1.y : mk1.w);
                __half2 mh = __floats2half2_rn(mka, mkb);
                __half2 w2 = __hmul2(*(__half2*)&e2, mh);
                wv[p] = *(uint32_t*)&w2;
            }
            *(uint4*)(smem + NWH(s) + rr*NWP + mm0*2) = make_uint4(wv[0],wv[1],wv[2],wv[3]);
        }
        if (c+1 < NCn) { NMP_PREFETCH(c+1, 1-s); CPCOMMIT(); CPWAIT(1); }
        else           { CPWAIT(0); }
        __syncthreads();   // W(c), msg(c) ready
        #pragma unroll
        for (int ks = 0; ks < 2; ks++) {
            uint32_t Aw[2][4], Bm[4][4];
            #pragma unroll
            for (int mi = 0; mi < 2; mi++) {
                uint32_t ad = sb + NWH(s) + (warp_n*32 + mi*16)*NWP + ks*32 + aOff;
                LDMX4(Aw[mi][0],Aw[mi][1],Aw[mi][2],Aw[mi][3], ad);
            }
            #pragma unroll
            for (int dj = 0; dj < 4; dj++) {
                uint32_t bd = sb + NMH(s) + (ks*16)*NMPITCH + (warp_d*64 + dj*16)*2 + bOffT;
                LDMX4T(Bm[dj][0],Bm[dj][1],Bm[dj][2],Bm[dj][3], bd);
            }
            #pragma unroll
            for (int mi = 0; mi < 2; mi++)
                #pragma unroll
                for (int dj = 0; dj < 4; dj++)
                    #pragma unroll
                    for (int h = 0; h < 2; h++)
                        MMA_F16(acc[mi][dj*2 + h], Aw[mi], Bm[dj][h*2], Bm[dj][h*2+1]);
        }
    }
#undef NMP_PREFETCH
#undef SSM_STORE

    #pragma unroll
    for (int mi = 0; mi < 2; mi++) {
        #pragma unroll
        for (int dj8 = 0; dj8 < 8; dj8++) {
            int d = warp_d*64 + dj8*8 + tid4*2;
            size_t r1 = (size_t)b*NSEQ + n0 + warp_n*32 + mi*16 + gid;
            size_t r2 = r1 + 8;
            uint32_t lo, hi;
            hi = pksplit_h(acc[mi][dj8][0], acc[mi][dj8][1], lo);
            *(uint32_t*)&g_xnh[r1*256 + d] = hi; *(uint32_t*)&g_xnl[r1*256 + d] = lo;
            hi = pksplit_h(acc[mi][dj8][2], acc[mi][dj8][3], lo);
            *(uint32_t*)&g_xnh[r2*256 + d] = hi; *(uint32_t*)&g_xnl[r2*256 + d] = lo;
        }
    }
}

// ---------------- gate epilogue (fp16 gi/gh) ------------------------------
__global__ void gate_kernel(const float* __restrict__ x,
                            const float* __restrict__ b_ih,
                            const float* __restrict__ b_hh,
                            float* __restrict__ out) {
    int idx = blockIdx.x * blockDim.x + threadIdx.x;
    size_t r = idx >> 6;
    int c = (idx & 63) * 4;
    const __half* gi = &g_gi[r*768];
    const __half* gh = &g_gh[r*768];
    float4 xv  = *(const float4*)&x[r*DIM + c];
    float o4[4];
    #pragma unroll
    for (int p = 0; p < 2; p++) {
        int cc = c + 2*p;
        float2 gir = __half22float2(*(__half2*)&gi[cc]);
        float2 giz = __half22float2(*(__half2*)&gi[256 + cc]);
        float2 gin = __half22float2(*(__half2*)&gi[512 + cc]);
        float2 ghr = __half22float2(*(__half2*)&gh[cc]);
        float2 ghz = __half22float2(*(__half2*)&gh[256 + cc]);
        float2 ghn = __half22float2(*(__half2*)&gh[512 + cc]);
        #pragma unroll
        for (int q = 0; q < 2; q++) {
            int cq = cc + q;
            float air = ((q==0)?gir.x:gir.y) + b_ih[cq]     + ((q==0)?ghr.x:ghr.y) + b_hh[cq];
            float aiz = ((q==0)?giz.x:giz.y) + b_ih[256+cq] + ((q==0)?ghz.x:ghz.y) + b_hh[256+cq];
            float rv = 1.0f/(1.0f + __expf(-air));
            float zv = 1.0f/(1.0f + __expf(-aiz));
            float nv = tanhf(((q==0)?gin.x:gin.y) + b_ih[512+cq]
                           + rv*(((q==0)?ghn.x:ghn.y) + b_hh[512+cq]));
            o4[2*p+q] = (1.0f - zv)*nv + zv*(&xv.x)[2*p+q];
        }
    }
    *(float4*)&out[r*DIM + c] = make_float4(o4[0], o4[1], o4[2], o4[3]);
}

// ---------------- launch --------------------------------------------------
extern "C" void kernel_launch(void* const* d_in, const int* in_sizes, int n_in,
                              void* d_out, int out_size) {
    const float* x       = (const float*)d_in[0];
    const float* mask    = (const float*)d_in[1];
    const float* w_se    = (const float*)d_in[2];
    const float* b_se    = (const float*)d_in[3];
    const float* conv1_w = (const float*)d_in[4];
    const float* bn1_g   = (const float*)d_in[5];
    const float* bn1_b   = (const float*)d_in[6];
    const float* bn1_m   = (const float*)d_in[7];
    const float* bn1_v   = (const float*)d_in[8];
    const float* conv2_w = (const float*)d_in[9];
    const float* bn2_g   = (const float*)d_in[10];
    const float* bn2_b   = (const float*)d_in[11];
    const float* bn2_m   = (const float*)d_in[12];
    const float* bn2_v   = (const float*)d_in[13];
    const float* w_msg   = (const float*)d_in[14];
    const float* b_msg   = (const float*)d_in[15];
    const float* w_ih    = (const float*)d_in[16];
    const float* b_ih    = (const float*)d_in[17];
    const float* w_hh    = (const float*)d_in[18];
    const float* b_hh    = (const float*)d_in[19];
    float* out = (float*)d_out;

    cudaFuncSetAttribute(mma_gemm<0>, cudaFuncAttributeMaxDynamicSharedMemorySize, GEMM_SMEM);
    cudaFuncSetAttribute(mma_gemm<1>, cudaFuncAttributeMaxDynamicSharedMemorySize, GEMM_SMEM);
    cudaFuncSetAttribute(mma_gemm<2>, cudaFuncAttributeMaxDynamicSharedMemorySize, GEMM_SMEM);
    cudaFuncSetAttribute(mma_gemm<3>, cudaFuncAttributeMaxDynamicSharedMemorySize, GEMM_SMEM);
    cudaFuncSetAttribute(nmp_kernel,  cudaFuncAttributeMaxDynamicSharedMemorySize, NMP_SMEM);

    repack_kernel<<<1024, 256>>>(x, conv1_w, w_msg, conv2_w,
                                 bn1_g, bn1_b, bn1_m, bn1_v,
                                 bn2_g, bn2_b, bn2_m, bn2_v,
                                 b_msg, w_ih, w_hh);

    mma_gemm<0><<<dim3(4, NROWS/256), 256, GEMM_SMEM>>>(x);      // front: h1 + msg

    skernel<<<NROWS/8, 256>>>(x, w_se, b_se);

    mma_gemm<1><<<dim3(2, NSEQ/256, BS), 256, GEMM_SMEM>>>(x);   // conv2 -> xc

    nmp_kernel<<<dim3(NSEQ/64, BS), 256, NMP_SMEM>>>(mask);      // -> xn

    mma_gemm<2><<<dim3(6, NROWS/256), 256, GEMM_SMEM>>>(x);      // gi
    mma_gemm<3><<<dim3(6, NROWS/256), 256, GEMM_SMEM>>>(x);      // gh

    gate_kernel<<<NROWS*64/256, 256>>>(x, b_ih, b_hh, out);
}

// round 12
// speedup vs baseline: 3.5972x; 1.0191x over previous
#include <cuda_runtime.h>
#include <cuda_fp16.h>
#include <math.h>
#include <stdint.h>

#define BS   16
#define NSEQ 2048
#define DIM  256
#define NROWS (BS*NSEQ)   // 32768

// ---------------- scratch (device globals) --------------------------------
__device__ float g_s2[NROWS*8];          // [u0,u1,u2,q'] [s0,s1,s2,q']
__device__ __half g_gi[(size_t)NROWS*768];
__device__ __half g_gh[(size_t)NROWS*768];

// fp16 activations
__device__ __half g_xh[NROWS*DIM],  g_xl[NROWS*DIM];     // x split
__device__ __half g_h1s[NROWS*DIM];                      // h1 SINGLE fp16
__device__ __half g_xch[NROWS*DIM], g_xcl[NROWS*DIM];    // xconv split
__device__ __half g_xnh[NROWS*DIM], g_xnl[NROWS*DIM];    // xnmp split
__device__ __half g_msg[NROWS*DIM];                      // single fp16 (positive)

// fp16 hi/lo split weights ([out][in], K-major)
__device__ __half g_wfh[512*256],  g_wfl[512*256];
__device__ __half g_w2h[256*4352], g_w2l[256*4352];
__device__ __half g_wihh[768*512], g_wihl[768*512];
__device__ __half g_whhh[768*256], g_whhl[768*256];

// bn constants
__device__ float g_sc1[DIM], g_sh1[DIM], g_sh2[DIM], g_bmsg[DIM];

// ---------------- helpers --------------------------------------------------
__device__ __forceinline__ uint32_t smem_u32(const void* p) {
    uint32_t a;
    asm("{ .reg .u64 t; cvta.to.shared.u64 t, %1; cvt.u32.u64 %0, t; }"
        : "=r"(a) : "l"(p));
    return a;
}
__device__ __forceinline__ uint32_t pkh(float a, float b) {
    __half2 h = __floats2half2_rn(a, b);
    return *(uint32_t*)&h;
}
__device__ __forceinline__ uint32_t pksplit_h(float a, float b, uint32_t& lo) {
    __half ha = __float2half_rn(a), hb = __float2half_rn(b);
    lo = pkh(a - __half2float(ha), b - __half2float(hb));
    __half2 h2; h2.x = ha; h2.y = hb;
    return *(uint32_t*)&h2;
}

#define LDMX4(r0,r1,r2,r3,addr) \
    asm volatile("ldmatrix.sync.aligned.m8n8.x4.shared.b16 {%0,%1,%2,%3}, [%4];" \
        : "=r"(r0),"=r"(r1),"=r"(r2),"=r"(r3) : "r"(addr))
#define LDMX4T(r0,r1,r2,r3,addr) \
    asm volatile("ldmatrix.sync.aligned.m8n8.x4.trans.shared.b16 {%0,%1,%2,%3}, [%4];" \
        : "=r"(r0),"=r"(r1),"=r"(r2),"=r"(r3) : "r"(addr))
#define MMA_F16(d, a, b0, b1) \
    asm volatile("mma.sync.aligned.m16n8k16.row.col.f32.f16.f16.f32 " \
        "{%0,%1,%2,%3}, {%4,%5,%6,%7}, {%8,%9}, {%0,%1,%2,%3};" \
        : "+f"((d)[0]),"+f"((d)[1]),"+f"((d)[2]),"+f"((d)[3]) \
        : "r"((a)[0]),"r"((a)[1]),"r"((a)[2]),"r"((a)[3]), "r"(b0),"r"(b1))

#define CPA16(dst, src) \
    asm volatile("cp.async.cg.shared.global [%0], [%1], 16;" :: "r"(dst), "l"(src))
#define CPA16Z(dst, src, sz) \
    asm volatile("cp.async.cg.shared.global [%0], [%1], 16, %2;" :: "r"(dst), "l"(src), "r"(sz))
#define CPCOMMIT() asm volatile("cp.async.commit_group;" ::: "memory")
#define CPWAIT(n)  asm volatile("cp.async.wait_group %0;" :: "n"(n) : "memory")

// ---------------- repack ---------------------------------------------------
__global__ void repack_kernel(const float* __restrict__ x,
                              const float* __restrict__ conv1_w,
                              const float* __restrict__ w_msg,
                              const float* __restrict__ conv2_w,
                              const float* __restrict__ bn1_g, const float* __restrict__ bn1_b,
                              const float* __restrict__ bn1_m, const float* __restrict__ bn1_v,
                              const float* __restrict__ bn2_g, const float* __restrict__ bn2_b,
                              const float* __restrict__ bn2_m, const float* __restrict__ bn2_v,
                              const float* __restrict__ b_msg,
                              const float* __restrict__ w_ih,
                              const float* __restrict__ w_hh) {
    int stride = gridDim.x * blockDim.x;
    int idx = blockIdx.x * blockDim.x + threadIdx.x;
    if (idx < DIM) {
        float sc = bn1_g[idx] * rsqrtf(bn1_v[idx] + 1e-5f);
        g_sc1[idx] = sc;
        g_sh1[idx] = bn1_b[idx] - bn1_m[idx]*sc;
        float sc2 = bn2_g[idx] * rsqrtf(bn2_v[idx] + 1e-5f);
        g_sh2[idx] = bn2_b[idx] - bn2_m[idx]*sc2;
        g_bmsg[idx] = b_msg[idx];
    }
    for (int i = idx; i < 512*256; i += stride) {
        int n = i >> 8, k = i & 255;
        float v = (n < 256) ? conv1_w[n*256 + k] : w_msg[(n-256)*256 + k];
        __half h = __float2half_rn(v);
        g_wfh[i] = h; g_wfl[i] = __float2half_rn(v - __half2float(h));
    }
    for (int i = idx; i < 256*4352; i += stride) {
        int o = i / 4352, kk = i - o*4352;
        int tap = kk >> 8, ic = kk & 255;
        float sc = bn2_g[o] * rsqrtf(bn2_v[o] + 1e-5f);
        float v = conv2_w[(o*256 + ic)*17 + tap] * sc;
        __half h = __float2half_rn(v);
        g_w2h[i] = h; g_w2l[i] = __float2half_rn(v - __half2float(h));
    }
    for (int i = idx; i < 768*512; i += stride) {
        float v = w_ih[i];
        __half h = __float2half_rn(v);
        g_wihh[i] = h; g_wihl[i] = __float2half_rn(v - __half2float(h));
    }
    for (int i = idx; i < 768*256; i += stride) {
        float v = w_hh[i];
        __half h = __float2half_rn(v);
        g_whhh[i] = h; g_whhl[i] = __float2half_rn(v - __half2float(h));
    }
    for (int i = idx; i < NROWS*DIM; i += stride) {
        float v = x[i];
        __half h = __float2half_rn(v);
        g_xh[i] = h; g_xl[i] = __float2half_rn(v - __half2float(h));
    }
}

// == HMMA GEMM template (modes 0,2,3): 256x128 tile, A-split, 3-stage ======
#define PITCH 80
#define A_ARR 20480            // 256 rows * 80
#define B_ARR 10240            // 128 rows * 80
#define SM_AHI(s) ((s)*61440 + 0)
#define SM_ALO(s) ((s)*61440 + A_ARR)
#define SM_BHI(s) ((s)*61440 + 2*A_ARR)
#define SM_BLO(s) ((s)*61440 + 2*A_ARR + B_ARR)
#define GEMM_SMEM 184320

template<int MODE>
__global__ void __launch_bounds__(256, 1) mma_gemm(const float* __restrict__ x) {
    extern __shared__ char smem[];
    const int tid  = threadIdx.x;
    const int wid  = tid >> 5, lane = tid & 31;
    const int warp_m = wid & 3;        // 4 x 64 rows
    const int warp_n = wid >> 2;       // 2 x 64 cols
    const int gid  = lane >> 2, tid4 = lane & 3;
    const uint32_t sb = smem_u32(smem);

    constexpr int KT = (MODE==0) ? 256 : (MODE==2) ? 512 : 256;
    constexpr int NC = KT / 32;
    const int col0 = blockIdx.x * 128;
    const int t0 = blockIdx.y * 256;
    const int row0 = t0;

    const uint32_t aOff = (uint32_t)(lane & 15)*PITCH + (uint32_t)(lane >> 4)*16;
    const uint32_t bOff = (uint32_t)(((lane >> 4) << 3) + (lane & 7))*PITCH
                        + (uint32_t)((lane >> 3) & 1)*16;

    const int r0_ = tid >> 2, u_ = tid & 3;

    float acc[4][8][4] = {};

#define CPA_TILE(c, s) { \
    uint32_t dAh = sb + SM_AHI(s), dAl = sb + SM_ALO(s); \
    uint32_t dBh = sb + SM_BHI(s), dBl = sb + SM_BLO(s); \
    _Pragma("unroll") \
    for (int g = 0; g < 4; g++) { \
        int arow = r0_ + 64*g; \
        uint32_t o = (uint32_t)(arow*PITCH + u_*16); \
        if (MODE == 0 || MODE == 3) { \
            size_t a0 = (size_t)(row0+arow)*256 + (c)*32 + u_*8; \
            CPA16(dAh+o, g_xh+a0); CPA16(dAl+o, g_xl+a0); \
        } else { \
            const __half* sh_ = ((c) < 8) ? g_xch : g_xnh; \
            const __half* sl_ = ((c) < 8) ? g_xcl : g_xnl; \
            int kk_ = ((c) & 7)*32; \
            size_t a0 = (size_t)(row0+arow)*256 + kk_ + u_*8; \
            CPA16(dAh+o, sh_+a0); CPA16(dAl+o, sl_+a0); \
        } \
    } \
    _Pragma("unroll") \
    for (int g = 0; g < 2; g++) { \
        int brow = r0_ + 64*g; \
        uint32_t o = (uint32_t)(brow*PITCH + u_*16); \
        if (MODE == 0) { \
            size_t b0 = (size_t)(col0+brow)*256 + (c)*32 + u_*8; \
            CPA16(dBh+o, g_wfh+b0); CPA16(dBl+o, g_wfl+b0); \
        } else if (MODE == 2) { \
            size_t b0 = (size_t)(col0+brow)*512 + (c)*32 + u_*8; \
            CPA16(dBh+o, g_wihh+b0); CPA16(dBl+o, g_wihl+b0); \
        } else { \
            size_t b0 = (size_t)(col0+brow)*256 + (c)*32 + u_*8; \
            CPA16(dBh+o, g_whhh+b0); CPA16(dBl+o, g_whhl+b0); \
        } \
    } }

#define COMPUTE(s) { \
    _Pragma("unroll") \
    for (int ks = 0; ks < 2; ks++) { \
        uint32_t Ah[4][4], Al[4][4]; \
        _Pragma("unroll") \
        for (int mi = 0; mi < 4; mi++) { \
            uint32_t ad = sb + SM_AHI(s) + (warp_m*64 + mi*16)*PITCH + ks*32 + aOff; \
            LDMX4(Ah[mi][0],Ah[mi][1],Ah[mi][2],Ah[mi][3], ad); \
            ad = sb + SM_ALO(s) + (warp_m*64 + mi*16)*PITCH + ks*32 + aOff; \
            LDMX4(Al[mi][0],Al[mi][1],Al[mi][2],Al[mi][3], ad); \
        } \
        _Pragma("unroll") \
        for (int pj = 0; pj < 4; pj++) { \
            uint32_t Bh[4], Bl[4]; \
            uint32_t bd = sb + SM_BHI(s) + (warp_n*64 + pj*16)*PITCH + ks*32 + bOff; \
            LDMX4(Bh[0],Bh[1],Bh[2],Bh[3], bd); \
            bd = sb + SM_BLO(s) + (warp_n*64 + pj*16)*PITCH + ks*32 + bOff; \
            LDMX4(Bl[0],Bl[1],Bl[2],Bl[3], bd); \
            _Pragma("unroll") \
            for (int mi = 0; mi < 4; mi++) \
                _Pragma("unroll") \
                for (int h = 0; h < 2; h++) { \
                    float* D = acc[mi][pj*2 + h]; \
                    MMA_F16(D, Ah[mi], Bh[h*2], Bh[h*2+1]); \
                    MMA_F16(D, Ah[mi], Bl[h*2], Bl[h*2+1]); \
                    MMA_F16(D, Al[mi], Bh[h*2], Bh[h*2+1]); \
                } \
        } \
    } }

    CPA_TILE(0, 0); CPCOMMIT();
    CPA_TILE(1, 1); CPCOMMIT();
    for (int c = 0; c < NC; c++) {
        if (c + 1 < NC) { CPWAIT(1); } else { CPWAIT(0); }
        __syncthreads();
        if (c + 2 < NC) { CPA_TILE(c+2, (c+2)%3); CPCOMMIT(); }
        COMPUTE(c%3);
    }
#undef CPA_TILE
#undef COMPUTE

    // ---------------- epilogue ----------------
    #pragma unroll
    for (int mi = 0; mi < 4; mi++) {
        #pragma unroll
        for (int nj = 0; nj < 8; nj++) {
            int c = col0 + warp_n*64 + nj*8 + tid4*2;
            size_t r1 = (size_t)row0 + warp_m*64 + mi*16 + gid;
            size_t r2 = r1 + 8;
            float v00 = acc[mi][nj][0], v01 = acc[mi][nj][1];
            float v10 = acc[mi][nj][2], v11 = acc[mi][nj][3];
            if (MODE == 0) {
                if (col0 < 256) {
                    float sc0 = g_sc1[c], sc1 = g_sc1[c+1];
                    float sh0 = g_sh1[c], sh1 = g_sh1[c+1];
                    *(uint32_t*)&g_h1s[r1*256 + c] =
                        pkh(fmaxf(v00*sc0+sh0,0.f), fmaxf(v01*sc1+sh1,0.f));
                    *(uint32_t*)&g_h1s[r2*256 + c] =
                        pkh(fmaxf(v10*sc0+sh0,0.f), fmaxf(v11*sc1+sh1,0.f));
                } else {
                    int cc = c - 256;
                    float b0 = g_bmsg[cc], b1 = g_bmsg[cc+1];
                    *(uint32_t*)&g_msg[r1*256 + cc] = pkh(fmaxf(v00+b0,0.f), fmaxf(v01+b1,0.f));
                    *(uint32_t*)&g_msg[r2*256 + cc] = pkh(fmaxf(v10+b0,0.f), fmaxf(v11+b1,0.f));
                }
            } else if (MODE == 2) {
                *(uint32_t*)&g_gi[r1*768 + c] = pkh(v00, v01);
                *(uint32_t*)&g_gi[r2*768 + c] = pkh(v10, v11);
            } else {
                *(uint32_t*)&g_gh[r1*768 + c] = pkh(v00, v01);
                *(uint32_t*)&g_gh[r2*768 + c] = pkh(v10, v11);
            }
        }
    }
}

// == conv2: 128x128 tile, A-single (h1s) x B-split, 3-stage, 2 CTAs/SM =====
#define C2_STAGE 30720         // A 10240 + Bh 10240 + Bl 10240
#define C2_A(s)   ((s)*C2_STAGE)
#define C2_BH(s)  ((s)*C2_STAGE + 10240)
#define C2_BL(s)  ((s)*C2_STAGE + 20480)
#define C2_SMEM   92160

__global__ void __launch_bounds__(256, 2) conv2_kernel(const float* __restrict__ x) {
    extern __shared__ char smem[];
    const int tid  = threadIdx.x;
    const int wid  = tid >> 5, lane = tid & 31;
    const int warp_m = wid & 1;        // 2 x 64 rows
    const int warp_n = wid >> 1;       // 4 x 32 cols
    const int gid  = lane >> 2, tid4 = lane & 3;
    const uint32_t sb = smem_u32(smem);

    constexpr int NC = 4352 / 32;      // 136
    const int col0 = blockIdx.x * 128;
    const int bz = blockIdx.z;
    const int t0 = blockIdx.y * 128;
    const size_t row0 = (size_t)bz*NSEQ + t0;

    const uint32_t aOff = (uint32_t)(lane & 15)*PITCH + (uint32_t)(lane >> 4)*16;
    const uint32_t bOff = (uint32_t)(((lane >> 4) << 3) + (lane & 7))*PITCH
                        + (uint32_t)((lane >> 3) & 1)*16;

    float acc[4][4][4] = {};

#define C2_CPA(c, s) { \
    uint32_t dA = sb + C2_A(s), dBh = sb + C2_BH(s), dBl = sb + C2_BL(s); \
    int tap = (c) >> 3, kloc = ((c) & 7)*32; \
    _Pragma("unroll") \
    for (int g = 0; g < 2; g++) { \
        int idx = tid + 256*g; \
        int r = idx >> 2, u = idx & 3; \
        uint32_t o = (uint32_t)(r*PITCH + u*16); \
        int t1 = t0 + r + tap - 8; \
        uint32_t z1 = ((unsigned)t1 < (unsigned)NSEQ) ? 16u : 0u; \
        int tc1 = min(max(t1, 0), NSEQ-1); \
        size_t a0 = ((size_t)bz*NSEQ + tc1)*256 + kloc + u*8; \
        CPA16Z(dA+o, g_h1s+a0, z1); \
        size_t b0 = (size_t)(col0+r)*4352 + (c)*32 + u*8; \
        CPA16(dBh+o, g_w2h+b0); CPA16(dBl+o, g_w2l+b0); \
    } }

#define C2_COMPUTE(s) { \
    _Pragma("unroll") \
    for (int ks = 0; ks < 2; ks++) { \
        uint32_t Ah[4][4]; \
        _Pragma("unroll") \
        for (int mi = 0; mi < 4; mi++) { \
            uint32_t ad = sb + C2_A(s) + (warp_m*64 + mi*16)*PITCH + ks*32 + aOff; \
            LDMX4(Ah[mi][0],Ah[mi][1],Ah[mi][2],Ah[mi][3], ad); \
        } \
        _Pragma("unroll") \
        for (int pj = 0; pj < 2; pj++) { \
            uint32_t Bh[4], Bl[4]; \
            uint32_t bd = sb + C2_BH(s) + (warp_n*32 + pj*16)*PITCH + ks*32 + bOff; \
            LDMX4(Bh[0],Bh[1],Bh[2],Bh[3], bd); \
            bd = sb + C2_BL(s) + (warp_n*32 + pj*16)*PITCH + ks*32 + bOff; \
            LDMX4(Bl[0],Bl[1],Bl[2],Bl[3], bd); \
            _Pragma("unroll") \
            for (int mi = 0; mi < 4; mi++) \
                _Pragma("unroll") \
                for (int h = 0; h < 2; h++) { \
                    float* D = acc[mi][pj*2 + h]; \
                    MMA_F16(D, Ah[mi], Bh[h*2], Bh[h*2+1]); \
                    MMA_F16(D, Ah[mi], Bl[h*2], Bl[h*2+1]); \
                } \
        } \
    } }

    C2_CPA(0, 0); CPCOMMIT();
    C2_CPA(1, 1); CPCOMMIT();
    for (int c = 0; c < NC; c++) {
        if (c + 1 < NC) { CPWAIT(1); } else { CPWAIT(0); }
        __syncthreads();
        if (c + 2 < NC) { C2_CPA(c+2, (c+2)%3); CPCOMMIT(); }
        C2_COMPUTE(c%3);
    }
#undef C2_CPA
#undef C2_COMPUTE

    #pragma unroll
    for (int mi = 0; mi < 4; mi++) {
        #pragma unroll
        for (int nj = 0; nj < 4; nj++) {
            int c = col0 + warp_n*32 + nj*8 + tid4*2;
            size_t r1 = row0 + warp_m*64 + mi*16 + gid;
            size_t r2 = r1 + 8;
            float sh0 = g_sh2[c], sh1 = g_sh2[c+1];
            uint32_t lo, hi;
            float a0 = fmaxf(acc[mi][nj][0] + sh0 + x[r1*256+c],   0.f);
            float a1 = fmaxf(acc[mi][nj][1] + sh1 + x[r1*256+c+1], 0.f);
            hi = pksplit_h(a0, a1, lo);
            *(uint32_t*)&g_xch[r1*256 + c] = hi; *(uint32_t*)&g_xcl[r1*256 + c] = lo;
            a0 = fmaxf(acc[mi][nj][2] + sh0 + x[r2*256+c],   0.f);
            a1 = fmaxf(acc[mi][nj][3] + sh1 + x[r2*256+c+1], 0.f);
            hi = pksplit_h(a0, a1, lo);
            *(uint32_t*)&g_xch[r2*256 + c] = hi; *(uint32_t*)&g_xcl[r2*256 + c] = lo;
        }
    }
}

// ---------------- s projection -> (u, q') and (s, q') ---------------------
__global__ void skernel(const float* __restrict__ x,
                        const float* __restrict__ w_se,
                        const float* __restrict__ b_se) {
    int row = blockIdx.x * 8 + (threadIdx.x >> 5);
    int lane = threadIdx.x & 31;
    float p0=0.f, p1=0.f, p2=0.f;
    for (int k = lane; k < DIM; k += 32) {
        float xv = x[(size_t)row*DIM + k];
        p0 += xv * w_se[k];
        p1 += xv * w_se[DIM + k];
        p2 += xv * w_se[2*DIM + k];
    }
    #pragma unroll
    for (int off = 16; off > 0; off >>= 1) {
        p0 += __shfl_down_sync(0xffffffffu, p0, off);
        p1 += __shfl_down_sync(0xffffffffu, p1, off);
        p2 += __shfl_down_sync(0xffffffffu, p2, off);
    }
    if (lane == 0) {
        const float L2E = 1.4426950408889634f;
        p0 += b_se[0]; p1 += b_se[1]; p2 += b_se[2];
        float sq = p0*p0 + p1*p1 + p2*p2;
        float qp = -L2E * sq;
        g_s2[row*8+0] = 2.0f*L2E*p0;
        g_s2[row*8+1] = 2.0f*L2E*p1;
        g_s2[row*8+2] = 2.0f*L2E*p2;
        g_s2[row*8+3] = qp;
        g_s2[row*8+4] = p0;
        g_s2[row*8+5] = p1;
        g_s2[row*8+6] = p2;
        g_s2[row*8+7] = qp;
    }
}

// ---------------- tensorized NMP: fp32 t, f16x2 ex2, 1-MMA ---------------
#define NWP  80
#define NWH(s)  ((s)*5120)             // W bufs: 0, 5120
#define NMPITCH 528
#define NMH(s) (10240 + (s)*16896)     // msg stages: 10240, 27136
#define NSMF(s) (44032 + (s)*512)      // sSm float bufs (4*32 floats)
#define NMP_SMEM 45056

__global__ void __launch_bounds__(256, 2) nmp_kernel(const float* __restrict__ mask) {
    extern __shared__ char smem[];
    const uint32_t sb = smem_u32(smem);
    const int b  = blockIdx.y;
    const int n0 = blockIdx.x * 64;
    const int tid = threadIdx.x;
    const int wid = tid >> 5, lane = tid & 31;
    const int warp_n = wid & 1, warp_d = wid >> 1;
    const int gid = lane >> 2, tid4 = lane & 3;

    const uint32_t aOff  = (uint32_t)(lane & 15)*NWP + (uint32_t)(lane >> 4)*16;
    const uint32_t bOffT = (uint32_t)(lane & 15)*NMPITCH + (uint32_t)(lane >> 4)*16;

    const size_t mbase = ((size_t)b*NSEQ + n0) * NSEQ;
    const int rr = tid >> 2, mm0 = (tid & 3)*8;

    float u0i, u1i, u2i, qi;
    {
        const float* sp = &g_s2[((size_t)b*NSEQ + n0 + rr)*8];
        u0i = sp[0]; u1i = sp[1]; u2i = sp[2]; qi = sp[3];
    }

    const int mrow = tid >> 5;
    const int mu   = tid & 31;

#define NMP_PREFETCH(c, s) { \
    uint32_t dh = sb + NMH(s); \
    const __half* srch = g_msg + ((size_t)b*NSEQ + (c)*32)*256; \
    _Pragma("unroll") \
    for (int q = 0; q < 4; q++) { \
        int row = mrow + q*8; \
        CPA16(dh + (uint32_t)row*NMPITCH + (uint32_t)mu*16, srch + (size_t)row*256 + mu*8); \
    } }

#define SSM_STORE(c, s) { \
    if (tid < 128) { \
        int j = tid >> 2, comp = tid & 3; \
        ((float*)(smem + NSMF(s)))[comp*32 + j] = \
            g_s2[((size_t)b*NSEQ + (c)*32 + j)*8 + 4 + comp]; \
    } }

    SSM_STORE(0, 0);
    NMP_PREFETCH(0, 0); CPCOMMIT();

    float acc[2][8][4] = {};
    constexpr int NCn = NSEQ/32;

    for (int c = 0; c < NCn; c++) {
        int s = c & 1;
        __syncthreads();   // ends MMA(c-1); publishes sSm(c)
        if (c+1 < NCn) SSM_STORE(c+1, 1-s);
        {   // compute W(c): t in fp32, ex2 in f16x2
            const float* sSmF = (const float*)(smem + NSMF(s));
            const float* mrow_p = &mask[mbase + (size_t)rr*NSEQ + c*32 + mm0];
            float4 mk0 = *(const float4*)mrow_p;
            float4 mk1 = *(const float4*)(mrow_p + 4);
            uint32_t wv[4];
            #pragma unroll
            for (int p = 0; p < 4; p++) {
                int mm = mm0 + 2*p;
                float ta = fmaf(u0i, sSmF[mm],
                           fmaf(u1i, sSmF[32+mm],
                           fmaf(u2i, sSmF[64+mm], sSmF[96+mm] + qi)));
                float tb = fmaf(u0i, sSmF[mm+1],
                           fmaf(u1i, sSmF[32+mm+1],
                           fmaf(u2i, sSmF[64+mm+1], sSmF[96+mm+1] + qi)));
                __half2 t2 = __floats2half2_rn(ta, tb);
                uint32_t e2;
                asm("ex2.approx.f16x2 %0, %1;" : "=r"(e2) : "r"(*(uint32_t*)&t2));
                float mka = (p < 2) ? ((p == 0) ? mk0.x : mk0.z) : ((p == 2) ? mk1.x : mk1.z);
                float mkb = (p < 2) ? ((p == 0) ? mk0.y : mk0.w) : ((p == 2) ? mk1.y : mk1.w);
                __half2 mh = __floats2half2_rn(mka, mkb);
                __half2 w2 = __hmul2(*(__half2*)&e2, mh);
                wv[p] = *(uint32_t*)&w2;
            }
            *(uint4*)(smem + NWH(s) + rr*NWP + mm0*2) = make_uint4(wv[0],wv[1],wv[2],wv[3]);
        }
        if (c+1 < NCn) { NMP_PREFETCH(c+1, 1-s); CPCOMMIT(); CPWAIT(1); }
        else           { CPWAIT(0); }
        __syncthreads();   // W(c), msg(c) ready
        #pragma unroll
        for (int ks = 0; ks < 2; ks++) {
            uint32_t Aw[2][4], Bm[4][4];
            #pragma unroll
            for (int mi = 0; mi < 2; mi++) {
                uint32_t ad = sb + NWH(s) + (warp_n*32 + mi*16)*NWP + ks*32 + aOff;
                LDMX4(Aw[mi][0],Aw[mi][1],Aw[mi][2],Aw[mi][3], ad);
            }
            #pragma unroll
            for (int dj = 0; dj < 4; dj++) {
                uint32_t bd = sb + NMH(s) + (ks*16)*NMPITCH + (warp_d*64 + dj*16)*2 + bOffT;
                LDMX4T(Bm[dj][0],Bm[dj][1],Bm[dj][2],Bm[dj][3], bd);
            }
            #pragma unroll
            for (int mi = 0; mi < 2; mi++)
                #pragma unroll
                for (int dj = 0; dj < 4; dj++)
                    #pragma unroll
                    for (int h = 0; h < 2; h++)
                        MMA_F16(acc[mi][dj*2 + h], Aw[mi], Bm[dj][h*2], Bm[dj][h*2+1]);
        }
    }
#undef NMP_PREFETCH
#undef SSM_STORE

    #pragma unroll
    for (int mi = 0; mi < 2; mi++) {
        #pragma unroll
        for (int dj8 = 0; dj8 < 8; dj8++) {
            int d = warp_d*64 + dj8*8 + tid4*2;
            size_t r1 = (size_t)b*NSEQ + n0 + warp_n*32 + mi*16 + gid;
            size_t r2 = r1 + 8;
            uint32_t lo, hi;
            hi = pksplit_h(acc[mi][dj8][0], acc[mi][dj8][1], lo);
            *(uint32_t*)&g_xnh[r1*256 + d] = hi; *(uint32_t*)&g_xnl[r1*256 + d] = lo;
            hi = pksplit_h(acc[mi][dj8][2], acc[mi][dj8][3], lo);
            *(uint32_t*)&g_xnh[r2*256 + d] = hi; *(uint32_t*)&g_xnl[r2*256 + d] = lo;
        }
    }
}

// ---------------- gate epilogue (fp16 gi/gh) ------------------------------
__global__ void gate_kernel(const float* __restrict__ x,
                            const float* __restrict__ b_ih,
                            const float* __restrict__ b_hh,
                            float* __restrict__ out) {
    int idx = blockIdx.x * blockDim.x + threadIdx.x;
    size_t r = idx >> 6;
    int c = (idx & 63) * 4;
    const __half* gi = &g_gi[r*768];
    const __half* gh = &g_gh[r*768];
    float4 xv  = *(const float4*)&x[r*DIM + c];
    float o4[4];
    #pragma unroll
    for (int p = 0; p < 2; p++) {
        int cc = c + 2*p;
        float2 gir = __half22float2(*(__half2*)&gi[cc]);
        float2 giz = __half22float2(*(__half2*)&gi[256 + cc]);
        float2 gin = __half22float2(*(__half2*)&gi[512 + cc]);
        float2 ghr = __half22float2(*(__half2*)&gh[cc]);
        float2 ghz = __half22float2(*(__half2*)&gh[256 + cc]);
        float2 ghn = __half22float2(*(__half2*)&gh[512 + cc]);
        #pragma unroll
        for (int q = 0; q < 2; q++) {
            int cq = cc + q;
            float air = ((q==0)?gir.x:gir.y) + b_ih[cq]     + ((q==0)?ghr.x:ghr.y) + b_hh[cq];
            float aiz = ((q==0)?giz.x:giz.y) + b_ih[256+cq] + ((q==0)?ghz.x:ghz.y) + b_hh[256+cq];
            float rv = 1.0f/(1.0f + __expf(-air));
            float zv = 1.0f/(1.0f + __expf(-aiz));
            float nv = tanhf(((q==0)?gin.x:gin.y) + b_ih[512+cq]
                           + rv*(((q==0)?ghn.x:ghn.y) + b_hh[512+cq]));
            o4[2*p+q] = (1.0f - zv)*nv + zv*(&xv.x)[2*p+q];
        }
    }
    *(float4*)&out[r*DIM + c] = make_float4(o4[0], o4[1], o4[2], o4[3]);
}

// ---------------- launch --------------------------------------------------
extern "C" void kernel_launch(void* const* d_in, const int* in_sizes, int n_in,
                              void* d_out, int out_size) {
    const float* x       = (const float*)d_in[0];
    const float* mask    = (const float*)d_in[1];
    const float* w_se    = (const float*)d_in[2];
    const float* b_se    = (const float*)d_in[3];
    const float* conv1_w = (const float*)d_in[4];
    const float* bn1_g   = (const float*)d_in[5];
    const float* bn1_b   = (const float*)d_in[6];
    const float* bn1_m   = (const float*)d_in[7];
    const float* bn1_v   = (const float*)d_in[8];
    const float* conv2_w = (const float*)d_in[9];
    const float* bn2_g   = (const float*)d_in[10];
    const float* bn2_b   = (const float*)d_in[11];
    const float* bn2_m   = (const float*)d_in[12];
    const float* bn2_v   = (const float*)d_in[13];
    const float* w_msg   = (const float*)d_in[14];
    const float* b_msg   = (const float*)d_in[15];
    const float* w_ih    = (const float*)d_in[16];
    const float* b_ih    = (const float*)d_in[17];
    const float* w_hh    = (const float*)d_in[18];
    const float* b_hh    = (const float*)d_in[19];
    float* out = (float*)d_out;

    cudaFuncSetAttribute(mma_gemm<0>, cudaFuncAttributeMaxDynamicSharedMemorySize, GEMM_SMEM);
    cudaFuncSetAttribute(mma_gemm<2>, cudaFuncAttributeMaxDynamicSharedMemorySize, GEMM_SMEM);
    cudaFuncSetAttribute(mma_gemm<3>, cudaFuncAttributeMaxDynamicSharedMemorySize, GEMM_SMEM);
    cudaFuncSetAttribute(conv2_kernel, cudaFuncAttributeMaxDynamicSharedMemorySize, C2_SMEM);
    cudaFuncSetAttribute(nmp_kernel,  cudaFuncAttributeMaxDynamicSharedMemorySize, NMP_SMEM);

    repack_kernel<<<1024, 256>>>(x, conv1_w, w_msg, conv2_w,
                                 bn1_g, bn1_b, bn1_m, bn1_v,
                                 bn2_g, bn2_b, bn2_m, bn2_v,
                                 b_msg, w_ih, w_hh);

    mma_gemm<0><<<dim3(4, NROWS/256), 256, GEMM_SMEM>>>(x);      // front: h1 + msg

    skernel<<<NROWS/8, 256>>>(x, w_se, b_se);

    conv2_kernel<<<dim3(2, NSEQ/128, BS), 256, C2_SMEM>>>(x);    // conv2 -> xc split

    nmp_kernel<<<dim3(NSEQ/64, BS), 256, NMP_SMEM>>>(mask);      // -> xn split

    mma_gemm<2><<<dim3(6, NROWS/256), 256, GEMM_SMEM>>>(x);      // gi
    mma_gemm<3><<<dim3(6, NROWS/256), 256, GEMM_SMEM>>>(x);      // gh

    gate_kernel<<<NROWS*64/256, 256>>>(x, b_ih, b_hh, out);
}

// round 14
// speedup vs baseline: 4.2998x; 1.1953x over previous
#include <cuda_runtime.h>
#include <cuda_fp16.h>
#include <math.h>
#include <stdint.h>

#define BS   16
#define NSEQ 2048
#define DIM  256
#define NROWS (BS*NSEQ)   // 32768

// ---------------- scratch (device globals) --------------------------------
__device__ float g_s2[NROWS*8];          // [u0,u1,u2,q'] [s0,s1,s2,q']
__device__ __half g_gi[(size_t)NROWS*768];
__device__ __half g_gh[(size_t)NROWS*768];

// fp16 activations
__device__ __half g_xh[NROWS*DIM],  g_xl[NROWS*DIM];     // x split
__device__ __half g_h1s[NROWS*DIM];                      // h1 SINGLE fp16
__device__ __half g_xch[NROWS*DIM], g_xcl[NROWS*DIM];    // xconv split
__device__ __half g_xnh[NROWS*DIM], g_xnl[NROWS*DIM];    // xnmp split
__device__ __half g_msg[NROWS*DIM];                      // single fp16 (positive)

// weights: w2 SINGLE; others hi/lo split ([out][in], K-major)
__device__ __half g_wfh[512*256],  g_wfl[512*256];
__device__ __half g_w2[256*4352];
__device__ __half g_wihh[768*512], g_wihl[768*512];
__device__ __half g_whhh[768*256], g_whhl[768*256];

// bn constants
__device__ float g_sc1[DIM], g_sh1[DIM], g_sh2[DIM], g_bmsg[DIM];

// ---------------- helpers --------------------------------------------------
__device__ __forceinline__ uint32_t smem_u32(const void* p) {
    uint32_t a;
    asm("{ .reg .u64 t; cvta.to.shared.u64 t, %1; cvt.u32.u64 %0, t; }"
        : "=r"(a) : "l"(p));
    return a;
}
__device__ __forceinline__ uint32_t pkh(float a, float b) {
    __half2 h = __floats2half2_rn(a, b);
    return *(uint32_t*)&h;
}
__device__ __forceinline__ uint32_t pksplit_h(float a, float b, uint32_t& lo) {
    __half ha = __float2half_rn(a), hb = __float2half_rn(b);
    lo = pkh(a - __half2float(ha), b - __half2float(hb));
    __half2 h2; h2.x = ha; h2.y = hb;
    return *(uint32_t*)&h2;
}

#define LDMX4(r0,r1,r2,r3,addr) \
    asm volatile("ldmatrix.sync.aligned.m8n8.x4.shared.b16 {%0,%1,%2,%3}, [%4];" \
        : "=r"(r0),"=r"(r1),"=r"(r2),"=r"(r3) : "r"(addr))
#define LDMX4T(r0,r1,r2,r3,addr) \
    asm volatile("ldmatrix.sync.aligned.m8n8.x4.trans.shared.b16 {%0,%1,%2,%3}, [%4];" \
        : "=r"(r0),"=r"(r1),"=r"(r2),"=r"(r3) : "r"(addr))
#define MMA_F16(d, a, b0, b1) \
    asm volatile("mma.sync.aligned.m16n8k16.row.col.f32.f16.f16.f32 " \
        "{%0,%1,%2,%3}, {%4,%5,%6,%7}, {%8,%9}, {%0,%1,%2,%3};" \
        : "+f"((d)[0]),"+f"((d)[1]),"+f"((d)[2]),"+f"((d)[3]) \
        : "r"((a)[0]),"r"((a)[1]),"r"((a)[2]),"r"((a)[3]), "r"(b0),"r"(b1))

#define CPA16(dst, src) \
    asm volatile("cp.async.cg.shared.global [%0], [%1], 16;" :: "r"(dst), "l"(src))
#define CPA16Z(dst, src, sz) \
    asm volatile("cp.async.cg.shared.global [%0], [%1], 16, %2;" :: "r"(dst), "l"(src), "r"(sz))
#define CPCOMMIT() asm volatile("cp.async.commit_group;" ::: "memory")
#define CPWAIT(n)  asm volatile("cp.async.wait_group %0;" :: "n"(n) : "memory")

// ---------------- repack ---------------------------------------------------
__global__ void repack_kernel(const float* __restrict__ x,
                              const float* __restrict__ conv1_w,
                              const float* __restrict__ w_msg,
                              const float* __restrict__ conv2_w,
                              const float* __restrict__ bn1_g, const float* __restrict__ bn1_b,
                              const float* __restrict__ bn1_m, const float* __restrict__ bn1_v,
                              const float* __restrict__ bn2_g, const float* __restrict__ bn2_b,
                              const float* __restrict__ bn2_m, const float* __restrict__ bn2_v,
                              const float* __restrict__ b_msg,
                              const float* __restrict__ w_ih,
                              const float* __restrict__ w_hh) {
    int stride = gridDim.x * blockDim.x;
    int idx = blockIdx.x * blockDim.x + threadIdx.x;
    if (idx < DIM) {
        float sc = bn1_g[idx] * rsqrtf(bn1_v[idx] + 1e-5f);
        g_sc1[idx] = sc;
        g_sh1[idx] = bn1_b[idx] - bn1_m[idx]*sc;
        float sc2 = bn2_g[idx] * rsqrtf(bn2_v[idx] + 1e-5f);
        g_sh2[idx] = bn2_b[idx] - bn2_m[idx]*sc2;
        g_bmsg[idx] = b_msg[idx];
    }
    for (int i = idx; i < 512*256; i += stride) {
        int n = i >> 8, k = i & 255;
        float v = (n < 256) ? conv1_w[n*256 + k] : w_msg[(n-256)*256 + k];
        __half h = __float2half_rn(v);
        g_wfh[i] = h; g_wfl[i] = __float2half_rn(v - __half2float(h));
    }
    for (int i = idx; i < 256*4352; i += stride) {
        int o = i / 4352, kk = i - o*4352;
        int tap = kk >> 8, ic = kk & 255;
        float sc = bn2_g[o] * rsqrtf(bn2_v[o] + 1e-5f);
        g_w2[i] = __float2half_rn(conv2_w[(o*256 + ic)*17 + tap] * sc);
    }
    for (int i = idx; i < 768*512; i += stride) {
        float v = w_ih[i];
        __half h = __float2half_rn(v);
        g_wihh[i] = h; g_wihl[i] = __float2half_rn(v - __half2float(h));
    }
    for (int i = idx; i < 768*256; i += stride) {
        float v = w_hh[i];
        __half h = __float2half_rn(v);
        g_whhh[i] = h; g_whhl[i] = __float2half_rn(v - __half2float(h));
    }
    for (int i = idx; i < NROWS*DIM; i += stride) {
        float v = x[i];
        __half h = __float2half_rn(v);
        g_xh[i] = h; g_xl[i] = __float2half_rn(v - __half2float(h));
    }
}

// == GEMM template (modes 0,2,3): 256x128 tile, A-split x B-split, 3-stage =
#define PITCH 80
#define A_ARR 20480            // 256 rows * 80
#define B_ARR 10240            // 128 rows * 80
#define SM_AHI(s) ((s)*61440 + 0)
#define SM_ALO(s) ((s)*61440 + A_ARR)
#define SM_BHI(s) ((s)*61440 + 2*A_ARR)
#define SM_BLO(s) ((s)*61440 + 2*A_ARR + B_ARR)
#define GEMM_SMEM 184320

template<int MODE>
__global__ void __launch_bounds__(256, 1) mma_gemm(const float* __restrict__ x) {
    extern __shared__ char smem[];
    const int tid  = threadIdx.x;
    const int wid  = tid >> 5, lane = tid & 31;
    const int warp_m = wid & 3;        // 4 x 64 rows
    const int warp_n = wid >> 2;       // 2 x 64 cols
    const int gid  = lane >> 2, tid4 = lane & 3;
    const uint32_t sb = smem_u32(smem);

    constexpr int KT = (MODE==0) ? 256 : (MODE==2) ? 512 : 256;
    constexpr int NC = KT / 32;
    const int col0 = blockIdx.x * 128;
    const int t0 = blockIdx.y * 256;
    const int row0 = t0;

    const uint32_t aOff = (uint32_t)(lane & 15)*PITCH + (uint32_t)(lane >> 4)*16;
    const uint32_t bOff = (uint32_t)(((lane >> 4) << 3) + (lane & 7))*PITCH
                        + (uint32_t)((lane >> 3) & 1)*16;

    const int r0_ = tid >> 2, u_ = tid & 3;

    float acc[4][8][4] = {};

#define CPA_TILE(c, s) { \
    uint32_t dAh = sb + SM_AHI(s), dAl = sb + SM_ALO(s); \
    uint32_t dBh = sb + SM_BHI(s), dBl = sb + SM_BLO(s); \
    _Pragma("unroll") \
    for (int g = 0; g < 4; g++) { \
        int arow = r0_ + 64*g; \
        uint32_t o = (uint32_t)(arow*PITCH + u_*16); \
        if (MODE == 0 || MODE == 3) { \
            size_t a0 = (size_t)(row0+arow)*256 + (c)*32 + u_*8; \
            CPA16(dAh+o, g_xh+a0); CPA16(dAl+o, g_xl+a0); \
        } else { \
            const __half* sh_ = ((c) < 8) ? g_xch : g_xnh; \
            const __half* sl_ = ((c) < 8) ? g_xcl : g_xnl; \
            int kk_ = ((c) & 7)*32; \
            size_t a0 = (size_t)(row0+arow)*256 + kk_ + u_*8; \
            CPA16(dAh+o, sh_+a0); CPA16(dAl+o, sl_+a0); \
        } \
    } \
    _Pragma("unroll") \
    for (int g = 0; g < 2; g++) { \
        int brow = r0_ + 64*g; \
        uint32_t o = (uint32_t)(brow*PITCH + u_*16); \
        if (MODE == 0) { \
            size_t b0 = (size_t)(col0+brow)*256 + (c)*32 + u_*8; \
            CPA16(dBh+o, g_wfh+b0); CPA16(dBl+o, g_wfl+b0); \
        } else if (MODE == 2) { \
            size_t b0 = (size_t)(col0+brow)*512 + (c)*32 + u_*8; \
            CPA16(dBh+o, g_wihh+b0); CPA16(dBl+o, g_wihl+b0); \
        } else { \
            size_t b0 = (size_t)(col0+brow)*256 + (c)*32 + u_*8; \
            CPA16(dBh+o, g_whhh+b0); CPA16(dBl+o, g_whhl+b0); \
        } \
    } }

#define COMPUTE(s) { \
    _Pragma("unroll") \
    for (int ks = 0; ks < 2; ks++) { \
        uint32_t Ah[4][4], Al[4][4]; \
        _Pragma("unroll") \
        for (int mi = 0; mi < 4; mi++) { \
            uint32_t ad = sb + SM_AHI(s) + (warp_m*64 + mi*16)*PITCH + ks*32 + aOff; \
            LDMX4(Ah[mi][0],Ah[mi][1],Ah[mi][2],Ah[mi][3], ad); \
            ad = sb + SM_ALO(s) + (warp_m*64 + mi*16)*PITCH + ks*32 + aOff; \
            LDMX4(Al[mi][0],Al[mi][1],Al[mi][2],Al[mi][3], ad); \
        } \
        _Pragma("unroll") \
        for (int pj = 0; pj < 4; pj++) { \
            uint32_t Bh[4], Bl[4]; \
            uint32_t bd = sb + SM_BHI(s) + (warp_n*64 + pj*16)*PITCH + ks*32 + bOff; \
            LDMX4(Bh[0],Bh[1],Bh[2],Bh[3], bd); \
            bd = sb + SM_BLO(s) + (warp_n*64 + pj*16)*PITCH + ks*32 + bOff; \
            LDMX4(Bl[0],Bl[1],Bl[2],Bl[3], bd); \
            _Pragma("unroll") \
            for (int mi = 0; mi < 4; mi++) \
                _Pragma("unroll") \
                for (int h = 0; h < 2; h++) { \
                    float* D = acc[mi][pj*2 + h]; \
                    MMA_F16(D, Ah[mi], Bh[h*2], Bh[h*2+1]); \
                    MMA_F16(D, Ah[mi], Bl[h*2], Bl[h*2+1]); \
                    MMA_F16(D, Al[mi], Bh[h*2], Bh[h*2+1]); \
                } \
        } \
    } }

    CPA_TILE(0, 0); CPCOMMIT();
    CPA_TILE(1, 1); CPCOMMIT();
    for (int c = 0; c < NC; c++) {
        if (c + 1 < NC) { CPWAIT(1); } else { CPWAIT(0); }
        __syncthreads();
        if (c + 2 < NC) { CPA_TILE(c+2, (c+2)%3); CPCOMMIT(); }
        COMPUTE(c%3);
    }
#undef CPA_TILE
#undef COMPUTE

    // ---------------- epilogue ----------------
    #pragma unroll
    for (int mi = 0; mi < 4; mi++) {
        #pragma unroll
        for (int nj = 0; nj < 8; nj++) {
            int c = col0 + warp_n*64 + nj*8 + tid4*2;
            size_t r1 = (size_t)row0 + warp_m*64 + mi*16 + gid;
            size_t r2 = r1 + 8;
            float v00 = acc[mi][nj][0], v01 = acc[mi][nj][1];
            float v10 = acc[mi][nj][2], v11 = acc[mi][nj][3];
            if (MODE == 0) {
                if (col0 < 256) {
                    float sc0 = g_sc1[c], sc1 = g_sc1[c+1];
                    float sh0 = g_sh1[c], sh1 = g_sh1[c+1];
                    *(uint32_t*)&g_h1s[r1*256 + c] =
                        pkh(fmaxf(v00*sc0+sh0,0.f), fmaxf(v01*sc1+sh1,0.f));
                    *(uint32_t*)&g_h1s[r2*256 + c] =
                        pkh(fmaxf(v10*sc0+sh0,0.f), fmaxf(v11*sc1+sh1,0.f));
                } else {
                    int cc = c - 256;
                    float b0 = g_bmsg[cc], b1 = g_bmsg[cc+1];
                    *(uint32_t*)&g_msg[r1*256 + cc] = pkh(fmaxf(v00+b0,0.f), fmaxf(v01+b1,0.f));
                    *(uint32_t*)&g_msg[r2*256 + cc] = pkh(fmaxf(v10+b0,0.f), fmaxf(v11+b1,0.f));
                }
            } else if (MODE == 2) {
                *(uint32_t*)&g_gi[r1*768 + c] = pkh(v00, v01);
                *(uint32_t*)&g_gi[r2*768 + c] = pkh(v10, v11);
            } else {
                *(uint32_t*)&g_gh[r1*768 + c] = pkh(v00, v01);
                *(uint32_t*)&g_gh[r2*768 + c] = pkh(v10, v11);
            }
        }
    }
}

// == conv2: 128x128 tile, A-single x B-single (1 MMA), 4-stage, 2 CTAs/SM ==
#define C2_STAGE 20480         // A 10240 + B 10240
#define C2_A(s)   ((s)*C2_STAGE)
#define C2_B(s)   ((s)*C2_STAGE + 10240)
#define C2_SMEM   81920

__global__ void __launch_bounds__(256, 2) conv2_kernel(const float* __restrict__ x) {
    extern __shared__ char smem[];
    const int tid  = threadIdx.x;
    const int wid  = tid >> 5, lane = tid & 31;
    const int warp_m = wid & 1;        // 2 x 64 rows
    const int warp_n = wid >> 1;       // 4 x 32 cols
    const int gid  = lane >> 2, tid4 = lane & 3;
    const uint32_t sb = smem_u32(smem);

    constexpr int NC = 4352 / 32;      // 136
    const int col0 = blockIdx.x * 128;
    const int bz = blockIdx.z;
    const int t0 = blockIdx.y * 128;
    const size_t row0 = (size_t)bz*NSEQ + t0;

    const uint32_t aOff = (uint32_t)(lane & 15)*PITCH + (uint32_t)(lane >> 4)*16;
    const uint32_t bOff = (uint32_t)(((lane >> 4) << 3) + (lane & 7))*PITCH
                        + (uint32_t)((lane >> 3) & 1)*16;

    float acc[4][4][4] = {};

#define C2_CPA(c, s) { \
    uint32_t dA = sb + C2_A(s), dB = sb + C2_B(s); \
    int tap = (c) >> 3, kloc = ((c) & 7)*32; \
    _Pragma("unroll") \
    for (int g = 0; g < 2; g++) { \
        int idx = tid + 256*g; \
        int r = idx >> 2, u = idx & 3; \
        uint32_t o = (uint32_t)(r*PITCH + u*16); \
        int t1 = t0 + r + tap - 8; \
        uint32_t z1 = ((unsigned)t1 < (unsigned)NSEQ) ? 16u : 0u; \
        int tc1 = min(max(t1, 0), NSEQ-1); \
        size_t a0 = ((size_t)bz*NSEQ + tc1)*256 + kloc + u*8; \
        CPA16Z(dA+o, g_h1s+a0, z1); \
        size_t b0 = (size_t)(col0+r)*4352 + (c)*32 + u*8; \
        CPA16(dB+o, g_w2+b0); \
    } }

#define C2_COMPUTE(s) { \
    _Pragma("unroll") \
    for (int ks = 0; ks < 2; ks++) { \
        uint32_t Ah[4][4]; \
        _Pragma("unroll") \
        for (int mi = 0; mi < 4; mi++) { \
            uint32_t ad = sb + C2_A(s) + (warp_m*64 + mi*16)*PITCH + ks*32 + aOff; \
            LDMX4(Ah[mi][0],Ah[mi][1],Ah[mi][2],Ah[mi][3], ad); \
        } \
        _Pragma("unroll") \
        for (int pj = 0; pj < 2; pj++) { \
            uint32_t Bh[4]; \
            uint32_t bd = sb + C2_B(s) + (warp_n*32 + pj*16)*PITCH + ks*32 + bOff; \
            LDMX4(Bh[0],Bh[1],Bh[2],Bh[3], bd); \
            _Pragma("unroll") \
            for (int mi = 0; mi < 4; mi++) \
                _Pragma("unroll") \
                for (int h = 0; h < 2; h++) \
                    MMA_F16(acc[mi][pj*2 + h], Ah[mi], Bh[h*2], Bh[h*2+1]); \
        } \
    } }

    C2_CPA(0, 0); CPCOMMIT();
    C2_CPA(1, 1); CPCOMMIT();
    C2_CPA(2, 2); CPCOMMIT();
    for (int c = 0; c < NC; c++) {
        if (c + 2 < NC)      { CPWAIT(2); }
        else if (c + 1 < NC) { CPWAIT(1); }
        else                 { CPWAIT(0); }
        __syncthreads();
        if (c + 3 < NC) { C2_CPA(c+3, (c+3)&3); CPCOMMIT(); }
        C2_COMPUTE(c&3);
    }
#undef C2_CPA
#undef C2_COMPUTE

    #pragma unroll
    for (int mi = 0; mi < 4; mi++) {
        #pragma unroll
        for (int nj = 0; nj < 4; nj++) {
            int c = col0 + warp_n*32 + nj*8 + tid4*2;
            size_t r1 = row0 + warp_m*64 + mi*16 + gid;
            size_t r2 = r1 + 8;
            float sh0 = g_sh2[c], sh1 = g_sh2[c+1];
            uint32_t lo, hi;
            float a0 = fmaxf(acc[mi][nj][0] + sh0 + x[r1*256+c],   0.f);
            float a1 = fmaxf(acc[mi][nj][1] + sh1 + x[r1*256+c+1], 0.f);
            hi = pksplit_h(a0, a1, lo);
            *(uint32_t*)&g_xch[r1*256 + c] = hi; *(uint32_t*)&g_xcl[r1*256 + c] = lo;
            a0 = fmaxf(acc[mi][nj][2] + sh0 + x[r2*256+c],   0.f);
            a1 = fmaxf(acc[mi][nj][3] + sh1 + x[r2*256+c+1], 0.f);
            hi = pksplit_h(a0, a1, lo);
            *(uint32_t*)&g_xch[r2*256 + c] = hi; *(uint32_t*)&g_xcl[r2*256 + c] = lo;
        }
    }
}

// ---------------- s projection -> (u, q') and (s, q') ---------------------
__global__ void skernel(const float* __restrict__ x,
                        const float* __restrict__ w_se,
                        const float* __restrict__ b_se) {
    int row = blockIdx.x * 8 + (threadIdx.x >> 5);
    int lane = threadIdx.x & 31;
    float p0=0.f, p1=0.f, p2=0.f;
    for (int k = lane; k < DIM; k += 32) {
        float xv = x[(size_t)row*DIM + k];
        p0 += xv * w_se[k];
        p1 += xv * w_se[DIM + k];
        p2 += xv * w_se[2*DIM + k];
    }
    #pragma unroll
    for (int off = 16; off > 0; off >>= 1) {
        p0 += __shfl_down_sync(0xffffffffu, p0, off);
        p1 += __shfl_down_sync(0xffffffffu, p1, off);
        p2 += __shfl_down_sync(0xffffffffu, p2, off);
    }
    if (lane == 0) {
        const float L2E = 1.4426950408889634f;
        p0 += b_se[0]; p1 += b_se[1]; p2 += b_se[2];
        float sq = p0*p0 + p1*p1 + p2*p2;
        float qp = -L2E * sq;
        g_s2[row*8+0] = 2.0f*L2E*p0;
        g_s2[row*8+1] = 2.0f*L2E*p1;
        g_s2[row*8+2] = 2.0f*L2E*p2;
        g_s2[row*8+3] = qp;
        g_s2[row*8+4] = p0;
        g_s2[row*8+5] = p1;
        g_s2[row*8+6] = p2;
        g_s2[row*8+7] = qp;
    }
}

// ---------------- tensorized NMP: fp32 t, f16x2 ex2, 1-MMA ---------------
#define NWP  80
#define NWH(s)  ((s)*5120)             // W bufs: 0, 5120
#define NMPITCH 528
#define NMH(s) (10240 + (s)*16896)     // msg stages: 10240, 27136
#define NSMF(s) (44032 + (s)*512)      // sSm float bufs (4*32 floats)
#define NMP_SMEM 45056

__global__ void __launch_bounds__(256, 2) nmp_kernel(const float* __restrict__ mask) {
    extern __shared__ char smem[];
    const uint32_t sb = smem_u32(smem);
    const int b  = blockIdx.y;
    const int n0 = blockIdx.x * 64;
    const int tid = threadIdx.x;
    const int wid = tid >> 5, lane = tid & 31;
    const int warp_n = wid & 1, warp_d = wid >> 1;
    const int gid = lane >> 2, tid4 = lane & 3;

    const uint32_t aOff  = (uint32_t)(lane & 15)*NWP + (uint32_t)(lane >> 4)*16;
    const uint32_t bOffT = (uint32_t)(lane & 15)*NMPITCH + (uint32_t)(lane >> 4)*16;

    const size_t mbase = ((size_t)b*NSEQ + n0) * NSEQ;
    const int rr = tid >> 2, mm0 = (tid & 3)*8;

    float u0i, u1i, u2i, qi;
    {
        const float* sp = &g_s2[((size_t)b*NSEQ + n0 + rr)*8];
        u0i = sp[0]; u1i = sp[1]; u2i = sp[2]; qi = sp[3];
    }

    const int mrow = tid >> 5;
    const int mu   = tid & 31;

#define NMP_PREFETCH(c, s) { \
    uint32_t dh = sb + NMH(s); \
    const __half* srch = g_msg + ((size_t)b*NSEQ + (c)*32)*256; \
    _Pragma("unroll") \
    for (int q = 0; q < 4; q++) { \
        int row = mrow + q*8; \
        CPA16(dh + (uint32_t)row*NMPITCH + (uint32_t)mu*16, srch + (size_t)row*256 + mu*8); \
    } }

#define SSM_STORE(c, s) { \
    if (tid < 128) { \
        int j = tid >> 2, comp = tid & 3; \
        ((float*)(smem + NSMF(s)))[comp*32 + j] = \
            g_s2[((size_t)b*NSEQ + (c)*32 + j)*8 + 4 + comp]; \
    } }

    SSM_STORE(0, 0);
    NMP_PREFETCH(0, 0); CPCOMMIT();

    float acc[2][8][4] = {};
    constexpr int NCn = NSEQ/32;

    for (int c = 0; c < NCn; c++) {
        int s = c & 1;
        __syncthreads();   // ends MMA(c-1); publishes sSm(c)
        if (c+1 < NCn) SSM_STORE(c+1, 1-s);
        {   // compute W(c): t in fp32, ex2 in f16x2
            const float* sSmF = (const float*)(smem + NSMF(s));
            const float* mrow_p = &mask[mbase + (size_t)rr*NSEQ + c*32 + mm0];
            float4 mk0 = *(const float4*)mrow_p;
            float4 mk1 = *(const float4*)(mrow_p + 4);
            uint32_t wv[4];
            #pragma unroll
            for (int p = 0; p < 4; p++) {
                int mm = mm0 + 2*p;
                float ta = fmaf(u0i, sSmF[mm],
                           fmaf(u1i, sSmF[32+mm],
                           fmaf(u2i, sSmF[64+mm], sSmF[96+mm] + qi)));
                float tb = fmaf(u0i, sSmF[mm+1],
                           fmaf(u1i, sSmF[32+mm+1],
                           fmaf(u2i, sSmF[64+mm+1], sSmF[96+mm+1] + qi)));
                __half2 t2 = __floats2half2_rn(ta, tb);
                uint32_t e2;
                asm("ex2.approx.f16x2 %0, %1;" : "=r"(e2) : "r"(*(uint32_t*)&t2));
                float mka = (p < 2) ? ((p == 0) ? mk0.x : mk0.z) : ((p == 2) ? mk1.x : mk1.z);
                float mkb = (p < 2) ? ((p == 0) ? mk0.y : mk0.w) : ((p == 2) ? mk1.y : mk1.w);
                __half2 mh = __floats2half2_rn(mka, mkb);
                __half2 w2 = __hmul2(*(__half2*)&e2, mh);
                wv[p] = *(uint32_t*)&w2;
            }
            *(uint4*)(smem + NWH(s) + rr*NWP + mm0*2) = make_uint4(wv[0],wv[1],wv[2],wv[3]);
        }
        if (c+1 < NCn) { NMP_PREFETCH(c+1, 1-s); CPCOMMIT(); CPWAIT(1); }
        else           { CPWAIT(0); }
        __syncthreads();   // W(c), msg(c) ready
        #pragma unroll
        for (int ks = 0; ks < 2; ks++) {
            uint32_t Aw[2][4], Bm[4][4];
            #pragma unroll
            for (int mi = 0; mi < 2; mi++) {
                uint32_t ad = sb + NWH(s) + (warp_n*32 + mi*16)*NWP + ks*32 + aOff;
                LDMX4(Aw[mi][0],Aw[mi][1],Aw[mi][2],Aw[mi][3], ad);
            }
            #pragma unroll
            for (int dj = 0; dj < 4; dj++) {
                uint32_t bd = sb + NMH(s) + (ks*16)*NMPITCH + (warp_d*64 + dj*16)*2 + bOffT;
                LDMX4T(Bm[dj][0],Bm[dj][1],Bm[dj][2],Bm[dj][3], bd);
            }
            #pragma unroll
            for (int mi = 0; mi < 2; mi++)
                #pragma unroll
                for (int dj = 0; dj < 4; dj++)
                    #pragma unroll
                    for (int h = 0; h < 2; h++)
                        MMA_F16(acc[mi][dj*2 + h], Aw[mi], Bm[dj][h*2], Bm[dj][h*2+1]);
        }
    }
#undef NMP_PREFETCH
#undef SSM_STORE

    #pragma unroll
    for (int mi = 0; mi < 2; mi++) {
        #pragma unroll
        for (int dj8 = 0; dj8 < 8; dj8++) {
            int d = warp_d*64 + dj8*8 + tid4*2;
            size_t r1 = (size_t)b*NSEQ + n0 + warp_n*32 + mi*16 + gid;
            size_t r2 = r1 + 8;
            uint32_t lo, hi;
            hi = pksplit_h(acc[mi][dj8][0], acc[mi][dj8][1], lo);
            *(uint32_t*)&g_xnh[r1*256 + d] = hi; *(uint32_t*)&g_xnl[r1*256 + d] = lo;
            hi = pksplit_h(acc[mi][dj8][2], acc[mi][dj8][3], lo);
            *(uint32_t*)&g_xnh[r2*256 + d] = hi; *(uint32_t*)&g_xnl[r2*256 + d] = lo;
        }
    }
}

// ---------------- gate epilogue (fp16 gi/gh) ------------------------------
__global__ void gate_kernel(const float* __restrict__ x,
                            const float* __restrict__ b_ih,
                            const float* __restrict__ b_hh,
                            float* __restrict__ out) {
    int idx = blockIdx.x * blockDim.x + threadIdx.x;
    size_t r = idx >> 6;
    int c = (idx & 63) * 4;
    const __half* gi = &g_gi[r*768];
    const __half* gh = &g_gh[r*768];
    float4 xv  = *(const float4*)&x[r*DIM + c];
    float o4[4];
    #pragma unroll
    for (int p = 0; p < 2; p++) {
        int cc = c + 2*p;
        float2 gir = __half22float2(*(__half2*)&gi[cc]);
        float2 giz = __half22float2(*(__half2*)&gi[256 + cc]);
        float2 gin = __half22float2(*(__half2*)&gi[512 + cc]);
        float2 ghr = __half22float2(*(__half2*)&gh[cc]);
        float2 ghz = __half22float2(*(__half2*)&gh[256 + cc]);
        float2 ghn = __half22float2(*(__half2*)&gh[512 + cc]);
        #pragma unroll
        for (int q = 0; q < 2; q++) {
            int cq = cc + q;
            float air = ((q==0)?gir.x:gir.y) + b_ih[cq]     + ((q==0)?ghr.x:ghr.y) + b_hh[cq];
            float aiz = ((q==0)?giz.x:giz.y) + b_ih[256+cq] + ((q==0)?ghz.x:ghz.y) + b_hh[256+cq];
            float rv = 1.0f/(1.0f + __expf(-air));
            float zv = 1.0f/(1.0f + __expf(-aiz));
            float nv = tanhf(((q==0)?gin.x:gin.y) + b_ih[512+cq]
                           + rv*(((q==0)?ghn.x:ghn.y) + b_hh[512+cq]));
            o4[2*p+q] = (1.0f - zv)*nv + zv*(&xv.x)[2*p+q];
        }
    }
    *(float4*)&out[r*DIM + c] = make_float4(o4[0], o4[1], o4[2], o4[3]);
}

// ---------------- launch --------------------------------------------------
extern "C" void kernel_launch(void* const* d_in, const int* in_sizes, int n_in,
                              void* d_out, int out_size) {
    const float* x       = (const float*)d_in[0];
    const float* mask    = (const float*)d_in[1];
    const float* w_se    = (const float*)d_in[2];
    const float* b_se    = (const float*)d_in[3];
    const float* conv1_w = (const float*)d_in[4];
    const float* bn1_g   = (const float*)d_in[5];
    const float* bn1_b   = (const float*)d_in[6];
    const float* bn1_m   = (const float*)d_in[7];
    const float* bn1_v   = (const float*)d_in[8];
    const float* conv2_w = (const float*)d_in[9];
    const float* bn2_g   = (const float*)d_in[10];
    const float* bn2_b   = (const float*)d_in[11];
    const float* bn2_m   = (const float*)d_in[12];
    const float* bn2_v   = (const float*)d_in[13];
    const float* w_msg   = (const float*)d_in[14];
    const float* b_msg   = (const float*)d_in[15];
    const float* w_ih    = (const float*)d_in[16];
    const float* b_ih    = (const float*)d_in[17];
    const float* w_hh    = (const float*)d_in[18];
    const float* b_hh    = (const float*)d_in[19];
    float* out = (float*)d_out;

    cudaFuncSetAttribute(mma_gemm<0>, cudaFuncAttributeMaxDynamicSharedMemorySize, GEMM_SMEM);
    cudaFuncSetAttribute(mma_gemm<2>, cudaFuncAttributeMaxDynamicSharedMemorySize, GEMM_SMEM);
    cudaFuncSetAttribute(mma_gemm<3>, cudaFuncAttributeMaxDynamicSharedMemorySize, GEMM_SMEM);
    cudaFuncSetAttribute(conv2_kernel, cudaFuncAttributeMaxDynamicSharedMemorySize, C2_SMEM);
    cudaFuncSetAttribute(nmp_kernel,  cudaFuncAttributeMaxDynamicSharedMemorySize, NMP_SMEM);

    repack_kernel<<<1024, 256>>>(x, conv1_w, w_msg, conv2_w,
                                 bn1_g, bn1_b, bn1_m, bn1_v,
                                 bn2_g, bn2_b, bn2_m, bn2_v,
                                 b_msg, w_ih, w_hh);

    mma_gemm<0><<<dim3(4, NROWS/256), 256, GEMM_SMEM>>>(x);      // front: h1 + msg

    skernel<<<NROWS/8, 256>>>(x, w_se, b_se);

    conv2_kernel<<<dim3(2, NSEQ/128, BS), 256, C2_SMEM>>>(x);    // conv2 -> xc split

    nmp_kernel<<<dim3(NSEQ/64, BS), 256, NMP_SMEM>>>(mask);      // -> xn split

    mma_gemm<2><<<dim3(6, NROWS/256), 256, GEMM_SMEM>>>(x);      // gi
    mma_gemm<3><<<dim3(6, NROWS/256), 256, GEMM_SMEM>>>(x);      // gh

    gate_kernel<<<NROWS*64/256, 256>>>(x, b_ih, b_hh, out);
}

// round 15
// speedup vs baseline: 4.4507x; 1.0351x over previous
#include <cuda_runtime.h>
#include <cuda_fp16.h>
#include <math.h>
#include <stdint.h>

#define BS   16
#define NSEQ 2048
#define DIM  256
#define NROWS (BS*NSEQ)   // 32768

// ---------------- scratch (device globals) --------------------------------
__device__ float g_s2[NROWS*8];          // [u0,u1,u2,q'] [s0,s1,s2,q']
__device__ __half g_gi[(size_t)NROWS*768];
__device__ __half g_gh[(size_t)NROWS*768];

// fp16 activations
__device__ __half g_xh[NROWS*DIM],  g_xl[NROWS*DIM];     // x split
__device__ __half g_h1s[NROWS*DIM];                      // h1 SINGLE fp16
__device__ __half g_xch[NROWS*DIM], g_xcl[NROWS*DIM];    // xconv split
__device__ __half g_xnh[NROWS*DIM], g_xnl[NROWS*DIM];    // xnmp split
__device__ __half g_msg[NROWS*DIM];                      // single fp16 (positive)

// weights: w2 SINGLE; others hi/lo split ([out][in], K-major)
__device__ __half g_wfh[512*256],  g_wfl[512*256];
__device__ __half g_w2[256*4352];
__device__ __half g_wihh[768*512], g_wihl[768*512];
__device__ __half g_whhh[768*256], g_whhl[768*256];

// bn constants
__device__ float g_sc1[DIM], g_sh1[DIM], g_sh2[DIM], g_bmsg[DIM];

// ---------------- helpers --------------------------------------------------
__device__ __forceinline__ uint32_t smem_u32(const void* p) {
    uint32_t a;
    asm("{ .reg .u64 t; cvta.to.shared.u64 t, %1; cvt.u32.u64 %0, t; }"
        : "=r"(a) : "l"(p));
    return a;
}
__device__ __forceinline__ uint32_t pkh(float a, float b) {
    __half2 h = __floats2half2_rn(a, b);
    return *(uint32_t*)&h;
}
__device__ __forceinline__ uint32_t pksplit_h(float a, float b, uint32_t& lo) {
    __half ha = __float2half_rn(a), hb = __float2half_rn(b);
    lo = pkh(a - __half2float(ha), b - __half2float(hb));
    __half2 h2; h2.x = ha; h2.y = hb;
    return *(uint32_t*)&h2;
}

#define LDMX4(r0,r1,r2,r3,addr) \
    asm volatile("ldmatrix.sync.aligned.m8n8.x4.shared.b16 {%0,%1,%2,%3}, [%4];" \
        : "=r"(r0),"=r"(r1),"=r"(r2),"=r"(r3) : "r"(addr))
#define LDMX4T(r0,r1,r2,r3,addr) \
    asm volatile("ldmatrix.sync.aligned.m8n8.x4.trans.shared.b16 {%0,%1,%2,%3}, [%4];" \
        : "=r"(r0),"=r"(r1),"=r"(r2),"=r"(r3) : "r"(addr))
#define MMA_F16(d, a, b0, b1) \
    asm volatile("mma.sync.aligned.m16n8k16.row.col.f32.f16.f16.f32 " \
        "{%0,%1,%2,%3}, {%4,%5,%6,%7}, {%8,%9}, {%0,%1,%2,%3};" \
        : "+f"((d)[0]),"+f"((d)[1]),"+f"((d)[2]),"+f"((d)[3]) \
        : "r"((a)[0]),"r"((a)[1]),"r"((a)[2]),"r"((a)[3]), "r"(b0),"r"(b1))

#define CPA16(dst, src) \
    asm volatile("cp.async.cg.shared.global [%0], [%1], 16;" :: "r"(dst), "l"(src))
#define CPA16Z(dst, src, sz) \
    asm volatile("cp.async.cg.shared.global [%0], [%1], 16, %2;" :: "r"(dst), "l"(src), "r"(sz))
#define CPCOMMIT() asm volatile("cp.async.commit_group;" ::: "memory")
#define CPWAIT(n)  asm volatile("cp.async.wait_group %0;" :: "n"(n) : "memory")

// ---------------- repack ---------------------------------------------------
__global__ void repack_kernel(const float* __restrict__ x,
                              const float* __restrict__ conv1_w,
                              const float* __restrict__ w_msg,
                              const float* __restrict__ conv2_w,
                              const float* __restrict__ bn1_g, const float* __restrict__ bn1_b,
                              const float* __restrict__ bn1_m, const float* __restrict__ bn1_v,
                              const float* __restrict__ bn2_g, const float* __restrict__ bn2_b,
                              const float* __restrict__ bn2_m, const float* __restrict__ bn2_v,
                              const float* __restrict__ b_msg,
                              const float* __restrict__ w_ih,
                              const float* __restrict__ w_hh) {
    int stride = gridDim.x * blockDim.x;
    int idx = blockIdx.x * blockDim.x + threadIdx.x;
    if (idx < DIM) {
        float sc = bn1_g[idx] * rsqrtf(bn1_v[idx] + 1e-5f);
        g_sc1[idx] = sc;
        g_sh1[idx] = bn1_b[idx] - bn1_m[idx]*sc;
        float sc2 = bn2_g[idx] * rsqrtf(bn2_v[idx] + 1e-5f);
        g_sh2[idx] = bn2_b[idx] - bn2_m[idx]*sc2;
        g_bmsg[idx] = b_msg[idx];
    }
    for (int i = idx; i < 512*256; i += stride) {
        int n = i >> 8, k = i & 255;
        float v = (n < 256) ? conv1_w[n*256 + k] : w_msg[(n-256)*256 + k];
        __half h = __float2half_rn(v);
        g_wfh[i] = h; g_wfl[i] = __float2half_rn(v - __half2float(h));
    }
    for (int i = idx; i < 256*4352; i += stride) {
        int o = i / 4352, kk = i - o*4352;
        int tap = kk >> 8, ic = kk & 255;
        float sc = bn2_g[o] * rsqrtf(bn2_v[o] + 1e-5f);
        g_w2[i] = __float2half_rn(conv2_w[(o*256 + ic)*17 + tap] * sc);
    }
    for (int i = idx; i < 768*512; i += stride) {
        float v = w_ih[i];
        __half h = __float2half_rn(v);
        g_wihh[i] = h; g_wihl[i] = __float2half_rn(v - __half2float(h));
    }
    for (int i = idx; i < 768*256; i += stride) {
        float v = w_hh[i];
        __half h = __float2half_rn(v);
        g_whhh[i] = h; g_whhl[i] = __float2half_rn(v - __half2float(h));
    }
    for (int i = idx; i < NROWS*DIM; i += stride) {
        float v = x[i];
        __half h = __float2half_rn(v);
        g_xh[i] = h; g_xl[i] = __float2half_rn(v - __half2float(h));
    }
}

// == GEMM template (modes 0,2,3): 256x128 tile, A-split x B-split, 3-stage =
#define PITCH 80
#define A_ARR 20480            // 256 rows * 80
#define B_ARR 10240            // 128 rows * 80
#define SM_AHI(s) ((s)*61440 + 0)
#define SM_ALO(s) ((s)*61440 + A_ARR)
#define SM_BHI(s) ((s)*61440 + 2*A_ARR)
#define SM_BLO(s) ((s)*61440 + 2*A_ARR + B_ARR)
#define GEMM_SMEM 184320

template<int MODE>
__global__ void __launch_bounds__(256, 1) mma_gemm(const float* __restrict__ x) {
    extern __shared__ char smem[];
    const int tid  = threadIdx.x;
    const int wid  = tid >> 5, lane = tid & 31;
    const int warp_m = wid & 3;        // 4 x 64 rows
    const int warp_n = wid >> 2;       // 2 x 64 cols
    const int gid  = lane >> 2, tid4 = lane & 3;
    const uint32_t sb = smem_u32(smem);

    constexpr int KT = (MODE==0) ? 256 : (MODE==2) ? 512 : 256;
    constexpr int NC = KT / 32;
    const int col0 = blockIdx.x * 128;
    const int t0 = blockIdx.y * 256;
    const int row0 = t0;

    const uint32_t aOff = (uint32_t)(lane & 15)*PITCH + (uint32_t)(lane >> 4)*16;
    const uint32_t bOff = (uint32_t)(((lane >> 4) << 3) + (lane & 7))*PITCH
                        + (uint32_t)((lane >> 3) & 1)*16;

    const int r0_ = tid >> 2, u_ = tid & 3;

    float acc[4][8][4] = {};

#define CPA_TILE(c, s) { \
    uint32_t dAh = sb + SM_AHI(s), dAl = sb + SM_ALO(s); \
    uint32_t dBh = sb + SM_BHI(s), dBl = sb + SM_BLO(s); \
    _Pragma("unroll") \
    for (int g = 0; g < 4; g++) { \
        int arow = r0_ + 64*g; \
        uint32_t o = (uint32_t)(arow*PITCH + u_*16); \
        if (MODE == 0 || MODE == 3) { \
            size_t a0 = (size_t)(row0+arow)*256 + (c)*32 + u_*8; \
            CPA16(dAh+o, g_xh+a0); CPA16(dAl+o, g_xl+a0); \
        } else { \
            const __half* sh_ = ((c) < 8) ? g_xch : g_xnh; \
            const __half* sl_ = ((c) < 8) ? g_xcl : g_xnl; \
            int kk_ = ((c) & 7)*32; \
            size_t a0 = (size_t)(row0+arow)*256 + kk_ + u_*8; \
            CPA16(dAh+o, sh_+a0); CPA16(dAl+o, sl_+a0); \
        } \
    } \
    _Pragma("unroll") \
    for (int g = 0; g < 2; g++) { \
        int brow = r0_ + 64*g; \
        uint32_t o = (uint32_t)(brow*PITCH + u_*16); \
        if (MODE == 0) { \
            size_t b0 = (size_t)(col0+brow)*256 + (c)*32 + u_*8; \
            CPA16(dBh+o, g_wfh+b0); CPA16(dBl+o, g_wfl+b0); \
        } else if (MODE == 2) { \
            size_t b0 = (size_t)(col0+brow)*512 + (c)*32 + u_*8; \
            CPA16(dBh+o, g_wihh+b0); CPA16(dBl+o, g_wihl+b0); \
        } else { \
            size_t b0 = (size_t)(col0+brow)*256 + (c)*32 + u_*8; \
            CPA16(dBh+o, g_whhh+b0); CPA16(dBl+o, g_whhl+b0); \
        } \
    } }

#define COMPUTE(s) { \
    _Pragma("unroll") \
    for (int ks = 0; ks < 2; ks++) { \
        uint32_t Ah[4][4], Al[4][4]; \
        _Pragma("unroll") \
        for (int mi = 0; mi < 4; mi++) { \
            uint32_t ad = sb + SM_AHI(s) + (warp_m*64 + mi*16)*PITCH + ks*32 + aOff; \
            LDMX4(Ah[mi][0],Ah[mi][1],Ah[mi][2],Ah[mi][3], ad); \
            ad = sb + SM_ALO(s) + (warp_m*64 + mi*16)*PITCH + ks*32 + aOff; \
            LDMX4(Al[mi][0],Al[mi][1],Al[mi][2],Al[mi][3], ad); \
        } \
        _Pragma("unroll") \
        for (int pj = 0; pj < 4; pj++) { \
            uint32_t Bh[4], Bl[4]; \
            uint32_t bd = sb + SM_BHI(s) + (warp_n*64 + pj*16)*PITCH + ks*32 + bOff; \
            LDMX4(Bh[0],Bh[1],Bh[2],Bh[3], bd); \
            bd = sb + SM_BLO(s) + (warp_n*64 + pj*16)*PITCH + ks*32 + bOff; \
            LDMX4(Bl[0],Bl[1],Bl[2],Bl[3], bd); \
            _Pragma("unroll") \
            for (int mi = 0; mi < 4; mi++) \
                _Pragma("unroll") \
                for (int h = 0; h < 2; h++) { \
                    float* D = acc[mi][pj*2 + h]; \
                    MMA_F16(D, Ah[mi], Bh[h*2], Bh[h*2+1]); \
                    MMA_F16(D, Ah[mi], Bl[h*2], Bl[h*2+1]); \
                    MMA_F16(D, Al[mi], Bh[h*2], Bh[h*2+1]); \
                } \
        } \
    } }

    CPA_TILE(0, 0); CPCOMMIT();
    CPA_TILE(1, 1); CPCOMMIT();
    for (int c = 0; c < NC; c++) {
        if (c + 1 < NC) { CPWAIT(1); } else { CPWAIT(0); }
        __syncthreads();
        if (c + 2 < NC) { CPA_TILE(c+2, (c+2)%3); CPCOMMIT(); }
        COMPUTE(c%3);
    }
#undef CPA_TILE
#undef COMPUTE

    // ---------------- epilogue ----------------
    #pragma unroll
    for (int mi = 0; mi < 4; mi++) {
        #pragma unroll
        for (int nj = 0; nj < 8; nj++) {
            int c = col0 + warp_n*64 + nj*8 + tid4*2;
            size_t r1 = (size_t)row0 + warp_m*64 + mi*16 + gid;
            size_t r2 = r1 + 8;
            float v00 = acc[mi][nj][0], v01 = acc[mi][nj][1];
            float v10 = acc[mi][nj][2], v11 = acc[mi][nj][3];
            if (MODE == 0) {
                if (col0 < 256) {
                    float sc0 = g_sc1[c], sc1 = g_sc1[c+1];
                    float sh0 = g_sh1[c], sh1 = g_sh1[c+1];
                    *(uint32_t*)&g_h1s[r1*256 + c] =
                        pkh(fmaxf(v00*sc0+sh0,0.f), fmaxf(v01*sc1+sh1,0.f));
                    *(uint32_t*)&g_h1s[r2*256 + c] =
                        pkh(fmaxf(v10*sc0+sh0,0.f), fmaxf(v11*sc1+sh1,0.f));
                } else {
                    int cc = c - 256;
                    float b0 = g_bmsg[cc], b1 = g_bmsg[cc+1];
                    *(uint32_t*)&g_msg[r1*256 + cc] = pkh(fmaxf(v00+b0,0.f), fmaxf(v01+b1,0.f));
                    *(uint32_t*)&g_msg[r2*256 + cc] = pkh(fmaxf(v10+b0,0.f), fmaxf(v11+b1,0.f));
                }
            } else if (MODE == 2) {
                *(uint32_t*)&g_gi[r1*768 + c] = pkh(v00, v01);
                *(uint32_t*)&g_gi[r2*768 + c] = pkh(v10, v11);
            } else {
                *(uint32_t*)&g_gh[r1*768 + c] = pkh(v00, v01);
                *(uint32_t*)&g_gh[r2*768 + c] = pkh(v10, v11);
            }
        }
    }
}

// == conv2: 128x128 tile, 128 thr, 64x64 warp tiles, 1 MMA, 4-stage ========
#define C2_STAGE 20480         // A 10240 + B 10240
#define C2_A(s)   ((s)*C2_STAGE)
#define C2_B(s)   ((s)*C2_STAGE + 10240)
#define C2_SMEM   81920

__global__ void __launch_bounds__(128, 2) conv2_kernel(const float* __restrict__ x) {
    extern __shared__ char smem[];
    const int tid  = threadIdx.x;
    const int wid  = tid >> 5, lane = tid & 31;
    const int warp_m = wid & 1;        // 2 x 64 rows
    const int warp_n = wid >> 1;       // 2 x 64 cols
    const int gid  = lane >> 2, tid4 = lane & 3;
    const uint32_t sb = smem_u32(smem);

    constexpr int NC = 4352 / 32;      // 136
    const int col0 = blockIdx.x * 128;
    const int bz = blockIdx.z;
    const int t0 = blockIdx.y * 128;
    const size_t row0 = (size_t)bz*NSEQ + t0;

    const uint32_t aOff = (uint32_t)(lane & 15)*PITCH + (uint32_t)(lane >> 4)*16;
    const uint32_t bOff = (uint32_t)(((lane >> 4) << 3) + (lane & 7))*PITCH
                        + (uint32_t)((lane >> 3) & 1)*16;

    float acc[4][8][4] = {};

#define C2_CPA(c, s) { \
    uint32_t dA = sb + C2_A(s), dB = sb + C2_B(s); \
    int tap = (c) >> 3, kloc = ((c) & 7)*32; \
    _Pragma("unroll") \
    for (int g = 0; g < 4; g++) { \
        int idx = tid + 128*g; \
        int r = idx >> 2, u = idx & 3; \
        uint32_t o = (uint32_t)(r*PITCH + u*16); \
        int t1 = t0 + r + tap - 8; \
        uint32_t z1 = ((unsigned)t1 < (unsigned)NSEQ) ? 16u : 0u; \
        int tc1 = min(max(t1, 0), NSEQ-1); \
        size_t a0 = ((size_t)bz*NSEQ + tc1)*256 + kloc + u*8; \
        CPA16Z(dA+o, g_h1s+a0, z1); \
        size_t b0 = (size_t)(col0+r)*4352 + (c)*32 + u*8; \
        CPA16(dB+o, g_w2+b0); \
    } }

#define C2_COMPUTE(s) { \
    _Pragma("unroll") \
    for (int ks = 0; ks < 2; ks++) { \
        uint32_t Ah[4][4], Bh[4][4]; \
        _Pragma("unroll") \
        for (int mi = 0; mi < 4; mi++) { \
            uint32_t ad = sb + C2_A(s) + (warp_m*64 + mi*16)*PITCH + ks*32 + aOff; \
            LDMX4(Ah[mi][0],Ah[mi][1],Ah[mi][2],Ah[mi][3], ad); \
        } \
        _Pragma("unroll") \
        for (int pj = 0; pj < 4; pj++) { \
            uint32_t bd = sb + C2_B(s) + (warp_n*64 + pj*16)*PITCH + ks*32 + bOff; \
            LDMX4(Bh[pj][0],Bh[pj][1],Bh[pj][2],Bh[pj][3], bd); \
        } \
        _Pragma("unroll") \
        for (int mi = 0; mi < 4; mi++) \
            _Pragma("unroll") \
            for (int pj = 0; pj < 4; pj++) \
                _Pragma("unroll") \
                for (int h = 0; h < 2; h++) \
                    MMA_F16(acc[mi][pj*2 + h], Ah[mi], Bh[pj][h*2], Bh[pj][h*2+1]); \
    } }

    C2_CPA(0, 0); CPCOMMIT();
    C2_CPA(1, 1); CPCOMMIT();
    C2_CPA(2, 2); CPCOMMIT();
    for (int c = 0; c < NC; c++) {
        if (c + 2 < NC)      { CPWAIT(2); }
        else if (c + 1 < NC) { CPWAIT(1); }
        else                 { CPWAIT(0); }
        __syncthreads();
        if (c + 3 < NC) { C2_CPA(c+3, (c+3)&3); CPCOMMIT(); }
        C2_COMPUTE(c&3);
    }
#undef C2_CPA
#undef C2_COMPUTE

    #pragma unroll
    for (int mi = 0; mi < 4; mi++) {
        #pragma unroll
        for (int nj = 0; nj < 8; nj++) {
            int c = col0 + warp_n*64 + nj*8 + tid4*2;
            size_t r1 = row0 + warp_m*64 + mi*16 + gid;
            size_t r2 = r1 + 8;
            float sh0 = g_sh2[c], sh1 = g_sh2[c+1];
            uint32_t lo, hi;
            float a0 = fmaxf(acc[mi][nj][0] + sh0 + x[r1*256+c],   0.f);
            float a1 = fmaxf(acc[mi][nj][1] + sh1 + x[r1*256+c+1], 0.f);
            hi = pksplit_h(a0, a1, lo);
            *(uint32_t*)&g_xch[r1*256 + c] = hi; *(uint32_t*)&g_xcl[r1*256 + c] = lo;
            a0 = fmaxf(acc[mi][nj][2] + sh0 + x[r2*256+c],   0.f);
            a1 = fmaxf(acc[mi][nj][3] + sh1 + x[r2*256+c+1], 0.f);
            hi = pksplit_h(a0, a1, lo);
            *(uint32_t*)&g_xch[r2*256 + c] = hi; *(uint32_t*)&g_xcl[r2*256 + c] = lo;
        }
    }
}

// ---------------- s projection -> (u, q') and (s, q') ---------------------
__global__ void skernel(const float* __restrict__ x,
                        const float* __restrict__ w_se,
                        const float* __restrict__ b_se) {
    int row = blockIdx.x * 8 + (threadIdx.x >> 5);
    int lane = threadIdx.x & 31;
    float p0=0.f, p1=0.f, p2=0.f;
    for (int k = lane; k < DIM; k += 32) {
        float xv = x[(size_t)row*DIM + k];
        p0 += xv * w_se[k];
        p1 += xv * w_se[DIM + k];
        p2 += xv * w_se[2*DIM + k];
    }
    #pragma unroll
    for (int off = 16; off > 0; off >>= 1) {
        p0 += __shfl_down_sync(0xffffffffu, p0, off);
        p1 += __shfl_down_sync(0xffffffffu, p1, off);
        p2 += __shfl_down_sync(0xffffffffu, p2, off);
    }
    if (lane == 0) {
        const float L2E = 1.4426950408889634f;
        p0 += b_se[0]; p1 += b_se[1]; p2 += b_se[2];
        float sq = p0*p0 + p1*p1 + p2*p2;
        float qp = -L2E * sq;
        g_s2[row*8+0] = 2.0f*L2E*p0;
        g_s2[row*8+1] = 2.0f*L2E*p1;
        g_s2[row*8+2] = 2.0f*L2E*p2;
        g_s2[row*8+3] = qp;
        g_s2[row*8+4] = p0;
        g_s2[row*8+5] = p1;
        g_s2[row*8+6] = p2;
        g_s2[row*8+7] = qp;
    }
}

// ---------------- tensorized NMP: fp32 t, f16x2 ex2, 1-MMA ---------------
#define NWP  80
#define NWH(s)  ((s)*5120)             // W bufs: 0, 5120
#define NMPITCH 528
#define NMH(s) (10240 + (s)*16896)     // msg stages: 10240, 27136
#define NSMF(s) (44032 + (s)*512)      // sSm float bufs (4*32 floats)
#define NMP_SMEM 45056

__global__ void __launch_bounds__(256, 2) nmp_kernel(const float* __restrict__ mask) {
    extern __shared__ char smem[];
    const uint32_t sb = smem_u32(smem);
    const int b  = blockIdx.y;
    const int n0 = blockIdx.x * 64;
    const int tid = threadIdx.x;
    const int wid = tid >> 5, lane = tid & 31;
    const int warp_n = wid & 1, warp_d = wid >> 1;
    const int gid = lane >> 2, tid4 = lane & 3;

    const uint32_t aOff  = (uint32_t)(lane & 15)*NWP + (uint32_t)(lane >> 4)*16;
    const uint32_t bOffT = (uint32_t)(lane & 15)*NMPITCH + (uint32_t)(lane >> 4)*16;

    const size_t mbase = ((size_t)b*NSEQ + n0) * NSEQ;
    const int rr = tid >> 2, mm0 = (tid & 3)*8;

    float u0i, u1i, u2i, qi;
    {
        const float* sp = &g_s2[((size_t)b*NSEQ + n0 + rr)*8];
        u0i = sp[0]; u1i = sp[1]; u2i = sp[2]; qi = sp[3];
    }

    const int mrow = tid >> 5;
    const int mu   = tid & 31;

#define NMP_PREFETCH(c, s) { \
    uint32_t dh = sb + NMH(s); \
    const __half* srch = g_msg + ((size_t)b*NSEQ + (c)*32)*256; \
    _Pragma("unroll") \
    for (int q = 0; q < 4; q++) { \
        int row = mrow + q*8; \
        CPA16(dh + (uint32_t)row*NMPITCH + (uint32_t)mu*16, srch + (size_t)row*256 + mu*8); \
    } }

#define SSM_STORE(c, s) { \
    if (tid < 128) { \
        int j = tid >> 2, comp = tid & 3; \
        ((float*)(smem + NSMF(s)))[comp*32 + j] = \
            g_s2[((size_t)b*NSEQ + (c)*32 + j)*8 + 4 + comp]; \
    } }

    SSM_STORE(0, 0);
    NMP_PREFETCH(0, 0); CPCOMMIT();

    float acc[2][8][4] = {};
    constexpr int NCn = NSEQ/32;

    for (int c = 0; c < NCn; c++) {
        int s = c & 1;
        __syncthreads();   // ends MMA(c-1); publishes sSm(c)
        if (c+1 < NCn) SSM_STORE(c+1, 1-s);
        {   // compute W(c): t in fp32, ex2 in f16x2
            const float* sSmF = (const float*)(smem + NSMF(s));
            const float* mrow_p = &mask[mbase + (size_t)rr*NSEQ + c*32 + mm0];
            float4 mk0 = *(const float4*)mrow_p;
            float4 mk1 = *(const float4*)(mrow_p + 4);
            uint32_t wv[4];
            #pragma unroll
            for (int p = 0; p < 4; p++) {
                int mm = mm0 + 2*p;
                float ta = fmaf(u0i, sSmF[mm],
                           fmaf(u1i, sSmF[32+mm],
                           fmaf(u2i, sSmF[64+mm], sSmF[96+mm] + qi)));
                float tb = fmaf(u0i, sSmF[mm+1],
                           fmaf(u1i, sSmF[32+mm+1],
                           fmaf(u2i, sSmF[64+mm+1], sSmF[96+mm+1] + qi)));
                __half2 t2 = __floats2half2_rn(ta, tb);
                uint32_t e2;
                asm("ex2.approx.f16x2 %0, %1;" : "=r"(e2) : "r"(*(uint32_t*)&t2));
                float mka = (p < 2) ? ((p == 0) ? mk0.x : mk0.z) : ((p == 2) ? mk1.x : mk1.z);
                float mkb = (p < 2) ? ((p == 0) ? mk0.y : mk0.w) : ((p == 2) ? mk1.y : mk1.w);
                __half2 mh = __floats2half2_rn(mka, mkb);
                __half2 w2 = __hmul2(*(__half2*)&e2, mh);
                wv[p] = *(uint32_t*)&w2;
            }
            *(uint4*)(smem + NWH(s) + rr*NWP + mm0*2) = make_uint4(wv[0],wv[1],wv[2],wv[3]);
        }
        if (c+1 < NCn) { NMP_PREFETCH(c+1, 1-s); CPCOMMIT(); CPWAIT(1); }
        else           { CPWAIT(0); }
        __syncthreads();   // W(c), msg(c) ready
        #pragma unroll
        for (int ks = 0; ks < 2; ks++) {
            uint32_t Aw[2][4], Bm[4][4];
            #pragma unroll
            for (int mi = 0; mi < 2; mi++) {
                uint32_t ad = sb + NWH(s) + (warp_n*32 + mi*16)*NWP + ks*32 + aOff;
                LDMX4(Aw[mi][0],Aw[mi][1],Aw[mi][2],Aw[mi][3], ad);
            }
            #pragma unroll
            for (int dj = 0; dj < 4; dj++) {
                uint32_t bd = sb + NMH(s) + (ks*16)*NMPITCH + (warp_d*64 + dj*16)*2 + bOffT;
                LDMX4T(Bm[dj][0],Bm[dj][1],Bm[dj][2],Bm[dj][3], bd);
            }
            #pragma unroll
            for (int mi = 0; mi < 2; mi++)
                #pragma unroll
                for (int dj = 0; dj < 4; dj++)
                    #pragma unroll
                    for (int h = 0; h < 2; h++)
                        MMA_F16(acc[mi][dj*2 + h], Aw[mi], Bm[dj][h*2], Bm[dj][h*2+1]);
        }
    }
#undef NMP_PREFETCH
#undef SSM_STORE

    #pragma unroll
    for (int mi = 0; mi < 2; mi++) {
        #pragma unroll
        for (int dj8 = 0; dj8 < 8; dj8++) {
            int d = warp_d*64 + dj8*8 + tid4*2;
            size_t r1 = (size_t)b*NSEQ + n0 + warp_n*32 + mi*16 + gid;
            size_t r2 = r1 + 8;
            uint32_t lo, hi;
            hi = pksplit_h(acc[mi][dj8][0], acc[mi][dj8][1], lo);
            *(uint32_t*)&g_xnh[r1*256 + d] = hi; *(uint32_t*)&g_xnl[r1*256 + d] = lo;
            hi = pksplit_h(acc[mi][dj8][2], acc[mi][dj8][3], lo);
            *(uint32_t*)&g_xnh[r2*256 + d] = hi; *(uint32_t*)&g_xnl[r2*256 + d] = lo;
        }
    }
}

// ---------------- gate epilogue (fp16 gi/gh) ------------------------------
__global__ void gate_kernel(const float* __restrict__ x,
                            const float* __restrict__ b_ih,
                            const float* __restrict__ b_hh,
                            float* __restrict__ out) {
    int idx = blockIdx.x * blockDim.x + threadIdx.x;
    size_t r = idx >> 6;
    int c = (idx & 63) * 4;
    const __half* gi = &g_gi[r*768];
    const __half* gh = &g_gh[r*768];
    float4 xv  = *(const float4*)&x[r*DIM + c];
    float o4[4];
    #pragma unroll
    for (int p = 0; p < 2; p++) {
        int cc = c + 2*p;
        float2 gir = __half22float2(*(__half2*)&gi[cc]);
        float2 giz = __half22float2(*(__half2*)&gi[256 + cc]);
        float2 gin = __half22float2(*(__half2*)&gi[512 + cc]);
        float2 ghr = __half22float2(*(__half2*)&gh[cc]);
        float2 ghz = __half22float2(*(__half2*)&gh[256 + cc]);
        float2 ghn = __half22float2(*(__half2*)&gh[512 + cc]);
        #pragma unroll
        for (int q = 0; q < 2; q++) {
            int cq = cc + q;
            float air = ((q==0)?gir.x:gir.y) + b_ih[cq]     + ((q==0)?ghr.x:ghr.y) + b_hh[cq];
            float aiz = ((q==0)?giz.x:giz.y) + b_ih[256+cq] + ((q==0)?ghz.x:ghz.y) + b_hh[256+cq];
            float rv = 1.0f/(1.0f + __expf(-air));
            float zv = 1.0f/(1.0f + __expf(-aiz));
            float nv = tanhf(((q==0)?gin.x:gin.y) + b_ih[512+cq]
                           + rv*(((q==0)?ghn.x:ghn.y) + b_hh[512+cq]));
            o4[2*p+q] = (1.0f - zv)*nv + zv*(&xv.x)[2*p+q];
        }
    }
    *(float4*)&out[r*DIM + c] = make_float4(o4[0], o4[1], o4[2], o4[3]);
}

// ---------------- launch --------------------------------------------------
extern "C" void kernel_launch(void* const* d_in, const int* in_sizes, int n_in,
                              void* d_out, int out_size) {
    const float* x       = (const float*)d_in[0];
    const float* mask    = (const float*)d_in[1];
    const float* w_se    = (const float*)d_in[2];
    const float* b_se    = (const float*)d_in[3];
    const float* conv1_w = (const float*)d_in[4];
    const float* bn1_g   = (const float*)d_in[5];
    const float* bn1_b   = (const float*)d_in[6];
    const float* bn1_m   = (const float*)d_in[7];
    const float* bn1_v   = (const float*)d_in[8];
    const float* conv2_w = (const float*)d_in[9];
    const float* bn2_g   = (const float*)d_in[10];
    const float* bn2_b   = (const float*)d_in[11];
    const float* bn2_m   = (const float*)d_in[12];
    const float* bn2_v   = (const float*)d_in[13];
    const float* w_msg   = (const float*)d_in[14];
    const float* b_msg   = (const float*)d_in[15];
    const float* w_ih    = (const float*)d_in[16];
    const float* b_ih    = (const float*)d_in[17];
    const float* w_hh    = (const float*)d_in[18];
    const float* b_hh    = (const float*)d_in[19];
    float* out = (float*)d_out;

    cudaFuncSetAttribute(mma_gemm<0>, cudaFuncAttributeMaxDynamicSharedMemorySize, GEMM_SMEM);
    cudaFuncSetAttribute(mma_gemm<2>, cudaFuncAttributeMaxDynamicSharedMemorySize, GEMM_SMEM);
    cudaFuncSetAttribute(mma_gemm<3>, cudaFuncAttributeMaxDynamicSharedMemorySize, GEMM_SMEM);
    cudaFuncSetAttribute(conv2_kernel, cudaFuncAttributeMaxDynamicSharedMemorySize, C2_SMEM);
    cudaFuncSetAttribute(nmp_kernel,  cudaFuncAttributeMaxDynamicSharedMemorySize, NMP_SMEM);

    repack_kernel<<<1024, 256>>>(x, conv1_w, w_msg, conv2_w,
                                 bn1_g, bn1_b, bn1_m, bn1_v,
                                 bn2_g, bn2_b, bn2_m, bn2_v,
                                 b_msg, w_ih, w_hh);

    mma_gemm<0><<<dim3(4, NROWS/256), 256, GEMM_SMEM>>>(x);      // front: h1 + msg

    skernel<<<NROWS/8, 256>>>(x, w_se, b_se);

    conv2_kernel<<<dim3(2, NSEQ/128, BS), 128, C2_SMEM>>>(x);    // conv2 -> xc split

    nmp_kernel<<<dim3(NSEQ/64, BS), 256, NMP_SMEM>>>(mask);      // -> xn split

    mma_gemm<2><<<dim3(6, NROWS/256), 256, GEMM_SMEM>>>(x);      // gi
    mma_gemm<3><<<dim3(6, NROWS/256), 256, GEMM_SMEM>>>(x);      // gh

    gate_kernel<<<NROWS*64/256, 256>>>(x, b_ih, b_hh, out);
}

// round 17
// speedup vs baseline: 4.6956x; 1.0550x over previous
#include <cuda_runtime.h>
#include <cuda_fp16.h>
#include <math.h>
#include <stdint.h>

#define BS   16
#define NSEQ 2048
#define DIM  256
#define NROWS (BS*NSEQ)   // 32768

// ---------------- scratch (device globals) --------------------------------
__device__ float g_s2[NROWS*8];          // [u0,u1,u2,q'] [s0,s1,s2,q']
__device__ __half g_gi[(size_t)NROWS*768];
__device__ __half g_gh[(size_t)NROWS*768];

// fp16 activations
__device__ __half g_xh[NROWS*DIM],  g_xl[NROWS*DIM];     // x split
__device__ __half g_h1s[NROWS*DIM];                      // h1 SINGLE fp16
__device__ __half g_xch[NROWS*DIM], g_xcl[NROWS*DIM];    // xconv split
__device__ __half g_xnh[NROWS*DIM], g_xnl[NROWS*DIM];    // xnmp split
__device__ __half g_msg[NROWS*DIM];                      // single fp16 (positive)

// weights: w2 SINGLE; others hi/lo split ([out][in], K-major)
__device__ __half g_wfh[512*256],  g_wfl[512*256];
__device__ __half g_w2[256*4352];
__device__ __half g_wihh[768*512], g_wihl[768*512];
__device__ __half g_whhh[768*256], g_whhl[768*256];

// bn constants
__device__ float g_sc1[DIM], g_sh1[DIM], g_sh2[DIM], g_bmsg[DIM];

// ---------------- helpers --------------------------------------------------
__device__ __forceinline__ uint32_t smem_u32(const void* p) {
    uint32_t a;
    asm("{ .reg .u64 t; cvta.to.shared.u64 t, %1; cvt.u32.u64 %0, t; }"
        : "=r"(a) : "l"(p));
    return a;
}
__device__ __forceinline__ uint32_t pkh(float a, float b) {
    __half2 h = __floats2half2_rn(a, b);
    return *(uint32_t*)&h;
}
__device__ __forceinline__ uint32_t pksplit_h(float a, float b, uint32_t& lo) {
    __half ha = __float2half_rn(a), hb = __float2half_rn(b);
    lo = pkh(a - __half2float(ha), b - __half2float(hb));
    __half2 h2; h2.x = ha; h2.y = hb;
    return *(uint32_t*)&h2;
}

#define LDMX4(r0,r1,r2,r3,addr) \
    asm volatile("ldmatrix.sync.aligned.m8n8.x4.shared.b16 {%0,%1,%2,%3}, [%4];" \
        : "=r"(r0),"=r"(r1),"=r"(r2),"=r"(r3) : "r"(addr))
#define LDMX4T(r0,r1,r2,r3,addr) \
    asm volatile("ldmatrix.sync.aligned.m8n8.x4.trans.shared.b16 {%0,%1,%2,%3}, [%4];" \
        : "=r"(r0),"=r"(r1),"=r"(r2),"=r"(r3) : "r"(addr))
#define MMA_F16(d, a, b0, b1) \
    asm volatile("mma.sync.aligned.m16n8k16.row.col.f32.f16.f16.f32 " \
        "{%0,%1,%2,%3}, {%4,%5,%6,%7}, {%8,%9}, {%0,%1,%2,%3};" \
        : "+f"((d)[0]),"+f"((d)[1]),"+f"((d)[2]),"+f"((d)[3]) \
        : "r"((a)[0]),"r"((a)[1]),"r"((a)[2]),"r"((a)[3]), "r"(b0),"r"(b1))

#define CPA16(dst, src) \
    asm volatile("cp.async.cg.shared.global [%0], [%1], 16;" :: "r"(dst), "l"(src))
#define CPA16Z(dst, src, sz) \
    asm volatile("cp.async.cg.shared.global [%0], [%1], 16, %2;" :: "r"(dst), "l"(src), "r"(sz))
#define CPCOMMIT() asm volatile("cp.async.commit_group;" ::: "memory")
#define CPWAIT(n)  asm volatile("cp.async.wait_group %0;" :: "n"(n) : "memory")

// ---------------- repack ---------------------------------------------------
__global__ void repack_kernel(const float* __restrict__ x,
                              const float* __restrict__ conv1_w,
                              const float* __restrict__ w_msg,
                              const float* __restrict__ conv2_w,
                              const float* __restrict__ bn1_g, const float* __restrict__ bn1_b,
                              const float* __restrict__ bn1_m, const float* __restrict__ bn1_v,
                              const float* __restrict__ bn2_g, const float* __restrict__ bn2_b,
                              const float* __restrict__ bn2_m, const float* __restrict__ bn2_v,
                              const float* __restrict__ b_msg,
                              const float* __restrict__ w_ih,
                              const float* __restrict__ w_hh) {
    int stride = gridDim.x * blockDim.x;
    int idx = blockIdx.x * blockDim.x + threadIdx.x;
    if (idx < DIM) {
        float sc = bn1_g[idx] * rsqrtf(bn1_v[idx] + 1e-5f);
        g_sc1[idx] = sc;
        g_sh1[idx] = bn1_b[idx] - bn1_m[idx]*sc;
        float sc2 = bn2_g[idx] * rsqrtf(bn2_v[idx] + 1e-5f);
        g_sh2[idx] = bn2_b[idx] - bn2_m[idx]*sc2;
        g_bmsg[idx] = b_msg[idx];
    }
    for (int i = idx; i < 512*256; i += stride) {
        int n = i >> 8, k = i & 255;
        float v = (n < 256) ? conv1_w[n*256 + k] : w_msg[(n-256)*256 + k];
        __half h = __float2half_rn(v);
        g_wfh[i] = h; g_wfl[i] = __float2half_rn(v - __half2float(h));
    }
    for (int i = idx; i < 256*4352; i += stride) {
        int o = i / 4352, kk = i - o*4352;
        int tap = kk >> 8, ic = kk & 255;
        float sc = bn2_g[o] * rsqrtf(bn2_v[o] + 1e-5f);
        g_w2[i] = __float2half_rn(conv2_w[(o*256 + ic)*17 + tap] * sc);
    }
    for (int i = idx; i < 768*512; i += stride) {
        float v = w_ih[i];
        __half h = __float2half_rn(v);
        g_wihh[i] = h; g_wihl[i] = __float2half_rn(v - __half2float(h));
    }
    for (int i = idx; i < 768*256; i += stride) {
        float v = w_hh[i];
        __half h = __float2half_rn(v);
        g_whhh[i] = h; g_whhl[i] = __float2half_rn(v - __half2float(h));
    }
    for (int i = idx; i < NROWS*DIM; i += stride) {
        float v = x[i];
        __half h = __float2half_rn(v);
        g_xh[i] = h; g_xl[i] = __float2half_rn(v - __half2float(h));
    }
}

// == front GEMM (MODE 0 only): 256x128 tile, A-split x B-split, 3-stage ====
#define PITCH 80
#define A_ARR 20480            // 256 rows * 80
#define B_ARR 10240            // 128 rows * 80
#define SM_AHI(s) ((s)*61440 + 0)
#define SM_ALO(s) ((s)*61440 + A_ARR)
#define SM_BHI(s) ((s)*61440 + 2*A_ARR)
#define SM_BLO(s) ((s)*61440 + 2*A_ARR + B_ARR)
#define GEMM_SMEM 184320

__global__ void __launch_bounds__(256, 1) front_kernel(const float* __restrict__ x) {
    extern __shared__ char smem[];
    const int tid  = threadIdx.x;
    const int wid  = tid >> 5, lane = tid & 31;
    const int warp_m = wid & 3;        // 4 x 64 rows
    const int warp_n = wid >> 2;       // 2 x 64 cols
    const int gid  = lane >> 2, tid4 = lane & 3;
    const uint32_t sb = smem_u32(smem);

    constexpr int NC = 256 / 32;
    const int col0 = blockIdx.x * 128;
    const int row0 = blockIdx.y * 256;

    const uint32_t aOff = (uint32_t)(lane & 15)*PITCH + (uint32_t)(lane >> 4)*16;
    const uint32_t bOff = (uint32_t)(((lane >> 4) << 3) + (lane & 7))*PITCH
                        + (uint32_t)((lane >> 3) & 1)*16;

    const int r0_ = tid >> 2, u_ = tid & 3;

    float acc[4][8][4] = {};

#define CPA_TILE(c, s) { \
    uint32_t dAh = sb + SM_AHI(s), dAl = sb + SM_ALO(s); \
    uint32_t dBh = sb + SM_BHI(s), dBl = sb + SM_BLO(s); \
    _Pragma("unroll") \
    for (int g = 0; g < 4; g++) { \
        int arow = r0_ + 64*g; \
        uint32_t o = (uint32_t)(arow*PITCH + u_*16); \
        size_t a0 = (size_t)(row0+arow)*256 + (c)*32 + u_*8; \
        CPA16(dAh+o, g_xh+a0); CPA16(dAl+o, g_xl+a0); \
    } \
    _Pragma("unroll") \
    for (int g = 0; g < 2; g++) { \
        int brow = r0_ + 64*g; \
        uint32_t o = (uint32_t)(brow*PITCH + u_*16); \
        size_t b0 = (size_t)(col0+brow)*256 + (c)*32 + u_*8; \
        CPA16(dBh+o, g_wfh+b0); CPA16(dBl+o, g_wfl+b0); \
    } }

#define COMPUTE(s) { \
    _Pragma("unroll") \
    for (int ks = 0; ks < 2; ks++) { \
        uint32_t Ah[4][4], Al[4][4]; \
        _Pragma("unroll") \
        for (int mi = 0; mi < 4; mi++) { \
            uint32_t ad = sb + SM_AHI(s) + (warp_m*64 + mi*16)*PITCH + ks*32 + aOff; \
            LDMX4(Ah[mi][0],Ah[mi][1],Ah[mi][2],Ah[mi][3], ad); \
            ad = sb + SM_ALO(s) + (warp_m*64 + mi*16)*PITCH + ks*32 + aOff; \
            LDMX4(Al[mi][0],Al[mi][1],Al[mi][2],Al[mi][3], ad); \
        } \
        _Pragma("unroll") \
        for (int pj = 0; pj < 4; pj++) { \
            uint32_t Bh[4], Bl[4]; \
            uint32_t bd = sb + SM_BHI(s) + (warp_n*64 + pj*16)*PITCH + ks*32 + bOff; \
            LDMX4(Bh[0],Bh[1],Bh[2],Bh[3], bd); \
            bd = sb + SM_BLO(s) + (warp_n*64 + pj*16)*PITCH + ks*32 + bOff; \
            LDMX4(Bl[0],Bl[1],Bl[2],Bl[3], bd); \
            _Pragma("unroll") \
            for (int mi = 0; mi < 4; mi++) \
                _Pragma("unroll") \
                for (int h = 0; h < 2; h++) { \
                    float* D = acc[mi][pj*2 + h]; \
                    MMA_F16(D, Ah[mi], Bh[h*2], Bh[h*2+1]); \
                    MMA_F16(D, Ah[mi], Bl[h*2], Bl[h*2+1]); \
                    MMA_F16(D, Al[mi], Bh[h*2], Bh[h*2+1]); \
                } \
        } \
    } }

    CPA_TILE(0, 0); CPCOMMIT();
    CPA_TILE(1, 1); CPCOMMIT();
    for (int c = 0; c < NC; c++) {
        if (c + 1 < NC) { CPWAIT(1); } else { CPWAIT(0); }
        __syncthreads();
        if (c + 2 < NC) { CPA_TILE(c+2, (c+2)%3); CPCOMMIT(); }
        COMPUTE(c%3);
    }
#undef CPA_TILE
#undef COMPUTE

    #pragma unroll
    for (int mi = 0; mi < 4; mi++) {
        #pragma unroll
        for (int nj = 0; nj < 8; nj++) {
            int c = col0 + warp_n*64 + nj*8 + tid4*2;
            size_t r1 = (size_t)row0 + warp_m*64 + mi*16 + gid;
            size_t r2 = r1 + 8;
            float v00 = acc[mi][nj][0], v01 = acc[mi][nj][1];
            float v10 = acc[mi][nj][2], v11 = acc[mi][nj][3];
            if (col0 < 256) {
                float sc0 = g_sc1[c], sc1 = g_sc1[c+1];
                float sh0 = g_sh1[c], sh1 = g_sh1[c+1];
                *(uint32_t*)&g_h1s[r1*256 + c] =
                    pkh(fmaxf(v00*sc0+sh0,0.f), fmaxf(v01*sc1+sh1,0.f));
                *(uint32_t*)&g_h1s[r2*256 + c] =
                    pkh(fmaxf(v10*sc0+sh0,0.f), fmaxf(v11*sc1+sh1,0.f));
            } else {
                int cc = c - 256;
                float b0 = g_bmsg[cc], b1 = g_bmsg[cc+1];
                *(uint32_t*)&g_msg[r1*256 + cc] = pkh(fmaxf(v00+b0,0.f), fmaxf(v01+b1,0.f));
                *(uint32_t*)&g_msg[r2*256 + cc] = pkh(fmaxf(v10+b0,0.f), fmaxf(v11+b1,0.f));
            }
        }
    }
}

// == gi/gh GEMM: 128x128 tile, 128 thr, 64x64 warp, A-split x B-split,
//    2-stage, 2 CTAs/SM.  MODE 2: gi (K=512), MODE 3: gh (K=256) ==========
#define GI_STAGE 40960         // Ahi+Alo+Bhi+Blo = 4*10240
#define GI_AHI(s) ((s)*GI_STAGE)
#define GI_ALO(s) ((s)*GI_STAGE + 10240)
#define GI_BHI(s) ((s)*GI_STAGE + 20480)
#define GI_BLO(s) ((s)*GI_STAGE + 30720)
#define GI_SMEM   81920

template<int MODE>
__global__ void __launch_bounds__(128, 2) gih_kernel() {
    extern __shared__ char smem[];
    const int tid  = threadIdx.x;
    const int wid  = tid >> 5, lane = tid & 31;
    const int warp_m = wid & 1;        // 2 x 64 rows
    const int warp_n = wid >> 1;       // 2 x 64 cols
    const int gid  = lane >> 2, tid4 = lane & 3;
    const uint32_t sb = smem_u32(smem);

    constexpr int KT = (MODE==2) ? 512 : 256;
    constexpr int NC = KT / 32;
    const int col0 = blockIdx.x * 128;
    const size_t row0 = (size_t)blockIdx.y * 128;

    const uint32_t aOff = (uint32_t)(lane & 15)*PITCH + (uint32_t)(lane >> 4)*16;
    const uint32_t bOff = (uint32_t)(((lane >> 4) << 3) + (lane & 7))*PITCH
                        + (uint32_t)((lane >> 3) & 1)*16;

    float acc[4][8][4] = {};

#define GI_CPA(c, s) { \
    uint32_t dAh = sb + GI_AHI(s), dAl = sb + GI_ALO(s); \
    uint32_t dBh = sb + GI_BHI(s), dBl = sb + GI_BLO(s); \
    _Pragma("unroll") \
    for (int g = 0; g < 4; g++) { \
        int idx = tid + 128*g; \
        int r = idx >> 2, u = idx & 3; \
        uint32_t o = (uint32_t)(r*PITCH + u*16); \
        if (MODE == 2) { \
            const __half* sh_ = ((c) < 8) ? g_xch : g_xnh; \
            const __half* sl_ = ((c) < 8) ? g_xcl : g_xnl; \
            int kk_ = ((c) & 7)*32; \
            size_t a0 = (row0+r)*256 + kk_ + u*8; \
            CPA16(dAh+o, sh_+a0); CPA16(dAl+o, sl_+a0); \
            size_t b0 = (size_t)(col0+r)*512 + (c)*32 + u*8; \
            CPA16(dBh+o, g_wihh+b0); CPA16(dBl+o, g_wihl+b0); \
        } else { \
            size_t a0 = (row0+r)*256 + (c)*32 + u*8; \
            CPA16(dAh+o, g_xh+a0); CPA16(dAl+o, g_xl+a0); \
            size_t b0 = (size_t)(col0+r)*256 + (c)*32 + u*8; \
            CPA16(dBh+o, g_whhh+b0); CPA16(dBl+o, g_whhl+b0); \
        } \
    } }

#define GI_COMPUTE(s) { \
    _Pragma("unroll") \
    for (int ks = 0; ks < 2; ks++) { \
        uint32_t Ah[4][4], Al[4][4]; \
        _Pragma("unroll") \
        for (int mi = 0; mi < 4; mi++) { \
            uint32_t ad = sb + GI_AHI(s) + (warp_m*64 + mi*16)*PITCH + ks*32 + aOff; \
            LDMX4(Ah[mi][0],Ah[mi][1],Ah[mi][2],Ah[mi][3], ad); \
            ad = sb + GI_ALO(s) + (warp_m*64 + mi*16)*PITCH + ks*32 + aOff; \
            LDMX4(Al[mi][0],Al[mi][1],Al[mi][2],Al[mi][3], ad); \
        } \
        _Pragma("unroll") \
        for (int pj = 0; pj < 4; pj++) { \
            uint32_t Bh[4], Bl[4]; \
            uint32_t bd = sb + GI_BHI(s) + (warp_n*64 + pj*16)*PITCH + ks*32 + bOff; \
            LDMX4(Bh[0],Bh[1],Bh[2],Bh[3], bd); \
            bd = sb + GI_BLO(s) + (warp_n*64 + pj*16)*PITCH + ks*32 + bOff; \
            LDMX4(Bl[0],Bl[1],Bl[2],Bl[3], bd); \
            _Pragma("unroll") \
            for (int mi = 0; mi < 4; mi++) \
                _Pragma("unroll") \
                for (int h = 0; h < 2; h++) { \
                    float* D = acc[mi][pj*2 + h]; \
                    MMA_F16(D, Ah[mi], Bh[h*2], Bh[h*2+1]); \
                    MMA_F16(D, Ah[mi], Bl[h*2], Bl[h*2+1]); \
                    MMA_F16(D, Al[mi], Bh[h*2], Bh[h*2+1]); \
                } \
        } \
    } }

    GI_CPA(0, 0); CPCOMMIT(); CPWAIT(0);
    __syncthreads();
    for (int c = 0; c < NC; c++) {
        if (c + 1 < NC) { GI_CPA(c+1, (c+1)&1); CPCOMMIT(); }
        GI_COMPUTE(c&1);
        if (c + 1 < NC) { CPWAIT(0); }
        __syncthreads();
    }
#undef GI_CPA
#undef GI_COMPUTE

    __half* gout = (MODE == 2) ? g_gi : g_gh;
    #pragma unroll
    for (int mi = 0; mi < 4; mi++) {
        #pragma unroll
        for (int nj = 0; nj < 8; nj++) {
            int c = col0 + warp_n*64 + nj*8 + tid4*2;
            size_t r1 = row0 + warp_m*64 + mi*16 + gid;
            size_t r2 = r1 + 8;
            *(uint32_t*)&gout[r1*768 + c] = pkh(acc[mi][nj][0], acc[mi][nj][1]);
            *(uint32_t*)&gout[r2*768 + c] = pkh(acc[mi][nj][2], acc[mi][nj][3]);
        }
    }
}

// == conv2: 128x128 tile, 128 thr, 64x64 warp tiles, 1 MMA, 4-stage ========
#define C2_STAGE 20480         // A 10240 + B 10240
#define C2_A(s)   ((s)*C2_STAGE)
#define C2_B(s)   ((s)*C2_STAGE + 10240)
#define C2_SMEM   81920

__global__ void __launch_bounds__(128, 2) conv2_kernel(const float* __restrict__ x) {
    extern __shared__ char smem[];
    const int tid  = threadIdx.x;
    const int wid  = tid >> 5, lane = tid & 31;
    const int warp_m = wid & 1;        // 2 x 64 rows
    const int warp_n = wid >> 1;       // 2 x 64 cols
    const int gid  = lane >> 2, tid4 = lane & 3;
    const uint32_t sb = smem_u32(smem);

    constexpr int NC = 4352 / 32;      // 136
    const int col0 = blockIdx.x * 128;
    const int bz = blockIdx.z;
    const int t0 = blockIdx.y * 128;
    const size_t row0 = (size_t)bz*NSEQ + t0;

    const uint32_t aOff = (uint32_t)(lane & 15)*PITCH + (uint32_t)(lane >> 4)*16;
    const uint32_t bOff = (uint32_t)(((lane >> 4) << 3) + (lane & 7))*PITCH
                        + (uint32_t)((lane >> 3) & 1)*16;

    float acc[4][8][4] = {};

#define C2_CPA(c, s) { \
    uint32_t dA = sb + C2_A(s), dB = sb + C2_B(s); \
    int tap = (c) >> 3, kloc = ((c) & 7)*32; \
    _Pragma("unroll") \
    for (int g = 0; g < 4; g++) { \
        int idx = tid + 128*g; \
        int r = idx >> 2, u = idx & 3; \
        uint32_t o = (uint32_t)(r*PITCH + u*16); \
        int t1 = t0 + r + tap - 8; \
        uint32_t z1 = ((unsigned)t1 < (unsigned)NSEQ) ? 16u : 0u; \
        int tc1 = min(max(t1, 0), NSEQ-1); \
        size_t a0 = ((size_t)bz*NSEQ + tc1)*256 + kloc + u*8; \
        CPA16Z(dA+o, g_h1s+a0, z1); \
        size_t b0 = (size_t)(col0+r)*4352 + (c)*32 + u*8; \
        CPA16(dB+o, g_w2+b0); \
    } }

#define C2_COMPUTE(s) { \
    _Pragma("unroll") \
    for (int ks = 0; ks < 2; ks++) { \
        uint32_t Ah[4][4], Bh[4][4]; \
        _Pragma("unroll") \
        for (int mi = 0; mi < 4; mi++) { \
            uint32_t ad = sb + C2_A(s) + (warp_m*64 + mi*16)*PITCH + ks*32 + aOff; \
            LDMX4(Ah[mi][0],Ah[mi][1],Ah[mi][2],Ah[mi][3], ad); \
        } \
        _Pragma("unroll") \
        for (int pj = 0; pj < 4; pj++) { \
            uint32_t bd = sb + C2_B(s) + (warp_n*64 + pj*16)*PITCH + ks*32 + bOff; \
            LDMX4(Bh[pj][0],Bh[pj][1],Bh[pj][2],Bh[pj][3], bd); \
        } \
        _Pragma("unroll") \
        for (int mi = 0; mi < 4; mi++) \
            _Pragma("unroll") \
            for (int pj = 0; pj < 4; pj++) \
                _Pragma("unroll") \
                for (int h = 0; h < 2; h++) \
                    MMA_F16(acc[mi][pj*2 + h], Ah[mi], Bh[pj][h*2], Bh[pj][h*2+1]); \
    } }

    C2_CPA(0, 0); CPCOMMIT();
    C2_CPA(1, 1); CPCOMMIT();
    C2_CPA(2, 2); CPCOMMIT();
    for (int c = 0; c < NC; c++) {
        if (c + 2 < NC)      { CPWAIT(2); }
        else if (c + 1 < NC) { CPWAIT(1); }
        else                 { CPWAIT(0); }
        __syncthreads();
        if (c + 3 < NC) { C2_CPA(c+3, (c+3)&3); CPCOMMIT(); }
        C2_COMPUTE(c&3);
    }
#undef C2_CPA
#undef C2_COMPUTE

    #pragma unroll
    for (int mi = 0; mi < 4; mi++) {
        #pragma unroll
        for (int nj = 0; nj < 8; nj++) {
            int c = col0 + warp_n*64 + nj*8 + tid4*2;
            size_t r1 = row0 + warp_m*64 + mi*16 + gid;
            size_t r2 = r1 + 8;
            float sh0 = g_sh2[c], sh1 = g_sh2[c+1];
            uint32_t lo, hi;
            float a0 = fmaxf(acc[mi][nj][0] + sh0 + x[r1*256+c],   0.f);
            float a1 = fmaxf(acc[mi][nj][1] + sh1 + x[r1*256+c+1], 0.f);
            hi = pksplit_h(a0, a1, lo);
            *(uint32_t*)&g_xch[r1*256 + c] = hi; *(uint32_t*)&g_xcl[r1*256 + c] = lo;
            a0 = fmaxf(acc[mi][nj][2] + sh0 + x[r2*256+c],   0.f);
            a1 = fmaxf(acc[mi][nj][3] + sh1 + x[r2*256+c+1], 0.f);
            hi = pksplit_h(a0, a1, lo);
            *(uint32_t*)&g_xch[r2*256 + c] = hi; *(uint32_t*)&g_xcl[r2*256 + c] = lo;
        }
    }
}

// ---------------- s projection -> (u, q') and (s, q') ---------------------
__global__ void skernel(const float* __restrict__ x,
                        const float* __restrict__ w_se,
                        const float* __restrict__ b_se) {
    int row = blockIdx.x * 8 + (threadIdx.x >> 5);
    int lane = threadIdx.x & 31;
    float p0=0.f, p1=0.f, p2=0.f;
    for (int k = lane; k < DIM; k += 32) {
        float xv = x[(size_t)row*DIM + k];
        p0 += xv * w_se[k];
        p1 += xv * w_se[DIM + k];
        p2 += xv * w_se[2*DIM + k];
    }
    #pragma unroll
    for (int off = 16; off > 0; off >>= 1) {
        p0 += __shfl_down_sync(0xffffffffu, p0, off);
        p1 += __shfl_down_sync(0xffffffffu, p1, off);
        p2 += __shfl_down_sync(0xffffffffu, p2, off);
    }
    if (lane == 0) {
        const float L2E = 1.4426950408889634f;
        p0 += b_se[0]; p1 += b_se[1]; p2 += b_se[2];
        float sq = p0*p0 + p1*p1 + p2*p2;
        float qp = -L2E * sq;
        g_s2[row*8+0] = 2.0f*L2E*p0;
        g_s2[row*8+1] = 2.0f*L2E*p1;
        g_s2[row*8+2] = 2.0f*L2E*p2;
        g_s2[row*8+3] = qp;
        g_s2[row*8+4] = p0;
        g_s2[row*8+5] = p1;
        g_s2[row*8+6] = p2;
        g_s2[row*8+7] = qp;
    }
}

// ---------------- tensorized NMP: fp32 t, f16x2 ex2, 1-MMA ---------------
#define NWP  80
#define NWH(s)  ((s)*5120)             // W bufs: 0, 5120
#define NMPITCH 528
#define NMH(s) (10240 + (s)*16896)     // msg stages: 10240, 27136
#define NSMF(s) (44032 + (s)*512)      // sSm float bufs (4*32 floats)
#define NMP_SMEM 45056

__global__ void __launch_bounds__(256, 2) nmp_kernel(const float* __restrict__ mask) {
    extern __shared__ char smem[];
    const uint32_t sb = smem_u32(smem);
    const int b  = blockIdx.y;
    const int n0 = blockIdx.x * 64;
    const int tid = threadIdx.x;
    const int wid = tid >> 5, lane = tid & 31;
    const int warp_n = wid & 1, warp_d = wid >> 1;
    const int gid = lane >> 2, tid4 = lane & 3;

    const uint32_t aOff  = (uint32_t)(lane & 15)*NWP + (uint32_t)(lane >> 4)*16;
    const uint32_t bOffT = (uint32_t)(lane & 15)*NMPITCH + (uint32_t)(lane >> 4)*16;

    const size_t mbase = ((size_t)b*NSEQ + n0) * NSEQ;
    const int rr = tid >> 2, mm0 = (tid & 3)*8;

    float u0i, u1i, u2i, qi;
    {
        const float* sp = &g_s2[((size_t)b*NSEQ + n0 + rr)*8];
        u0i = sp[0]; u1i = sp[1]; u2i = sp[2]; qi = sp[3];
    }

    const int mrow = tid >> 5;
    const int mu   = tid & 31;

#define NMP_PREFETCH(c, s) { \
    uint32_t dh = sb + NMH(s); \
    const __half* srch = g_msg + ((size_t)b*NSEQ + (c)*32)*256; \
    _Pragma("unroll") \
    for (int q = 0; q < 4; q++) { \
        int row = mrow + q*8; \
        CPA16(dh + (uint32_t)row*NMPITCH + (uint32_t)mu*16, srch + (size_t)row*256 + mu*8); \
    } }

#define SSM_STORE(c, s) { \
    if (tid < 128) { \
        int j = tid >> 2, comp = tid & 3; \
        ((float*)(smem + NSMF(s)))[comp*32 + j] = \
            g_s2[((size_t)b*NSEQ + (c)*32 + j)*8 + 4 + comp]; \
    } }

    SSM_STORE(0, 0);
    NMP_PREFETCH(0, 0); CPCOMMIT();

    float acc[2][8][4] = {};
    constexpr int NCn = NSEQ/32;

    for (int c = 0; c < NCn; c++) {
        int s = c & 1;
        __syncthreads();   // ends MMA(c-1); publishes sSm(c)
        if (c+1 < NCn) SSM_STORE(c+1, 1-s);
        {   // compute W(c): t in fp32, ex2 in f16x2
            const float* sSmF = (const float*)(smem + NSMF(s));
            const float* mrow_p = &mask[mbase + (size_t)rr*NSEQ + c*32 + mm0];
            float4 mk0 = *(const float4*)mrow_p;
            float4 mk1 = *(const float4*)(mrow_p + 4);
            uint32_t wv[4];
            #pragma unroll
            for (int p = 0; p < 4; p++) {
                int mm = mm0 + 2*p;
                float ta = fmaf(u0i, sSmF[mm],
                           fmaf(u1i, sSmF[32+mm],
                           fmaf(u2i, sSmF[64+mm], sSmF[96+mm] + qi)));
                float tb = fmaf(u0i, sSmF[mm+1],
                           fmaf(u1i, sSmF[32+mm+1],
                           fmaf(u2i, sSmF[64+mm+1], sSmF[96+mm+1] + qi)));
                __half2 t2 = __floats2half2_rn(ta, tb);
                uint32_t e2;
                asm("ex2.approx.f16x2 %0, %1;" : "=r"(e2) : "r"(*(uint32_t*)&t2));
                float mka = (p < 2) ? ((p == 0) ? mk0.x : mk0.z) : ((p == 2) ? mk1.x : mk1.z);
                float mkb = (p < 2) ? ((p == 0) ? mk0.y : mk0.w) : ((p == 2) ? mk1.y : mk1.w);
                __half2 mh = __floats2half2_rn(mka, mkb);
                __half2 w2 = __hmul2(*(__half2*)&e2, mh);
                wv[p] = *(uint32_t*)&w2;
            }
            *(uint4*)(smem + NWH(s) + rr*NWP + mm0*2) = make_uint4(wv[0],wv[1],wv[2],wv[3]);
        }
        if (c+1 < NCn) { NMP_PREFETCH(c+1, 1-s); CPCOMMIT(); CPWAIT(1); }
        else           { CPWAIT(0); }
        __syncthreads();   // W(c), msg(c) ready
        #pragma unroll
        for (int ks = 0; ks < 2; ks++) {
            uint32_t Aw[2][4], Bm[4][4];
            #pragma unroll
            for (int mi = 0; mi < 2; mi++) {
                uint32_t ad = sb + NWH(s) + (warp_n*32 + mi*16)*NWP + ks*32 + aOff;
                LDMX4(Aw[mi][0],Aw[mi][1],Aw[mi][2],Aw[mi][3], ad);
            }
            #pragma unroll
            for (int dj = 0; dj < 4; dj++) {
                uint32_t bd = sb + NMH(s) + (ks*16)*NMPITCH + (warp_d*64 + dj*16)*2 + bOffT;
                LDMX4T(Bm[dj][0],Bm[dj][1],Bm[dj][2],Bm[dj][3], bd);
            }
            #pragma unroll
            for (int mi = 0; mi < 2; mi++)
                #pragma unroll
                for (int dj = 0; dj < 4; dj++)
                    #pragma unroll
                    for (int h = 0; h < 2; h++)
                        MMA_F16(acc[mi][dj*2 + h], Aw[mi], Bm[dj][h*2], Bm[dj][h*2+1]);
        }
    }
#undef NMP_PREFETCH
#undef SSM_STORE

    #pragma unroll
    for (int mi = 0; mi < 2; mi++) {
        #pragma unroll
        for (int dj8 = 0; dj8 < 8; dj8++) {
            int d = warp_d*64 + dj8*8 + tid4*2;
            size_t r1 = (size_t)b*NSEQ + n0 + warp_n*32 + mi*16 + gid;
            size_t r2 = r1 + 8;
            uint32_t lo, hi;
            hi = pksplit_h(acc[mi][dj8][0], acc[mi][dj8][1], lo);
            *(uint32_t*)&g_xnh[r1*256 + d] = hi; *(uint32_t*)&g_xnl[r1*256 + d] = lo;
            hi = pksplit_h(acc[mi][dj8][2], acc[mi][dj8][3], lo);
            *(uint32_t*)&g_xnh[r2*256 + d] = hi; *(uint32_t*)&g_xnl[r2*256 + d] = lo;
        }
    }
}

// ---------------- gate epilogue (fp16 gi/gh) ------------------------------
__global__ void gate_kernel(const float* __restrict__ x,
                            const float* __restrict__ b_ih,
                            const float* __restrict__ b_hh,
                            float* __restrict__ out) {
    int idx = blockIdx.x * blockDim.x + threadIdx.x;
    size_t r = idx >> 6;
    int c = (idx & 63) * 4;
    const __half* gi = &g_gi[r*768];
    const __half* gh = &g_gh[r*768];
    float4 xv  = *(const float4*)&x[r*DIM + c];
    float o4[4];
    #pragma unroll
    for (int p = 0; p < 2; p++) {
        int cc = c + 2*p;
        float2 gir = __half22float2(*(__half2*)&gi[cc]);
        float2 giz = __half22float2(*(__half2*)&gi[256 + cc]);
        float2 gin = __half22float2(*(__half2*)&gi[512 + cc]);
        float2 ghr = __half22float2(*(__half2*)&gh[cc]);
        float2 ghz = __half22float2(*(__half2*)&gh[256 + cc]);
        float2 ghn = __half22float2(*(__half2*)&gh[512 + cc]);
        #pragma unroll
        for (int q = 0; q < 2; q++) {
            int cq = cc + q;
            float air = ((q==0)?gir.x:gir.y) + b_ih[cq]     + ((q==0)?ghr.x:ghr.y) + b_hh[cq];
            float aiz = ((q==0)?giz.x:giz.y) + b_ih[256+cq] + ((q==0)?ghz.x:ghz.y) + b_hh[256+cq];
            float rv = 1.0f/(1.0f + __expf(-air));
            float zv = 1.0f/(1.0f + __expf(-aiz));
            float nv = tanhf(((q==0)?gin.x:gin.y) + b_ih[512+cq]
                           + rv*(((q==0)?ghn.x:ghn.y) + b_hh[512+cq]));
            o4[2*p+q] = (1.0f - zv)*nv + zv*(&xv.x)[2*p+q];
        }
    }
    *(float4*)&out[r*DIM + c] = make_float4(o4[0], o4[1], o4[2], o4[3]);
}

// ---------------- launch --------------------------------------------------
extern "C" void kernel_launch(void* const* d_in, const int* in_sizes, int n_in,
                              void* d_out, int out_size) {
    const float* x       = (const float*)d_in[0];
    const float* mask    = (const float*)d_in[1];
    const float* w_se    = (const float*)d_in[2];
    const float* b_se    = (const float*)d_in[3];
    const float* conv1_w = (const float*)d_in[4];
    const float* bn1_g   = (const float*)d_in[5];
    const float* bn1_b   = (const float*)d_in[6];
    const float* bn1_m   = (const float*)d_in[7];
    const float* bn1_v   = (const float*)d_in[8];
    const float* conv2_w = (const float*)d_in[9];
    const float* bn2_g   = (const float*)d_in[10];
    const float* bn2_b   = (const float*)d_in[11];
    const float* bn2_m   = (const float*)d_in[12];
    const float* bn2_v   = (const float*)d_in[13];
    const float* w_msg   = (const float*)d_in[14];
    const float* b_msg   = (const float*)d_in[15];
    const float* w_ih    = (const float*)d_in[16];
    const float* b_ih    = (const float*)d_in[17];
    const float* w_hh    = (const float*)d_in[18];
    const float* b_hh    = (const float*)d_in[19];
    float* out = (float*)d_out;

    cudaFuncSetAttribute(front_kernel, cudaFuncAttributeMaxDynamicSharedMemorySize, GEMM_SMEM);
    cudaFuncSetAttribute(gih_kernel<2>, cudaFuncAttributeMaxDynamicSharedMemorySize, GI_SMEM);
    cudaFuncSetAttribute(gih_kernel<3>, cudaFuncAttributeMaxDynamicSharedMemorySize, GI_SMEM);
    cudaFuncSetAttribute(conv2_kernel, cudaFuncAttributeMaxDynamicSharedMemorySize, C2_SMEM);
    cudaFuncSetAttribute(nmp_kernel,  cudaFuncAttributeMaxDynamicSharedMemorySize, NMP_SMEM);

    repack_kernel<<<1024, 256>>>(x, conv1_w, w_msg, conv2_w,
                                 bn1_g, bn1_b, bn1_m, bn1_v,
                                 bn2_g, bn2_b, bn2_m, bn2_v,
                                 b_msg, w_ih, w_hh);

    front_kernel<<<dim3(4, NROWS/256), 256, GEMM_SMEM>>>(x);     // front: h1 + msg

    skernel<<<NROWS/8, 256>>>(x, w_se, b_se);

    conv2_kernel<<<dim3(2, NSEQ/128, BS), 128, C2_SMEM>>>(x);    // conv2 -> xc split

    nmp_kernel<<<dim3(NSEQ/64, BS), 256, NMP_SMEM>>>(mask);      // -> xn split

    gih_kernel<2><<<dim3(6, NROWS/128), 128, GI_SMEM>>>();       // gi
    gih_kernel<3><<<dim3(6, NROWS/128), 128, GI_SMEM>>>();       // gh

    gate_kernel<<<NROWS*64/256, 256>>>(x, b_ih, b_hh, out);
}